// round 5
// baseline (speedup 1.0000x reference)
#include <cuda_runtime.h>
#include <cuda_bf16.h>
#include <math.h>
#include <stdint.h>

// Problem dims (fixed)
#define BB 2
#define TT 2048
#define CC 1024
#define NHH 16
#define HDD 64
#define MTOK 4096          // B*T
#define C3 3072
#define C4 4096

// ---------------- scratch (no allocation allowed) ----------------
__device__ float g_x1 [(size_t)MTOK * CC];
__device__ float g_y  [(size_t)MTOK * CC];

// bf16 split weights, transposed to [N][K]
__device__ __nv_bfloat16 g_wqkv_hi[(size_t)C3 * CC], g_wqkv_lo[(size_t)C3 * CC];
__device__ __nv_bfloat16 g_wa1_hi [(size_t)C4 * CC], g_wa1_lo [(size_t)C4 * CC];
__device__ __nv_bfloat16 g_wa2_hi [(size_t)CC * C4], g_wa2_lo [(size_t)CC * C4];
__device__ __nv_bfloat16 g_wf1_hi [(size_t)C4 * CC], g_wf1_lo [(size_t)C4 * CC];
__device__ __nv_bfloat16 g_wf2_hi [(size_t)CC * C4], g_wf2_lo [(size_t)CC * C4];
// bf16 split activations
__device__ __nv_bfloat16 g_ahi [(size_t)MTOK * CC], g_alo [(size_t)MTOK * CC];
__device__ __nv_bfloat16 g_hhi [(size_t)MTOK * C4], g_hlo [(size_t)MTOK * C4];
__device__ __nv_bfloat16 g_qkvh[(size_t)MTOK * C3], g_qkvl[(size_t)MTOK * C3];

__device__ __forceinline__ float gelu_f(float v) {
    return 0.5f * v * (1.0f + erff(v * 0.7071067811865475f));
}

// ======================= PTX helpers =======================
__device__ __forceinline__ uint32_t smem_u32(const void* p) {
    uint32_t a;
    asm("{ .reg .u64 t; cvta.to.shared.u64 t, %1; cvt.u32.u64 %0, t; }" : "=r"(a) : "l"(p));
    return a;
}
__device__ __forceinline__ void ldsm4(uint32_t* r, uint32_t addr) {
    asm volatile("ldmatrix.sync.aligned.m8n8.x4.shared.b16 {%0,%1,%2,%3}, [%4];"
                 : "=r"(r[0]), "=r"(r[1]), "=r"(r[2]), "=r"(r[3]) : "r"(addr));
}
__device__ __forceinline__ void ldsm4t(uint32_t* r, uint32_t addr) {
    asm volatile("ldmatrix.sync.aligned.m8n8.x4.trans.shared.b16 {%0,%1,%2,%3}, [%4];"
                 : "=r"(r[0]), "=r"(r[1]), "=r"(r[2]), "=r"(r[3]) : "r"(addr));
}
__device__ __forceinline__ void mma_bf16(float* d, const uint32_t* a, const uint32_t* b) {
    asm volatile(
        "mma.sync.aligned.m16n8k16.row.col.f32.bf16.bf16.f32 "
        "{%0,%1,%2,%3}, {%4,%5,%6,%7}, {%8,%9}, {%0,%1,%2,%3};"
        : "+f"(d[0]), "+f"(d[1]), "+f"(d[2]), "+f"(d[3])
        : "r"(a[0]), "r"(a[1]), "r"(a[2]), "r"(a[3]), "r"(b[0]), "r"(b[1]));
}
__device__ __forceinline__ void cp16(uint32_t dst, const void* src) {
    unsigned long long g = __cvta_generic_to_global(src);
    asm volatile("cp.async.ca.shared.global [%0], [%1], 16;" :: "r"(dst), "l"(g) : "memory");
}
__device__ __forceinline__ void cp_commit() {
    asm volatile("cp.async.commit_group;" ::: "memory");
}
template<int N>
__device__ __forceinline__ void cp_wait() {
    asm volatile("cp.async.wait_group %0;" :: "n"(N) : "memory");
}
__device__ __forceinline__ void split2(float a, float b, uint32_t& hi, uint32_t& lo) {
    __nv_bfloat16 ha = __float2bfloat16_rn(a), hb = __float2bfloat16_rn(b);
    __nv_bfloat162 H{ha, hb};
    __nv_bfloat162 L{__float2bfloat16_rn(a - __bfloat162float(ha)),
                     __float2bfloat16_rn(b - __bfloat162float(hb))};
    hi = *(uint32_t*)&H;
    lo = *(uint32_t*)&L;
}

// ======================= conversion kernels =======================
__global__ void __launch_bounds__(256)
cvt_act_kernel(const float* __restrict__ in, __nv_bfloat16* __restrict__ hi,
               __nv_bfloat16* __restrict__ lo, int n)
{
    int i = (blockIdx.x * 256 + threadIdx.x) * 4;
    if (i >= n) return;
    float4 v = *(const float4*)(in + i);
    uint32_t h0, l0, h1, l1;
    split2(v.x, v.y, h0, l0);
    split2(v.z, v.w, h1, l1);
    *(uint32_t*)(hi + i)     = h0;
    *(uint32_t*)(hi + i + 2) = h1;
    *(uint32_t*)(lo + i)     = l0;
    *(uint32_t*)(lo + i + 2) = l1;
}

__global__ void __launch_bounds__(256)
cvt_wt_kernel(const float* __restrict__ W, __nv_bfloat16* __restrict__ hi,
              __nv_bfloat16* __restrict__ lo, int K, int N)
{
    __shared__ float tile[32][33];
    const int n0 = blockIdx.x * 32, k0 = blockIdx.y * 32;
    const int tx = threadIdx.x & 31, ty = threadIdx.x >> 5;
#pragma unroll
    for (int r = 0; r < 4; ++r)
        tile[ty + r * 8][tx] = W[(size_t)(k0 + ty + r * 8) * N + n0 + tx];
    __syncthreads();
#pragma unroll
    for (int r = 0; r < 4; ++r) {
        int n = n0 + ty + r * 8;
        float v = tile[tx][ty + r * 8];
        __nv_bfloat16 h = __float2bfloat16_rn(v);
        hi[(size_t)n * K + k0 + tx] = h;
        lo[(size_t)n * K + k0 + tx] = __float2bfloat16_rn(v - __bfloat162float(h));
    }
}

// shared swizzle for 64B-row operand tiles
__device__ __forceinline__ uint32_t sw_off(int row, int kq) {
    return (uint32_t)(row * 64 + (((kq) ^ ((row >> 1) & 3)) << 4));
}

// ======================= HMMA GEMM, CTA 128x128 (for N=1024) =======================
#define GSMEM (3 * 32768)
template<int MODE>
__global__ void __launch_bounds__(256)
gemm_mma_kernel(const __nv_bfloat16* __restrict__ Ahi, const __nv_bfloat16* __restrict__ Alo,
                const __nv_bfloat16* __restrict__ Bhi, const __nv_bfloat16* __restrict__ Blo,
                const float* __restrict__ bias, float* __restrict__ Cf,
                __nv_bfloat16* __restrict__ Chi, __nv_bfloat16* __restrict__ Clo,
                int N, int K)
{
    extern __shared__ char smem[];
    const uint32_t sb = smem_u32(smem);

    const int t = threadIdx.x;
    const int wid = t >> 5, lane = t & 31;
    const int bm = blockIdx.y * 128;
    const int bn = blockIdx.x * 128;
    const int wm = wid >> 2, wn = wid & 3;

    const __nv_bfloat16* gsrc[4] = {Ahi, Alo, Bhi, Blo};

    float acc[4][4][4];
#pragma unroll
    for (int i = 0; i < 4; ++i)
#pragma unroll
        for (int j = 0; j < 4; ++j)
#pragma unroll
            for (int k = 0; k < 4; ++k) acc[i][j][k] = 0.0f;

    const int nc = K >> 5;

    const int g  = lane >> 3, lr = lane & 7;
    const int a_rit = lr + (g & 1) * 8, a_kqo = g >> 1;
    const int b_rit = lr + (g >> 1) * 8, b_kqo = g & 1;

    uint32_t aAhi[4], aAlo[4], aBhi[2], aBlo[2];
    int aRsw[4], bRsw[2];
#pragma unroll
    for (int mt = 0; mt < 4; ++mt) {
        int row = wm * 64 + mt * 16 + a_rit;
        aAhi[mt] = sb + 0     + row * 64;
        aAlo[mt] = sb + 8192  + row * 64;
        aRsw[mt] = (row >> 1) & 3;
    }
#pragma unroll
    for (int p = 0; p < 2; ++p) {
        int row = wn * 32 + p * 16 + b_rit;
        aBhi[p] = sb + 16384 + row * 64;
        aBlo[p] = sb + 24576 + row * 64;
        bRsw[p] = (row >> 1) & 3;
    }

    auto issue = [&](int c, int s) {
        const uint32_t st = sb + s * 32768;
        const int kb = c * 32;
#pragma unroll
        for (int i = 0; i < 8; ++i) {
            int u = t + i * 256;
            int arr = u >> 9, v = u & 511, row = v >> 2, kq = v & 3;
            const __nv_bfloat16* src = gsrc[arr] +
                (size_t)((arr < 2 ? bm : bn) + row) * K + kb + kq * 8;
            cp16(st + arr * 8192 + sw_off(row, kq), src);
        }
        cp_commit();
    };

    issue(0, 0);
    issue(1, 1);
    int s = 0;
    for (int c = 0; c < nc; ++c) {
        if (c + 2 < nc) { issue(c + 2, (c + 2) % 3); cp_wait<2>(); }
        else if (c + 1 < nc) cp_wait<1>();
        else cp_wait<0>();
        __syncthreads();

        const uint32_t stoff = (uint32_t)(s * 32768);
#pragma unroll
        for (int ks = 0; ks < 2; ++ks) {
            uint32_t ah[4][4], al[4][4], bh[4][2], bl[4][2];
#pragma unroll
            for (int mt = 0; mt < 4; ++mt) {
                uint32_t o = (uint32_t)((((2 * ks + a_kqo) ^ aRsw[mt]) << 4));
                ldsm4(ah[mt], aAhi[mt] + stoff + o);
                ldsm4(al[mt], aAlo[mt] + stoff + o);
            }
#pragma unroll
            for (int p = 0; p < 2; ++p) {
                uint32_t r[4];
                uint32_t o = (uint32_t)((((2 * ks + b_kqo) ^ bRsw[p]) << 4));
                ldsm4(r, aBhi[p] + stoff + o);
                bh[2 * p][0] = r[0]; bh[2 * p][1] = r[1];
                bh[2 * p + 1][0] = r[2]; bh[2 * p + 1][1] = r[3];
                ldsm4(r, aBlo[p] + stoff + o);
                bl[2 * p][0] = r[0]; bl[2 * p][1] = r[1];
                bl[2 * p + 1][0] = r[2]; bl[2 * p + 1][1] = r[3];
            }
#pragma unroll
            for (int mt = 0; mt < 4; ++mt)
#pragma unroll
                for (int nt = 0; nt < 4; ++nt) {
                    mma_bf16(acc[mt][nt], ah[mt], bh[nt]);
                    mma_bf16(acc[mt][nt], ah[mt], bl[nt]);
                    mma_bf16(acc[mt][nt], al[mt], bh[nt]);
                }
        }
        __syncthreads();
        s = (s + 1) % 3;
    }

    const int mrow = bm + wm * 64;
    const int ncol = bn + wn * 32;
#pragma unroll
    for (int mt = 0; mt < 4; ++mt) {
#pragma unroll
        for (int nt = 0; nt < 4; ++nt) {
            float* d = acc[mt][nt];
            int r0 = mrow + mt * 16 + (lane >> 2);
            int cix = ncol + nt * 8 + (lane & 3) * 2;
            float b0 = bias[cix], b1 = bias[cix + 1];
            float v00 = d[0] + b0, v01 = d[1] + b1;
            float v10 = d[2] + b0, v11 = d[3] + b1;
            if (MODE == 0) {
                float2 p0{v00, v01}, p1{v10, v11};
                *(float2*)&Cf[(size_t)r0 * N + cix]       = p0;
                *(float2*)&Cf[(size_t)(r0 + 8) * N + cix] = p1;
            } else {
                if (MODE == 1) {
                    v00 = gelu_f(v00); v01 = gelu_f(v01);
                    v10 = gelu_f(v10); v11 = gelu_f(v11);
                }
                uint32_t h0, l0, h1, l1;
                split2(v00, v01, h0, l0);
                split2(v10, v11, h1, l1);
                *(uint32_t*)&Chi[(size_t)r0 * N + cix]       = h0;
                *(uint32_t*)&Clo[(size_t)r0 * N + cix]       = l0;
                *(uint32_t*)&Chi[(size_t)(r0 + 8) * N + cix] = h1;
                *(uint32_t*)&Clo[(size_t)(r0 + 8) * N + cix] = l1;
            }
        }
    }
}

// ======================= HMMA GEMM, CTA 128x256 (for N>=2048) =======================
// 8 warps (2x4), warp tile 64x64; A-frags reused across 8 n-tiles.
// smem/stage: Ahi 8K | Alo 8K | Bhi 16K | Blo 16K = 48KB; 3 stages = 144KB.
#define GSMEM2 (3 * 49152)
template<int MODE>
__global__ void __launch_bounds__(256)
gemm_mma256_kernel(const __nv_bfloat16* __restrict__ Ahi, const __nv_bfloat16* __restrict__ Alo,
                   const __nv_bfloat16* __restrict__ Bhi, const __nv_bfloat16* __restrict__ Blo,
                   const float* __restrict__ bias, float* __restrict__ Cf,
                   __nv_bfloat16* __restrict__ Chi, __nv_bfloat16* __restrict__ Clo,
                   int N, int K)
{
    extern __shared__ char smem[];
    const uint32_t sb = smem_u32(smem);

    const int t = threadIdx.x;
    const int wid = t >> 5, lane = t & 31;
    const int bm = blockIdx.y * 128;
    const int bn = blockIdx.x * 256;
    const int wm = wid >> 2, wn = wid & 3;

    const __nv_bfloat16* gsrc[4] = {Ahi, Alo, Bhi, Blo};

    float acc[4][8][4];
#pragma unroll
    for (int i = 0; i < 4; ++i)
#pragma unroll
        for (int j = 0; j < 8; ++j)
#pragma unroll
            for (int k = 0; k < 4; ++k) acc[i][j][k] = 0.0f;

    const int nc = K >> 5;

    const int g  = lane >> 3, lr = lane & 7;
    const int a_rit = lr + (g & 1) * 8, a_kqo = g >> 1;
    const int b_rit = lr + (g >> 1) * 8, b_kqo = g & 1;

    uint32_t aAhi[4], aAlo[4], aBhi[4], aBlo[4];
    int aRsw[4], bRsw[4];
#pragma unroll
    for (int mt = 0; mt < 4; ++mt) {
        int row = wm * 64 + mt * 16 + a_rit;
        aAhi[mt] = sb + 0    + row * 64;
        aAlo[mt] = sb + 8192 + row * 64;
        aRsw[mt] = (row >> 1) & 3;
    }
#pragma unroll
    for (int p = 0; p < 4; ++p) {
        int row = wn * 64 + p * 16 + b_rit;
        aBhi[p] = sb + 16384 + row * 64;
        aBlo[p] = sb + 32768 + row * 64;
        bRsw[p] = (row >> 1) & 3;
    }

    // per stage: 3072 16B units (Ahi 512, Alo 512, Bhi 1024, Blo 1024)
    auto issue = [&](int c, int s) {
        const uint32_t st = sb + s * 49152;
        const int kb = c * 32;
#pragma unroll
        for (int i = 0; i < 12; ++i) {
            int u = t + i * 256;
            uint32_t dst;
            const __nv_bfloat16* src;
            if (u < 1024) {
                int arr = u >> 9, v = u & 511, row = v >> 2, kq = v & 3;
                src = gsrc[arr] + (size_t)(bm + row) * K + kb + kq * 8;
                dst = st + arr * 8192 + sw_off(row, kq);
            } else {
                int w = u - 1024;
                int arr = w >> 10, v = w & 1023, row = v >> 2, kq = v & 3;
                src = gsrc[2 + arr] + (size_t)(bn + row) * K + kb + kq * 8;
                dst = st + 16384 + arr * 16384 + sw_off(row, kq);
            }
            cp16(dst, src);
        }
        cp_commit();
    };

    issue(0, 0);
    issue(1, 1);
    int s = 0;
    for (int c = 0; c < nc; ++c) {
        if (c + 2 < nc) { issue(c + 2, (c + 2) % 3); cp_wait<2>(); }
        else if (c + 1 < nc) cp_wait<1>();
        else cp_wait<0>();
        __syncthreads();

        const uint32_t stoff = (uint32_t)(s * 49152);
#pragma unroll
        for (int ks = 0; ks < 2; ++ks) {
            uint32_t ah[4][4], al[4][4];
#pragma unroll
            for (int mt = 0; mt < 4; ++mt) {
                uint32_t o = (uint32_t)((((2 * ks + a_kqo) ^ aRsw[mt]) << 4));
                ldsm4(ah[mt], aAhi[mt] + stoff + o);
                ldsm4(al[mt], aAlo[mt] + stoff + o);
            }
#pragma unroll
            for (int p = 0; p < 4; ++p) {
                uint32_t rh[4], rl[4];
                uint32_t o = (uint32_t)((((2 * ks + b_kqo) ^ bRsw[p]) << 4));
                ldsm4(rh, aBhi[p] + stoff + o);
                ldsm4(rl, aBlo[p] + stoff + o);
#pragma unroll
                for (int mt = 0; mt < 4; ++mt) {
                    mma_bf16(acc[mt][2 * p],     ah[mt], rh);
                    mma_bf16(acc[mt][2 * p],     ah[mt], rl);
                    mma_bf16(acc[mt][2 * p],     al[mt], rh);
                    mma_bf16(acc[mt][2 * p + 1], ah[mt], rh + 2);
                    mma_bf16(acc[mt][2 * p + 1], ah[mt], rl + 2);
                    mma_bf16(acc[mt][2 * p + 1], al[mt], rh + 2);
                }
            }
        }
        __syncthreads();
        s = (s + 1) % 3;
    }

    const int mrow = bm + wm * 64;
    const int ncol = bn + wn * 64;
#pragma unroll
    for (int mt = 0; mt < 4; ++mt) {
#pragma unroll
        for (int nt = 0; nt < 8; ++nt) {
            float* d = acc[mt][nt];
            int r0 = mrow + mt * 16 + (lane >> 2);
            int cix = ncol + nt * 8 + (lane & 3) * 2;
            float b0 = bias[cix], b1 = bias[cix + 1];
            float v00 = d[0] + b0, v01 = d[1] + b1;
            float v10 = d[2] + b0, v11 = d[3] + b1;
            if (MODE == 0) {
                float2 p0{v00, v01}, p1{v10, v11};
                *(float2*)&Cf[(size_t)r0 * N + cix]       = p0;
                *(float2*)&Cf[(size_t)(r0 + 8) * N + cix] = p1;
            } else {
                if (MODE == 1) {
                    v00 = gelu_f(v00); v01 = gelu_f(v01);
                    v10 = gelu_f(v10); v11 = gelu_f(v11);
                }
                uint32_t h0, l0, h1, l1;
                split2(v00, v01, h0, l0);
                split2(v10, v11, h1, l1);
                *(uint32_t*)&Chi[(size_t)r0 * N + cix]       = h0;
                *(uint32_t*)&Clo[(size_t)r0 * N + cix]       = l0;
                *(uint32_t*)&Chi[(size_t)(r0 + 8) * N + cix] = h1;
                *(uint32_t*)&Clo[(size_t)(r0 + 8) * N + cix] = l1;
            }
        }
    }
}

// ======================= HMMA causal attention (FA2-style) =======================
#define ASMEM 49152
__device__ __forceinline__ uint32_t asw(int row, int u) {
    return (uint32_t)(row * 128 + ((u ^ (row & 7)) << 4));
}

__global__ void __launch_bounds__(128, 3)
attn_mma_kernel(const __nv_bfloat16* __restrict__ qkvh, const __nv_bfloat16* __restrict__ qkvl,
                __nv_bfloat16* __restrict__ ohi, __nv_bfloat16* __restrict__ olo)
{
    extern __shared__ char asmem[];
    const uint32_t sb = smem_u32(asmem);

    const int t = threadIdx.x, wid = t >> 5, lane = t & 31;
    const int qb = blockIdx.x * 64;
    const int h  = blockIdx.y, b = blockIdx.z;

    const __nv_bfloat16* Kh_g = qkvh + (size_t)b * TT * C3 + h * HDD;
    const __nv_bfloat16* Kl_g = qkvl + (size_t)b * TT * C3 + h * HDD;
    const __nv_bfloat16* Qh_g = Kh_g + CC;
    const __nv_bfloat16* Ql_g = Kl_g + CC;
    const __nv_bfloat16* Vh_g = Kh_g + 2 * CC;
    const __nv_bfloat16* Vl_g = Kl_g + 2 * CC;

#pragma unroll
    for (int i = 0; i < 8; ++i) {
        int uu = t + i * 128;
        int arr = uu >> 9, v = uu & 511, row = v >> 3, u = v & 7;
        const __nv_bfloat16* src = (arr ? Ql_g : Qh_g) + (size_t)(qb + row) * C3 + u * 8;
        cp16(sb + arr * 8192 + asw(row, u), src);
    }
    cp_commit();

    const int g = lane >> 3, lr = lane & 7;
    const int r = lane >> 2, c = lane & 3;
    const int qrow = wid * 16 + lr + ((g & 1) << 3);
    const int a_u  = g >> 1;
    const int krit = lr + ((g >> 1) << 3);
    const int b_u  = g & 1;
    const int vrit = lr + ((g & 1) << 3);
    const int v_u  = g >> 1;

    float O[8][4];
#pragma unroll
    for (int i = 0; i < 8; ++i)
#pragma unroll
        for (int j = 0; j < 4; ++j) O[i][j] = 0.0f;
    float m0 = -1e30f, m1 = -1e30f, l0 = 0.0f, l1 = 0.0f;

    const int ntiles = blockIdx.x + 1;
    for (int kt = 0; kt < ntiles; ++kt) {
        const int kb = kt * 64;
        __syncthreads();
#pragma unroll
        for (int i = 0; i < 16; ++i) {
            int uu = t + i * 128;
            int arr = uu >> 9, v = uu & 511, row = v >> 3, u = v & 7;
            const __nv_bfloat16* src;
            if      (arr == 0) src = Kh_g + (size_t)(kb + row) * C3 + u * 8;
            else if (arr == 1) src = Kl_g + (size_t)(kb + row) * C3 + u * 8;
            else if (arr == 2) src = Vh_g + (size_t)(kb + row) * C3 + u * 8;
            else               src = Vl_g + (size_t)(kb + row) * C3 + u * 8;
            cp16(sb + 16384 + arr * 8192 + asw(row, u), src);
        }
        cp_commit();
        cp_wait<0>();
        __syncthreads();

        float S[8][4];
#pragma unroll
        for (int i = 0; i < 8; ++i)
#pragma unroll
            for (int j = 0; j < 4; ++j) S[i][j] = 0.0f;

#pragma unroll
        for (int kk = 0; kk < 4; ++kk) {
            uint32_t ah[4], al[4];
            uint32_t aoq = (uint32_t)(qrow * 128 + ((((kk << 1) | a_u) ^ (qrow & 7)) << 4));
            ldsm4(ah, sb + aoq);
            ldsm4(al, sb + 8192 + aoq);
#pragma unroll
            for (int p = 0; p < 4; ++p) {
                int krow = (p << 4) + krit;
                uint32_t ko = (uint32_t)(krow * 128 + ((((kk << 1) | b_u) ^ (krow & 7)) << 4));
                uint32_t bh[4], bl[4];
                ldsm4(bh, sb + 16384 + ko);
                ldsm4(bl, sb + 24576 + ko);
                mma_bf16(S[2 * p],     ah, bh);
                mma_bf16(S[2 * p],     ah, bl);
                mma_bf16(S[2 * p],     al, bh);
                mma_bf16(S[2 * p + 1], ah, bh + 2);
                mma_bf16(S[2 * p + 1], ah, bl + 2);
                mma_bf16(S[2 * p + 1], al, bh + 2);
            }
        }

#pragma unroll
        for (int nt = 0; nt < 8; ++nt)
#pragma unroll
            for (int e = 0; e < 4; ++e) S[nt][e] *= 0.125f;
        if (kt == blockIdx.x) {
            const int q0 = qb + wid * 16 + r, q1 = q0 + 8;
#pragma unroll
            for (int nt = 0; nt < 8; ++nt) {
                int k0 = kb + 8 * nt + 2 * c;
                if (k0     > q0) S[nt][0] = -1e30f;
                if (k0 + 1 > q0) S[nt][1] = -1e30f;
                if (k0     > q1) S[nt][2] = -1e30f;
                if (k0 + 1 > q1) S[nt][3] = -1e30f;
            }
        }

        float mx0 = -1e30f, mx1 = -1e30f;
#pragma unroll
        for (int nt = 0; nt < 8; ++nt) {
            mx0 = fmaxf(mx0, fmaxf(S[nt][0], S[nt][1]));
            mx1 = fmaxf(mx1, fmaxf(S[nt][2], S[nt][3]));
        }
        mx0 = fmaxf(mx0, __shfl_xor_sync(0xffffffffu, mx0, 1));
        mx0 = fmaxf(mx0, __shfl_xor_sync(0xffffffffu, mx0, 2));
        mx1 = fmaxf(mx1, __shfl_xor_sync(0xffffffffu, mx1, 1));
        mx1 = fmaxf(mx1, __shfl_xor_sync(0xffffffffu, mx1, 2));
        float mn0 = fmaxf(m0, mx0), mn1 = fmaxf(m1, mx1);
        float al0 = __expf(m0 - mn0), al1 = __expf(m1 - mn1);
        m0 = mn0; m1 = mn1;

        float s0 = 0.0f, s1 = 0.0f;
#pragma unroll
        for (int nt = 0; nt < 8; ++nt) {
            S[nt][0] = __expf(S[nt][0] - mn0);
            S[nt][1] = __expf(S[nt][1] - mn0);
            S[nt][2] = __expf(S[nt][2] - mn1);
            S[nt][3] = __expf(S[nt][3] - mn1);
            s0 += S[nt][0] + S[nt][1];
            s1 += S[nt][2] + S[nt][3];
        }
        l0 = l0 * al0 + s0;
        l1 = l1 * al1 + s1;
#pragma unroll
        for (int nt = 0; nt < 8; ++nt) {
            O[nt][0] *= al0; O[nt][1] *= al0;
            O[nt][2] *= al1; O[nt][3] *= al1;
        }

#pragma unroll
        for (int kk = 0; kk < 4; ++kk) {
            uint32_t ph[4], pl[4];
            split2(S[2 * kk][0],     S[2 * kk][1],     ph[0], pl[0]);
            split2(S[2 * kk][2],     S[2 * kk][3],     ph[1], pl[1]);
            split2(S[2 * kk + 1][0], S[2 * kk + 1][1], ph[2], pl[2]);
            split2(S[2 * kk + 1][2], S[2 * kk + 1][3], ph[3], pl[3]);
            int vrow = (kk << 4) + vrit;
#pragma unroll
            for (int p = 0; p < 4; ++p) {
                uint32_t vo = (uint32_t)(vrow * 128 + ((((p << 1) | v_u) ^ (vrow & 7)) << 4));
                uint32_t vh[4], vl[4];
                ldsm4t(vh, sb + 32768 + vo);
                ldsm4t(vl, sb + 40960 + vo);
                mma_bf16(O[2 * p],     ph, vh);
                mma_bf16(O[2 * p],     ph, vl);
                mma_bf16(O[2 * p],     pl, vh);
                mma_bf16(O[2 * p + 1], ph, vh + 2);
                mma_bf16(O[2 * p + 1], ph, vl + 2);
                mma_bf16(O[2 * p + 1], pl, vh + 2);
            }
        }
    }

    l0 += __shfl_xor_sync(0xffffffffu, l0, 1);
    l0 += __shfl_xor_sync(0xffffffffu, l0, 2);
    l1 += __shfl_xor_sync(0xffffffffu, l1, 1);
    l1 += __shfl_xor_sync(0xffffffffu, l1, 2);
    const float i0 = 1.0f / l0, i1 = 1.0f / l1;
    const int row0 = qb + wid * 16 + r, row1 = row0 + 8;
#pragma unroll
    for (int nt = 0; nt < 8; ++nt) {
        int col = h * HDD + 8 * nt + 2 * c;
        size_t idx0 = ((size_t)b * TT + row0) * CC + col;
        size_t idx1 = ((size_t)b * TT + row1) * CC + col;
        uint32_t h0, lo0, h1, lo1;
        split2(O[nt][0] * i0, O[nt][1] * i0, h0, lo0);
        split2(O[nt][2] * i1, O[nt][3] * i1, h1, lo1);
        *(uint32_t*)&ohi[idx0] = h0;
        *(uint32_t*)&olo[idx0] = lo0;
        *(uint32_t*)&ohi[idx1] = h1;
        *(uint32_t*)&olo[idx1] = lo1;
    }
}

// ---------------- LayerNorm + residual ----------------
__device__ __forceinline__ float block_sum(float v, float* red) {
    const int lane = threadIdx.x & 31, w = threadIdx.x >> 5;
#pragma unroll
    for (int o = 16; o; o >>= 1) v += __shfl_xor_sync(0xffffffffu, v, o);
    if (lane == 0) red[w] = v;
    __syncthreads();
    if (w == 0) {
        float s = (lane < 8) ? red[lane] : 0.0f;
#pragma unroll
        for (int o = 4; o; o >>= 1) s += __shfl_xor_sync(0xffffffffu, s, o);
        if (lane == 0) red[0] = s;
    }
    __syncthreads();
    float rr = red[0];
    __syncthreads();
    return rr;
}

template<bool SPLIT>
__global__ void __launch_bounds__(256)
ln_res_kernel(const float* __restrict__ res, const float* __restrict__ y,
              const float* __restrict__ g, const float* __restrict__ be,
              float* __restrict__ out,
              __nv_bfloat16* __restrict__ ohi, __nv_bfloat16* __restrict__ olo)
{
    __shared__ float red[8];
    const int row = blockIdx.x;
    const int t = threadIdx.x;
    const float* yr = y + (size_t)row * CC;

    float v[4];
    float s = 0.0f;
#pragma unroll
    for (int i = 0; i < 4; ++i) { v[i] = yr[t + i * 256]; s += v[i]; }
    const float mean = block_sum(s, red) * (1.0f / CC);

    float sq = 0.0f;
#pragma unroll
    for (int i = 0; i < 4; ++i) { float d = v[i] - mean; sq += d * d; }
    const float var = block_sum(sq, red) * (1.0f / CC);
    const float rstd = rsqrtf(var + 1e-5f);

    const float* rr = res + (size_t)row * CC;
    float* orow = out + (size_t)row * CC;
#pragma unroll
    for (int i = 0; i < 4; ++i) {
        int cix = t + i * 256;
        float o = rr[cix] + (v[i] - mean) * rstd * g[cix] + be[cix];
        orow[cix] = o;
        if (SPLIT) {
            __nv_bfloat16 hh = __float2bfloat16_rn(o);
            ohi[(size_t)row * CC + cix] = hh;
            olo[(size_t)row * CC + cix] = __float2bfloat16_rn(o - __bfloat162float(hh));
        }
    }
}

// ---------------- launch ----------------
extern "C" void kernel_launch(void* const* d_in, const int* in_sizes, int n_in,
                              void* d_out, int out_size)
{
    const float* x      = (const float*)d_in[0];
    const float* w_attn = (const float*)d_in[1];
    const float* b_attn = (const float*)d_in[2];
    const float* wa1    = (const float*)d_in[3];
    const float* ba1    = (const float*)d_in[4];
    const float* wa2    = (const float*)d_in[5];
    const float* ba2    = (const float*)d_in[6];
    const float* g1     = (const float*)d_in[7];
    const float* be1    = (const float*)d_in[8];
    const float* wf1    = (const float*)d_in[9];
    const float* bf1    = (const float*)d_in[10];
    const float* wf2    = (const float*)d_in[11];
    const float* bf2    = (const float*)d_in[12];
    const float* g2     = (const float*)d_in[13];
    const float* be2    = (const float*)d_in[14];
    float* out = (float*)d_out;

    float *x1, *y;
    cudaGetSymbolAddress((void**)&x1, g_x1);
    cudaGetSymbolAddress((void**)&y,  g_y);

    __nv_bfloat16 *wqkv_hi, *wqkv_lo, *wa1_hi, *wa1_lo, *wa2_hi, *wa2_lo,
                  *wf1_hi, *wf1_lo, *wf2_hi, *wf2_lo, *ahi, *alo, *hhi, *hlo,
                  *qkvh, *qkvl;
    cudaGetSymbolAddress((void**)&wqkv_hi, g_wqkv_hi);
    cudaGetSymbolAddress((void**)&wqkv_lo, g_wqkv_lo);
    cudaGetSymbolAddress((void**)&wa1_hi,  g_wa1_hi);
    cudaGetSymbolAddress((void**)&wa1_lo,  g_wa1_lo);
    cudaGetSymbolAddress((void**)&wa2_hi,  g_wa2_hi);
    cudaGetSymbolAddress((void**)&wa2_lo,  g_wa2_lo);
    cudaGetSymbolAddress((void**)&wf1_hi,  g_wf1_hi);
    cudaGetSymbolAddress((void**)&wf1_lo,  g_wf1_lo);
    cudaGetSymbolAddress((void**)&wf2_hi,  g_wf2_hi);
    cudaGetSymbolAddress((void**)&wf2_lo,  g_wf2_lo);
    cudaGetSymbolAddress((void**)&ahi,     g_ahi);
    cudaGetSymbolAddress((void**)&alo,     g_alo);
    cudaGetSymbolAddress((void**)&hhi,     g_hhi);
    cudaGetSymbolAddress((void**)&hlo,     g_hlo);
    cudaGetSymbolAddress((void**)&qkvh,    g_qkvh);
    cudaGetSymbolAddress((void**)&qkvl,    g_qkvl);

    cudaFuncSetAttribute(attn_mma_kernel, cudaFuncAttributeMaxDynamicSharedMemorySize, ASMEM);
    cudaFuncSetAttribute(gemm_mma_kernel<0>, cudaFuncAttributeMaxDynamicSharedMemorySize, GSMEM);
    cudaFuncSetAttribute(gemm_mma256_kernel<1>, cudaFuncAttributeMaxDynamicSharedMemorySize, GSMEM2);
    cudaFuncSetAttribute(gemm_mma256_kernel<2>, cudaFuncAttributeMaxDynamicSharedMemorySize, GSMEM2);

    // weight transpose + bf16 split
    cvt_wt_kernel<<<dim3(C3 / 32, CC / 32), 256>>>(w_attn, wqkv_hi, wqkv_lo, CC, C3);
    cvt_wt_kernel<<<dim3(C4 / 32, CC / 32), 256>>>(wa1, wa1_hi, wa1_lo, CC, C4);
    cvt_wt_kernel<<<dim3(CC / 32, C4 / 32), 256>>>(wa2, wa2_hi, wa2_lo, C4, CC);
    cvt_wt_kernel<<<dim3(C4 / 32, CC / 32), 256>>>(wf1, wf1_hi, wf1_lo, CC, C4);
    cvt_wt_kernel<<<dim3(CC / 32, C4 / 32), 256>>>(wf2, wf2_hi, wf2_lo, C4, CC);

    // 1) qkv = x @ w_attn + b_attn -> split bf16
    cvt_act_kernel<<<(MTOK * CC) / 1024, 256>>>(x, ahi, alo, MTOK * CC);
    gemm_mma256_kernel<2><<<dim3(C3 / 256, MTOK / 128), 256, GSMEM2>>>(
        ahi, alo, wqkv_hi, wqkv_lo, b_attn, nullptr, qkvh, qkvl, C3, CC);
    // 2) attention (HMMA) -> split bf16 att
    attn_mma_kernel<<<dim3(TT / 64, NHH, BB), 128, ASMEM>>>(qkvh, qkvl, ahi, alo);
    // 3) h = gelu(att @ wa1 + ba1) -> split bf16
    gemm_mma256_kernel<1><<<dim3(C4 / 256, MTOK / 128), 256, GSMEM2>>>(
        ahi, alo, wa1_hi, wa1_lo, ba1, nullptr, hhi, hlo, C4, CC);
    // 4) y = h @ wa2 + ba2
    gemm_mma_kernel<0><<<dim3(CC / 128, MTOK / 128), 256, GSMEM>>>(
        hhi, hlo, wa2_hi, wa2_lo, ba2, y, nullptr, nullptr, CC, C4);
    // 5) x1 = x + ln(y); emit split bf16 x1
    ln_res_kernel<true><<<MTOK, 256>>>(x, y, g1, be1, x1, ahi, alo);
    // 6) h = gelu(x1 @ wf1 + bf1) -> split bf16
    gemm_mma256_kernel<1><<<dim3(C4 / 256, MTOK / 128), 256, GSMEM2>>>(
        ahi, alo, wf1_hi, wf1_lo, bf1, nullptr, hhi, hlo, C4, CC);
    // 7) y = h @ wf2 + bf2
    gemm_mma_kernel<0><<<dim3(CC / 128, MTOK / 128), 256, GSMEM>>>(
        hhi, hlo, wf2_hi, wf2_lo, bf2, y, nullptr, nullptr, CC, C4);
    // 8) out = x1 + ln(y)
    ln_res_kernel<false><<<MTOK, 256>>>(x1, y, g2, be2, out, nullptr, nullptr);
}

// round 6
// speedup vs baseline: 1.0422x; 1.0422x over previous
#include <cuda_runtime.h>
#include <cuda_bf16.h>
#include <math.h>
#include <stdint.h>

// Problem dims (fixed)
#define BB 2
#define TT 2048
#define CC 1024
#define NHH 16
#define HDD 64
#define MTOK 4096          // B*T
#define C3 3072
#define C4 4096

// ---------------- scratch (no allocation allowed) ----------------
__device__ float g_x1 [(size_t)MTOK * CC];
__device__ float g_y  [(size_t)MTOK * CC];

// bf16 split weights, transposed to [N][K]
__device__ __nv_bfloat16 g_wqkv_hi[(size_t)C3 * CC], g_wqkv_lo[(size_t)C3 * CC];
__device__ __nv_bfloat16 g_wa1_hi [(size_t)C4 * CC], g_wa1_lo [(size_t)C4 * CC];
__device__ __nv_bfloat16 g_wa2_hi [(size_t)CC * C4], g_wa2_lo [(size_t)CC * C4];
__device__ __nv_bfloat16 g_wf1_hi [(size_t)C4 * CC], g_wf1_lo [(size_t)C4 * CC];
__device__ __nv_bfloat16 g_wf2_hi [(size_t)CC * C4], g_wf2_lo [(size_t)CC * C4];
// bf16 split activations
__device__ __nv_bfloat16 g_ahi [(size_t)MTOK * CC], g_alo [(size_t)MTOK * CC];
__device__ __nv_bfloat16 g_hhi [(size_t)MTOK * C4], g_hlo [(size_t)MTOK * C4];
__device__ __nv_bfloat16 g_qkvh[(size_t)MTOK * C3], g_qkvl[(size_t)MTOK * C3];

__device__ __forceinline__ float gelu_f(float v) {
    return 0.5f * v * (1.0f + erff(v * 0.7071067811865475f));
}

// ======================= PTX helpers =======================
__device__ __forceinline__ uint32_t smem_u32(const void* p) {
    uint32_t a;
    asm("{ .reg .u64 t; cvta.to.shared.u64 t, %1; cvt.u32.u64 %0, t; }" : "=r"(a) : "l"(p));
    return a;
}
__device__ __forceinline__ void ldsm4(uint32_t* r, uint32_t addr) {
    asm volatile("ldmatrix.sync.aligned.m8n8.x4.shared.b16 {%0,%1,%2,%3}, [%4];"
                 : "=r"(r[0]), "=r"(r[1]), "=r"(r[2]), "=r"(r[3]) : "r"(addr));
}
__device__ __forceinline__ void ldsm4t(uint32_t* r, uint32_t addr) {
    asm volatile("ldmatrix.sync.aligned.m8n8.x4.trans.shared.b16 {%0,%1,%2,%3}, [%4];"
                 : "=r"(r[0]), "=r"(r[1]), "=r"(r[2]), "=r"(r[3]) : "r"(addr));
}
__device__ __forceinline__ void mma_bf16(float* d, const uint32_t* a, const uint32_t* b) {
    asm volatile(
        "mma.sync.aligned.m16n8k16.row.col.f32.bf16.bf16.f32 "
        "{%0,%1,%2,%3}, {%4,%5,%6,%7}, {%8,%9}, {%0,%1,%2,%3};"
        : "+f"(d[0]), "+f"(d[1]), "+f"(d[2]), "+f"(d[3])
        : "r"(a[0]), "r"(a[1]), "r"(a[2]), "r"(a[3]), "r"(b[0]), "r"(b[1]));
}
__device__ __forceinline__ void cp16(uint32_t dst, const void* src) {
    unsigned long long g = __cvta_generic_to_global(src);
    asm volatile("cp.async.ca.shared.global [%0], [%1], 16;" :: "r"(dst), "l"(g) : "memory");
}
__device__ __forceinline__ void cp_commit() {
    asm volatile("cp.async.commit_group;" ::: "memory");
}
template<int N>
__device__ __forceinline__ void cp_wait() {
    asm volatile("cp.async.wait_group %0;" :: "n"(N) : "memory");
}
__device__ __forceinline__ void split2(float a, float b, uint32_t& hi, uint32_t& lo) {
    __nv_bfloat16 ha = __float2bfloat16_rn(a), hb = __float2bfloat16_rn(b);
    __nv_bfloat162 H{ha, hb};
    __nv_bfloat162 L{__float2bfloat16_rn(a - __bfloat162float(ha)),
                     __float2bfloat16_rn(b - __bfloat162float(hb))};
    hi = *(uint32_t*)&H;
    lo = *(uint32_t*)&L;
}

// ======================= conversion kernels =======================
__global__ void __launch_bounds__(256)
cvt_act_kernel(const float* __restrict__ in, __nv_bfloat16* __restrict__ hi,
               __nv_bfloat16* __restrict__ lo, int n)
{
    int i = (blockIdx.x * 256 + threadIdx.x) * 4;
    if (i >= n) return;
    float4 v = *(const float4*)(in + i);
    uint32_t h0, l0, h1, l1;
    split2(v.x, v.y, h0, l0);
    split2(v.z, v.w, h1, l1);
    *(uint32_t*)(hi + i)     = h0;
    *(uint32_t*)(hi + i + 2) = h1;
    *(uint32_t*)(lo + i)     = l0;
    *(uint32_t*)(lo + i + 2) = l1;
}

__global__ void __launch_bounds__(256)
cvt_wt_kernel(const float* __restrict__ W, __nv_bfloat16* __restrict__ hi,
              __nv_bfloat16* __restrict__ lo, int K, int N)
{
    __shared__ float tile[32][33];
    const int n0 = blockIdx.x * 32, k0 = blockIdx.y * 32;
    const int tx = threadIdx.x & 31, ty = threadIdx.x >> 5;
#pragma unroll
    for (int r = 0; r < 4; ++r)
        tile[ty + r * 8][tx] = W[(size_t)(k0 + ty + r * 8) * N + n0 + tx];
    __syncthreads();
#pragma unroll
    for (int r = 0; r < 4; ++r) {
        int n = n0 + ty + r * 8;
        float v = tile[tx][ty + r * 8];
        __nv_bfloat16 h = __float2bfloat16_rn(v);
        hi[(size_t)n * K + k0 + tx] = h;
        lo[(size_t)n * K + k0 + tx] = __float2bfloat16_rn(v - __bfloat162float(h));
    }
}

// shared swizzle for 64B-row operand tiles
__device__ __forceinline__ uint32_t sw_off(int row, int kq) {
    return (uint32_t)(row * 64 + (((kq) ^ ((row >> 1) & 3)) << 4));
}

// ======================= HMMA split-bf16 GEMM, CTA 128x128 =======================
// 8 warps (2x4), warp tile 64x32, 3-stage cp.async, 2 CTAs/SM (regs capped to 128).
#define GSMEM (3 * 32768)
template<int MODE>
__global__ void __launch_bounds__(256, 2)
gemm_mma_kernel(const __nv_bfloat16* __restrict__ Ahi, const __nv_bfloat16* __restrict__ Alo,
                const __nv_bfloat16* __restrict__ Bhi, const __nv_bfloat16* __restrict__ Blo,
                const float* __restrict__ bias, float* __restrict__ Cf,
                __nv_bfloat16* __restrict__ Chi, __nv_bfloat16* __restrict__ Clo,
                int N, int K)
{
    extern __shared__ char smem[];
    const uint32_t sb = smem_u32(smem);

    const int t = threadIdx.x;
    const int wid = t >> 5, lane = t & 31;
    const int bm = blockIdx.y * 128;
    const int bn = blockIdx.x * 128;
    const int wm = wid >> 2, wn = wid & 3;

    const __nv_bfloat16* gsrc[4] = {Ahi, Alo, Bhi, Blo};

    float acc[4][4][4];
#pragma unroll
    for (int i = 0; i < 4; ++i)
#pragma unroll
        for (int j = 0; j < 4; ++j)
#pragma unroll
            for (int k = 0; k < 4; ++k) acc[i][j][k] = 0.0f;

    const int nc = K >> 5;

    const int g  = lane >> 3, lr = lane & 7;
    const int a_rit = lr + (g & 1) * 8, a_kqo = g >> 1;
    const int b_rit = lr + (g >> 1) * 8, b_kqo = g & 1;

    uint32_t aAhi[4], aAlo[4], aBhi[2], aBlo[2];
    int aRsw[4], bRsw[2];
#pragma unroll
    for (int mt = 0; mt < 4; ++mt) {
        int row = wm * 64 + mt * 16 + a_rit;
        aAhi[mt] = sb + 0     + row * 64;
        aAlo[mt] = sb + 8192  + row * 64;
        aRsw[mt] = (row >> 1) & 3;
    }
#pragma unroll
    for (int p = 0; p < 2; ++p) {
        int row = wn * 32 + p * 16 + b_rit;
        aBhi[p] = sb + 16384 + row * 64;
        aBlo[p] = sb + 24576 + row * 64;
        bRsw[p] = (row >> 1) & 3;
    }

    auto issue = [&](int c, int s) {
        const uint32_t st = sb + s * 32768;
        const int kb = c * 32;
#pragma unroll
        for (int i = 0; i < 8; ++i) {
            int u = t + i * 256;
            int arr = u >> 9, v = u & 511, row = v >> 2, kq = v & 3;
            const __nv_bfloat16* src = gsrc[arr] +
                (size_t)((arr < 2 ? bm : bn) + row) * K + kb + kq * 8;
            cp16(st + arr * 8192 + sw_off(row, kq), src);
        }
        cp_commit();
    };

    issue(0, 0);
    issue(1, 1);
    int s = 0;
    for (int c = 0; c < nc; ++c) {
        if (c + 2 < nc) { issue(c + 2, (c + 2) % 3); cp_wait<2>(); }
        else if (c + 1 < nc) cp_wait<1>();
        else cp_wait<0>();
        __syncthreads();

        const uint32_t stoff = (uint32_t)(s * 32768);
#pragma unroll
        for (int ks = 0; ks < 2; ++ks) {
            uint32_t ah[4][4], al[4][4], bh[4][2], bl[4][2];
#pragma unroll
            for (int mt = 0; mt < 4; ++mt) {
                uint32_t o = (uint32_t)((((2 * ks + a_kqo) ^ aRsw[mt]) << 4));
                ldsm4(ah[mt], aAhi[mt] + stoff + o);
                ldsm4(al[mt], aAlo[mt] + stoff + o);
            }
#pragma unroll
            for (int p = 0; p < 2; ++p) {
                uint32_t r[4];
                uint32_t o = (uint32_t)((((2 * ks + b_kqo) ^ bRsw[p]) << 4));
                ldsm4(r, aBhi[p] + stoff + o);
                bh[2 * p][0] = r[0]; bh[2 * p][1] = r[1];
                bh[2 * p + 1][0] = r[2]; bh[2 * p + 1][1] = r[3];
                ldsm4(r, aBlo[p] + stoff + o);
                bl[2 * p][0] = r[0]; bl[2 * p][1] = r[1];
                bl[2 * p + 1][0] = r[2]; bl[2 * p + 1][1] = r[3];
            }
#pragma unroll
            for (int mt = 0; mt < 4; ++mt)
#pragma unroll
                for (int nt = 0; nt < 4; ++nt) {
                    mma_bf16(acc[mt][nt], ah[mt], bh[nt]);
                    mma_bf16(acc[mt][nt], ah[mt], bl[nt]);
                    mma_bf16(acc[mt][nt], al[mt], bh[nt]);
                }
        }
        __syncthreads();
        s = (s + 1) % 3;
    }

    const int mrow = bm + wm * 64;
    const int ncol = bn + wn * 32;
#pragma unroll
    for (int mt = 0; mt < 4; ++mt) {
#pragma unroll
        for (int nt = 0; nt < 4; ++nt) {
            float* d = acc[mt][nt];
            int r0 = mrow + mt * 16 + (lane >> 2);
            int cix = ncol + nt * 8 + (lane & 3) * 2;
            float b0 = bias[cix], b1 = bias[cix + 1];
            float v00 = d[0] + b0, v01 = d[1] + b1;
            float v10 = d[2] + b0, v11 = d[3] + b1;
            if (MODE == 0) {
                float2 p0{v00, v01}, p1{v10, v11};
                *(float2*)&Cf[(size_t)r0 * N + cix]       = p0;
                *(float2*)&Cf[(size_t)(r0 + 8) * N + cix] = p1;
            } else {
                if (MODE == 1) {
                    v00 = gelu_f(v00); v01 = gelu_f(v01);
                    v10 = gelu_f(v10); v11 = gelu_f(v11);
                }
                uint32_t h0, l0, h1, l1;
                split2(v00, v01, h0, l0);
                split2(v10, v11, h1, l1);
                *(uint32_t*)&Chi[(size_t)r0 * N + cix]       = h0;
                *(uint32_t*)&Clo[(size_t)r0 * N + cix]       = l0;
                *(uint32_t*)&Chi[(size_t)(r0 + 8) * N + cix] = h1;
                *(uint32_t*)&Clo[(size_t)(r0 + 8) * N + cix] = l1;
            }
        }
    }
}

// ======================= HMMA causal attention (FA2-style) =======================
#define ASMEM 49152
__device__ __forceinline__ uint32_t asw(int row, int u) {
    return (uint32_t)(row * 128 + ((u ^ (row & 7)) << 4));
}

__global__ void __launch_bounds__(128, 3)
attn_mma_kernel(const __nv_bfloat16* __restrict__ qkvh, const __nv_bfloat16* __restrict__ qkvl,
                __nv_bfloat16* __restrict__ ohi, __nv_bfloat16* __restrict__ olo)
{
    extern __shared__ char asmem[];
    const uint32_t sb = smem_u32(asmem);

    const int t = threadIdx.x, wid = t >> 5, lane = t & 31;
    const int qb = blockIdx.x * 64;
    const int h  = blockIdx.y, b = blockIdx.z;

    const __nv_bfloat16* Kh_g = qkvh + (size_t)b * TT * C3 + h * HDD;
    const __nv_bfloat16* Kl_g = qkvl + (size_t)b * TT * C3 + h * HDD;
    const __nv_bfloat16* Qh_g = Kh_g + CC;
    const __nv_bfloat16* Ql_g = Kl_g + CC;
    const __nv_bfloat16* Vh_g = Kh_g + 2 * CC;
    const __nv_bfloat16* Vl_g = Kl_g + 2 * CC;

#pragma unroll
    for (int i = 0; i < 8; ++i) {
        int uu = t + i * 128;
        int arr = uu >> 9, v = uu & 511, row = v >> 3, u = v & 7;
        const __nv_bfloat16* src = (arr ? Ql_g : Qh_g) + (size_t)(qb + row) * C3 + u * 8;
        cp16(sb + arr * 8192 + asw(row, u), src);
    }
    cp_commit();

    const int g = lane >> 3, lr = lane & 7;
    const int r = lane >> 2, c = lane & 3;
    const int qrow = wid * 16 + lr + ((g & 1) << 3);
    const int a_u  = g >> 1;
    const int krit = lr + ((g >> 1) << 3);
    const int b_u  = g & 1;
    const int vrit = lr + ((g & 1) << 3);
    const int v_u  = g >> 1;

    float O[8][4];
#pragma unroll
    for (int i = 0; i < 8; ++i)
#pragma unroll
        for (int j = 0; j < 4; ++j) O[i][j] = 0.0f;
    float m0 = -1e30f, m1 = -1e30f, l0 = 0.0f, l1 = 0.0f;

    const int ntiles = blockIdx.x + 1;
    for (int kt = 0; kt < ntiles; ++kt) {
        const int kb = kt * 64;
        __syncthreads();
#pragma unroll
        for (int i = 0; i < 16; ++i) {
            int uu = t + i * 128;
            int arr = uu >> 9, v = uu & 511, row = v >> 3, u = v & 7;
            const __nv_bfloat16* src;
            if      (arr == 0) src = Kh_g + (size_t)(kb + row) * C3 + u * 8;
            else if (arr == 1) src = Kl_g + (size_t)(kb + row) * C3 + u * 8;
            else if (arr == 2) src = Vh_g + (size_t)(kb + row) * C3 + u * 8;
            else               src = Vl_g + (size_t)(kb + row) * C3 + u * 8;
            cp16(sb + 16384 + arr * 8192 + asw(row, u), src);
        }
        cp_commit();
        cp_wait<0>();
        __syncthreads();

        float S[8][4];
#pragma unroll
        for (int i = 0; i < 8; ++i)
#pragma unroll
            for (int j = 0; j < 4; ++j) S[i][j] = 0.0f;

#pragma unroll
        for (int kk = 0; kk < 4; ++kk) {
            uint32_t ah[4], al[4];
            uint32_t aoq = (uint32_t)(qrow * 128 + ((((kk << 1) | a_u) ^ (qrow & 7)) << 4));
            ldsm4(ah, sb + aoq);
            ldsm4(al, sb + 8192 + aoq);
#pragma unroll
            for (int p = 0; p < 4; ++p) {
                int krow = (p << 4) + krit;
                uint32_t ko = (uint32_t)(krow * 128 + ((((kk << 1) | b_u) ^ (krow & 7)) << 4));
                uint32_t bh[4], bl[4];
                ldsm4(bh, sb + 16384 + ko);
                ldsm4(bl, sb + 24576 + ko);
                mma_bf16(S[2 * p],     ah, bh);
                mma_bf16(S[2 * p],     ah, bl);
                mma_bf16(S[2 * p],     al, bh);
                mma_bf16(S[2 * p + 1], ah, bh + 2);
                mma_bf16(S[2 * p + 1], ah, bl + 2);
                mma_bf16(S[2 * p + 1], al, bh + 2);
            }
        }

#pragma unroll
        for (int nt = 0; nt < 8; ++nt)
#pragma unroll
            for (int e = 0; e < 4; ++e) S[nt][e] *= 0.125f;
        if (kt == blockIdx.x) {
            const int q0 = qb + wid * 16 + r, q1 = q0 + 8;
#pragma unroll
            for (int nt = 0; nt < 8; ++nt) {
                int k0 = kb + 8 * nt + 2 * c;
                if (k0     > q0) S[nt][0] = -1e30f;
                if (k0 + 1 > q0) S[nt][1] = -1e30f;
                if (k0     > q1) S[nt][2] = -1e30f;
                if (k0 + 1 > q1) S[nt][3] = -1e30f;
            }
        }

        float mx0 = -1e30f, mx1 = -1e30f;
#pragma unroll
        for (int nt = 0; nt < 8; ++nt) {
            mx0 = fmaxf(mx0, fmaxf(S[nt][0], S[nt][1]));
            mx1 = fmaxf(mx1, fmaxf(S[nt][2], S[nt][3]));
        }
        mx0 = fmaxf(mx0, __shfl_xor_sync(0xffffffffu, mx0, 1));
        mx0 = fmaxf(mx0, __shfl_xor_sync(0xffffffffu, mx0, 2));
        mx1 = fmaxf(mx1, __shfl_xor_sync(0xffffffffu, mx1, 1));
        mx1 = fmaxf(mx1, __shfl_xor_sync(0xffffffffu, mx1, 2));
        float mn0 = fmaxf(m0, mx0), mn1 = fmaxf(m1, mx1);
        float al0 = __expf(m0 - mn0), al1 = __expf(m1 - mn1);
        m0 = mn0; m1 = mn1;

        float s0 = 0.0f, s1 = 0.0f;
#pragma unroll
        for (int nt = 0; nt < 8; ++nt) {
            S[nt][0] = __expf(S[nt][0] - mn0);
            S[nt][1] = __expf(S[nt][1] - mn0);
            S[nt][2] = __expf(S[nt][2] - mn1);
            S[nt][3] = __expf(S[nt][3] - mn1);
            s0 += S[nt][0] + S[nt][1];
            s1 += S[nt][2] + S[nt][3];
        }
        l0 = l0 * al0 + s0;
        l1 = l1 * al1 + s1;
#pragma unroll
        for (int nt = 0; nt < 8; ++nt) {
            O[nt][0] *= al0; O[nt][1] *= al0;
            O[nt][2] *= al1; O[nt][3] *= al1;
        }

#pragma unroll
        for (int kk = 0; kk < 4; ++kk) {
            uint32_t ph[4], pl[4];
            split2(S[2 * kk][0],     S[2 * kk][1],     ph[0], pl[0]);
            split2(S[2 * kk][2],     S[2 * kk][3],     ph[1], pl[1]);
            split2(S[2 * kk + 1][0], S[2 * kk + 1][1], ph[2], pl[2]);
            split2(S[2 * kk + 1][2], S[2 * kk + 1][3], ph[3], pl[3]);
            int vrow = (kk << 4) + vrit;
#pragma unroll
            for (int p = 0; p < 4; ++p) {
                uint32_t vo = (uint32_t)(vrow * 128 + ((((p << 1) | v_u) ^ (vrow & 7)) << 4));
                uint32_t vh[4], vl[4];
                ldsm4t(vh, sb + 32768 + vo);
                ldsm4t(vl, sb + 40960 + vo);
                mma_bf16(O[2 * p],     ph, vh);
                mma_bf16(O[2 * p],     ph, vl);
                mma_bf16(O[2 * p],     pl, vh);
                mma_bf16(O[2 * p + 1], ph, vh + 2);
                mma_bf16(O[2 * p + 1], ph, vl + 2);
                mma_bf16(O[2 * p + 1], pl, vh + 2);
            }
        }
    }

    l0 += __shfl_xor_sync(0xffffffffu, l0, 1);
    l0 += __shfl_xor_sync(0xffffffffu, l0, 2);
    l1 += __shfl_xor_sync(0xffffffffu, l1, 1);
    l1 += __shfl_xor_sync(0xffffffffu, l1, 2);
    const float i0 = 1.0f / l0, i1 = 1.0f / l1;
    const int row0 = qb + wid * 16 + r, row1 = row0 + 8;
#pragma unroll
    for (int nt = 0; nt < 8; ++nt) {
        int col = h * HDD + 8 * nt + 2 * c;
        size_t idx0 = ((size_t)b * TT + row0) * CC + col;
        size_t idx1 = ((size_t)b * TT + row1) * CC + col;
        uint32_t h0, lo0, h1, lo1;
        split2(O[nt][0] * i0, O[nt][1] * i0, h0, lo0);
        split2(O[nt][2] * i1, O[nt][3] * i1, h1, lo1);
        *(uint32_t*)&ohi[idx0] = h0;
        *(uint32_t*)&olo[idx0] = lo0;
        *(uint32_t*)&ohi[idx1] = h1;
        *(uint32_t*)&olo[idx1] = lo1;
    }
}

// ---------------- LayerNorm + residual ----------------
__device__ __forceinline__ float block_sum(float v, float* red) {
    const int lane = threadIdx.x & 31, w = threadIdx.x >> 5;
#pragma unroll
    for (int o = 16; o; o >>= 1) v += __shfl_xor_sync(0xffffffffu, v, o);
    if (lane == 0) red[w] = v;
    __syncthreads();
    if (w == 0) {
        float s = (lane < 8) ? red[lane] : 0.0f;
#pragma unroll
        for (int o = 4; o; o >>= 1) s += __shfl_xor_sync(0xffffffffu, s, o);
        if (lane == 0) red[0] = s;
    }
    __syncthreads();
    float rr = red[0];
    __syncthreads();
    return rr;
}

template<bool SPLIT>
__global__ void __launch_bounds__(256)
ln_res_kernel(const float* __restrict__ res, const float* __restrict__ y,
              const float* __restrict__ g, const float* __restrict__ be,
              float* __restrict__ out,
              __nv_bfloat16* __restrict__ ohi, __nv_bfloat16* __restrict__ olo)
{
    __shared__ float red[8];
    const int row = blockIdx.x;
    const int t = threadIdx.x;
    const float* yr = y + (size_t)row * CC;

    float v[4];
    float s = 0.0f;
#pragma unroll
    for (int i = 0; i < 4; ++i) { v[i] = yr[t + i * 256]; s += v[i]; }
    const float mean = block_sum(s, red) * (1.0f / CC);

    float sq = 0.0f;
#pragma unroll
    for (int i = 0; i < 4; ++i) { float d = v[i] - mean; sq += d * d; }
    const float var = block_sum(sq, red) * (1.0f / CC);
    const float rstd = rsqrtf(var + 1e-5f);

    const float* rr = res + (size_t)row * CC;
    float* orow = out + (size_t)row * CC;
#pragma unroll
    for (int i = 0; i < 4; ++i) {
        int cix = t + i * 256;
        float o = rr[cix] + (v[i] - mean) * rstd * g[cix] + be[cix];
        orow[cix] = o;
        if (SPLIT) {
            __nv_bfloat16 hh = __float2bfloat16_rn(o);
            ohi[(size_t)row * CC + cix] = hh;
            olo[(size_t)row * CC + cix] = __float2bfloat16_rn(o - __bfloat162float(hh));
        }
    }
}

// ---------------- launch ----------------
extern "C" void kernel_launch(void* const* d_in, const int* in_sizes, int n_in,
                              void* d_out, int out_size)
{
    const float* x      = (const float*)d_in[0];
    const float* w_attn = (const float*)d_in[1];
    const float* b_attn = (const float*)d_in[2];
    const float* wa1    = (const float*)d_in[3];
    const float* ba1    = (const float*)d_in[4];
    const float* wa2    = (const float*)d_in[5];
    const float* ba2    = (const float*)d_in[6];
    const float* g1     = (const float*)d_in[7];
    const float* be1    = (const float*)d_in[8];
    const float* wf1    = (const float*)d_in[9];
    const float* bf1    = (const float*)d_in[10];
    const float* wf2    = (const float*)d_in[11];
    const float* bf2    = (const float*)d_in[12];
    const float* g2     = (const float*)d_in[13];
    const float* be2    = (const float*)d_in[14];
    float* out = (float*)d_out;

    float *x1, *y;
    cudaGetSymbolAddress((void**)&x1, g_x1);
    cudaGetSymbolAddress((void**)&y,  g_y);

    __nv_bfloat16 *wqkv_hi, *wqkv_lo, *wa1_hi, *wa1_lo, *wa2_hi, *wa2_lo,
                  *wf1_hi, *wf1_lo, *wf2_hi, *wf2_lo, *ahi, *alo, *hhi, *hlo,
                  *qkvh, *qkvl;
    cudaGetSymbolAddress((void**)&wqkv_hi, g_wqkv_hi);
    cudaGetSymbolAddress((void**)&wqkv_lo, g_wqkv_lo);
    cudaGetSymbolAddress((void**)&wa1_hi,  g_wa1_hi);
    cudaGetSymbolAddress((void**)&wa1_lo,  g_wa1_lo);
    cudaGetSymbolAddress((void**)&wa2_hi,  g_wa2_hi);
    cudaGetSymbolAddress((void**)&wa2_lo,  g_wa2_lo);
    cudaGetSymbolAddress((void**)&wf1_hi,  g_wf1_hi);
    cudaGetSymbolAddress((void**)&wf1_lo,  g_wf1_lo);
    cudaGetSymbolAddress((void**)&wf2_hi,  g_wf2_hi);
    cudaGetSymbolAddress((void**)&wf2_lo,  g_wf2_lo);
    cudaGetSymbolAddress((void**)&ahi,     g_ahi);
    cudaGetSymbolAddress((void**)&alo,     g_alo);
    cudaGetSymbolAddress((void**)&hhi,     g_hhi);
    cudaGetSymbolAddress((void**)&hlo,     g_hlo);
    cudaGetSymbolAddress((void**)&qkvh,    g_qkvh);
    cudaGetSymbolAddress((void**)&qkvl,    g_qkvl);

    cudaFuncSetAttribute(attn_mma_kernel, cudaFuncAttributeMaxDynamicSharedMemorySize, ASMEM);
    cudaFuncSetAttribute(gemm_mma_kernel<0>, cudaFuncAttributeMaxDynamicSharedMemorySize, GSMEM);
    cudaFuncSetAttribute(gemm_mma_kernel<1>, cudaFuncAttributeMaxDynamicSharedMemorySize, GSMEM);
    cudaFuncSetAttribute(gemm_mma_kernel<2>, cudaFuncAttributeMaxDynamicSharedMemorySize, GSMEM);

    // weight transpose + bf16 split
    cvt_wt_kernel<<<dim3(C3 / 32, CC / 32), 256>>>(w_attn, wqkv_hi, wqkv_lo, CC, C3);
    cvt_wt_kernel<<<dim3(C4 / 32, CC / 32), 256>>>(wa1, wa1_hi, wa1_lo, CC, C4);
    cvt_wt_kernel<<<dim3(CC / 32, C4 / 32), 256>>>(wa2, wa2_hi, wa2_lo, C4, CC);
    cvt_wt_kernel<<<dim3(C4 / 32, CC / 32), 256>>>(wf1, wf1_hi, wf1_lo, CC, C4);
    cvt_wt_kernel<<<dim3(CC / 32, C4 / 32), 256>>>(wf2, wf2_hi, wf2_lo, C4, CC);

    // 1) qkv = x @ w_attn + b_attn -> split bf16
    cvt_act_kernel<<<(MTOK * CC) / 1024, 256>>>(x, ahi, alo, MTOK * CC);
    gemm_mma_kernel<2><<<dim3(C3 / 128, MTOK / 128), 256, GSMEM>>>(
        ahi, alo, wqkv_hi, wqkv_lo, b_attn, nullptr, qkvh, qkvl, C3, CC);
    // 2) attention (HMMA) -> split bf16 att
    attn_mma_kernel<<<dim3(TT / 64, NHH, BB), 128, ASMEM>>>(qkvh, qkvl, ahi, alo);
    // 3) h = gelu(att @ wa1 + ba1) -> split bf16
    gemm_mma_kernel<1><<<dim3(C4 / 128, MTOK / 128), 256, GSMEM>>>(
        ahi, alo, wa1_hi, wa1_lo, ba1, nullptr, hhi, hlo, C4, CC);
    // 4) y = h @ wa2 + ba2
    gemm_mma_kernel<0><<<dim3(CC / 128, MTOK / 128), 256, GSMEM>>>(
        hhi, hlo, wa2_hi, wa2_lo, ba2, y, nullptr, nullptr, CC, C4);
    // 5) x1 = x + ln(y); emit split bf16 x1
    ln_res_kernel<true><<<MTOK, 256>>>(x, y, g1, be1, x1, ahi, alo);
    // 6) h = gelu(x1 @ wf1 + bf1) -> split bf16
    gemm_mma_kernel<1><<<dim3(C4 / 128, MTOK / 128), 256, GSMEM>>>(
        ahi, alo, wf1_hi, wf1_lo, bf1, nullptr, hhi, hlo, C4, CC);
    // 7) y = h @ wf2 + bf2
    gemm_mma_kernel<0><<<dim3(CC / 128, MTOK / 128), 256, GSMEM>>>(
        hhi, hlo, wf2_hi, wf2_lo, bf2, y, nullptr, nullptr, CC, C4);
    // 8) out = x1 + ln(y)
    ln_res_kernel<false><<<MTOK, 256>>>(x1, y, g2, be2, out, nullptr, nullptr);
}

// round 7
// speedup vs baseline: 1.3897x; 1.3334x over previous
#include <cuda_runtime.h>
#include <cuda_fp16.h>
#include <math.h>
#include <stdint.h>

// Problem dims (fixed)
#define BB 2
#define TT 2048
#define CC 1024
#define NHH 16
#define HDD 64
#define MTOK 4096          // B*T
#define C3 3072
#define C4 4096

// ---------------- scratch (no allocation allowed) ----------------
__device__ float g_x1 [(size_t)MTOK * CC];
__device__ float g_y  [(size_t)MTOK * CC];

// fp16 split weights, transposed to [N][K]
__device__ __half g_wqkv_hi[(size_t)C3 * CC], g_wqkv_lo[(size_t)C3 * CC];
__device__ __half g_wa1_hi [(size_t)C4 * CC], g_wa1_lo [(size_t)C4 * CC];
__device__ __half g_wa2_hi [(size_t)CC * C4], g_wa2_lo [(size_t)CC * C4];
__device__ __half g_wf1_hi [(size_t)C4 * CC], g_wf1_lo [(size_t)C4 * CC];
__device__ __half g_wf2_hi [(size_t)CC * C4], g_wf2_lo [(size_t)CC * C4];
// fp16 activations (hi; lo only for x feeding the 3-pass qkv GEMM)
__device__ __half g_ahi [(size_t)MTOK * CC], g_alo [(size_t)MTOK * CC];
__device__ __half g_hhi [(size_t)MTOK * C4];
__device__ __half g_qkvh[(size_t)MTOK * C3], g_qkvl[(size_t)MTOK * C3];

__device__ __forceinline__ float gelu_f(float v) {
    return 0.5f * v * (1.0f + erff(v * 0.7071067811865475f));
}

// ======================= PTX helpers =======================
__device__ __forceinline__ uint32_t smem_u32(const void* p) {
    uint32_t a;
    asm("{ .reg .u64 t; cvta.to.shared.u64 t, %1; cvt.u32.u64 %0, t; }" : "=r"(a) : "l"(p));
    return a;
}
__device__ __forceinline__ void ldsm4(uint32_t* r, uint32_t addr) {
    asm volatile("ldmatrix.sync.aligned.m8n8.x4.shared.b16 {%0,%1,%2,%3}, [%4];"
                 : "=r"(r[0]), "=r"(r[1]), "=r"(r[2]), "=r"(r[3]) : "r"(addr));
}
__device__ __forceinline__ void ldsm4t(uint32_t* r, uint32_t addr) {
    asm volatile("ldmatrix.sync.aligned.m8n8.x4.trans.shared.b16 {%0,%1,%2,%3}, [%4];"
                 : "=r"(r[0]), "=r"(r[1]), "=r"(r[2]), "=r"(r[3]) : "r"(addr));
}
__device__ __forceinline__ void mma_f16(float* d, const uint32_t* a, const uint32_t* b) {
    asm volatile(
        "mma.sync.aligned.m16n8k16.row.col.f32.f16.f16.f32 "
        "{%0,%1,%2,%3}, {%4,%5,%6,%7}, {%8,%9}, {%0,%1,%2,%3};"
        : "+f"(d[0]), "+f"(d[1]), "+f"(d[2]), "+f"(d[3])
        : "r"(a[0]), "r"(a[1]), "r"(a[2]), "r"(a[3]), "r"(b[0]), "r"(b[1]));
}
__device__ __forceinline__ void cp16(uint32_t dst, const void* src) {
    unsigned long long g = __cvta_generic_to_global(src);
    asm volatile("cp.async.ca.shared.global [%0], [%1], 16;" :: "r"(dst), "l"(g) : "memory");
}
__device__ __forceinline__ void cp_commit() {
    asm volatile("cp.async.commit_group;" ::: "memory");
}
template<int N>
__device__ __forceinline__ void cp_wait() {
    asm volatile("cp.async.wait_group %0;" :: "n"(N) : "memory");
}
// split two floats into packed fp16x2 hi and lo
__device__ __forceinline__ void split2(float a, float b, uint32_t& hi, uint32_t& lo) {
    __half ha = __float2half_rn(a), hb = __float2half_rn(b);
    __half2 H = __halves2half2(ha, hb);
    __half2 L = __halves2half2(__float2half_rn(a - __half2float(ha)),
                               __float2half_rn(b - __half2float(hb)));
    hi = *(uint32_t*)&H;
    lo = *(uint32_t*)&L;
}
__device__ __forceinline__ uint32_t pack2h(float a, float b) {
    __half2 H = __halves2half2(__float2half_rn(a), __float2half_rn(b));
    return *(uint32_t*)&H;
}

// ======================= conversion kernels =======================
__global__ void __launch_bounds__(256)
cvt_act_kernel(const float* __restrict__ in, __half* __restrict__ hi,
               __half* __restrict__ lo, int n)
{
    int i = (blockIdx.x * 256 + threadIdx.x) * 4;
    if (i >= n) return;
    float4 v = *(const float4*)(in + i);
    uint32_t h0, l0, h1, l1;
    split2(v.x, v.y, h0, l0);
    split2(v.z, v.w, h1, l1);
    *(uint32_t*)(hi + i)     = h0;
    *(uint32_t*)(hi + i + 2) = h1;
    *(uint32_t*)(lo + i)     = l0;
    *(uint32_t*)(lo + i + 2) = l1;
}

__global__ void __launch_bounds__(256)
cvt_wt_kernel(const float* __restrict__ W, __half* __restrict__ hi,
              __half* __restrict__ lo, int K, int N)
{
    __shared__ float tile[32][33];
    const int n0 = blockIdx.x * 32, k0 = blockIdx.y * 32;
    const int tx = threadIdx.x & 31, ty = threadIdx.x >> 5;
#pragma unroll
    for (int r = 0; r < 4; ++r)
        tile[ty + r * 8][tx] = W[(size_t)(k0 + ty + r * 8) * N + n0 + tx];
    __syncthreads();
#pragma unroll
    for (int r = 0; r < 4; ++r) {
        int n = n0 + ty + r * 8;
        float v = tile[tx][ty + r * 8];
        __half h = __float2half_rn(v);
        hi[(size_t)n * K + k0 + tx] = h;
        lo[(size_t)n * K + k0 + tx] = __float2half_rn(v - __half2float(h));
    }
}

// shared swizzle for 64B-row operand tiles
__device__ __forceinline__ uint32_t sw_off(int row, int kq) {
    return (uint32_t)(row * 64 + (((kq) ^ ((row >> 1) & 3)) << 4));
}

// ======================= HMMA split-fp16 GEMM, CTA 128x128 =======================
// 8 warps (2x4), warp tile 64x32, 3-stage cp.async, 2 CTAs/SM.
// PASSES=2: D = Ah*Bh + Ah*Bl (Alo unused).  PASSES=3: + Al*Bh.
// MODE 0: fp32 out.  MODE 1: exact-GELU, fp16 hi out.  MODE 2: fp16 hi+lo out.
template<int MODE, int PASSES>
__global__ void __launch_bounds__(256, 2)
gemm_mma_kernel(const __half* __restrict__ Ahi, const __half* __restrict__ Alo,
                const __half* __restrict__ Bhi, const __half* __restrict__ Blo,
                const float* __restrict__ bias, float* __restrict__ Cf,
                __half* __restrict__ Chi, __half* __restrict__ Clo,
                int N, int K)
{
    constexpr uint32_t STAGE   = (PASSES == 3) ? 32768u : 24576u;
    constexpr uint32_t ALO_OFF = 8192u;
    constexpr uint32_t BHI_OFF = (PASSES == 3) ? 16384u : 8192u;
    constexpr uint32_t BLO_OFF = BHI_OFF + 8192u;
    constexpr int UNITS = (PASSES == 3) ? 2048 : 1536;

    extern __shared__ char smem[];
    const uint32_t sb = smem_u32(smem);

    const int t = threadIdx.x;
    const int wid = t >> 5, lane = t & 31;
    const int bm = blockIdx.y * 128;
    const int bn = blockIdx.x * 128;
    const int wm = wid >> 2, wn = wid & 3;

    const __half* gsrc[4] = {Ahi, Alo, Bhi, Blo};
    const uint32_t goff[4] = {0u, ALO_OFF, BHI_OFF, BLO_OFF};

    float acc[4][4][4];
#pragma unroll
    for (int i = 0; i < 4; ++i)
#pragma unroll
        for (int j = 0; j < 4; ++j)
#pragma unroll
            for (int k = 0; k < 4; ++k) acc[i][j][k] = 0.0f;

    const int nc = K >> 5;

    const int g  = lane >> 3, lr = lane & 7;
    const int a_rit = lr + (g & 1) * 8, a_kqo = g >> 1;
    const int b_rit = lr + (g >> 1) * 8, b_kqo = g & 1;

    uint32_t aAhi[4], aAlo[4], aBhi[2], aBlo[2];
    int aRsw[4], bRsw[2];
#pragma unroll
    for (int mt = 0; mt < 4; ++mt) {
        int row = wm * 64 + mt * 16 + a_rit;
        aAhi[mt] = sb + row * 64;
        aAlo[mt] = sb + ALO_OFF + row * 64;
        aRsw[mt] = (row >> 1) & 3;
    }
#pragma unroll
    for (int p = 0; p < 2; ++p) {
        int row = wn * 32 + p * 16 + b_rit;
        aBhi[p] = sb + BHI_OFF + row * 64;
        aBlo[p] = sb + BLO_OFF + row * 64;
        bRsw[p] = (row >> 1) & 3;
    }

    auto issue = [&](int c, int s) {
        const uint32_t st = sb + s * STAGE;
        const int kb = c * 32;
#pragma unroll
        for (int i = 0; i < UNITS / 256; ++i) {
            int u = t + i * 256;
            int arr, v;
            if (PASSES == 3) { arr = u >> 9; v = u & 511; }
            else { arr = (u < 512) ? 0 : 2 + ((u - 512) >> 9); v = (u < 512) ? u : ((u - 512) & 511); }
            int row = v >> 2, kq = v & 3;
            const __half* src = gsrc[arr] +
                (size_t)((arr < 2 ? bm : bn) + row) * K + kb + kq * 8;
            cp16(st + goff[arr] + sw_off(row, kq), src);
        }
        cp_commit();
    };

    issue(0, 0);
    issue(1, 1);
    int s = 0;
    for (int c = 0; c < nc; ++c) {
        if (c + 2 < nc) { issue(c + 2, (c + 2) % 3); cp_wait<2>(); }
        else if (c + 1 < nc) cp_wait<1>();
        else cp_wait<0>();
        __syncthreads();

        const uint32_t stoff = (uint32_t)(s * STAGE);
#pragma unroll
        for (int ks = 0; ks < 2; ++ks) {
            uint32_t ah[4][4], al[4][4], bh[4][2], bl[4][2];
#pragma unroll
            for (int mt = 0; mt < 4; ++mt) {
                uint32_t o = (uint32_t)((((2 * ks + a_kqo) ^ aRsw[mt]) << 4));
                ldsm4(ah[mt], aAhi[mt] + stoff + o);
                if (PASSES == 3) ldsm4(al[mt], aAlo[mt] + stoff + o);
            }
#pragma unroll
            for (int p = 0; p < 2; ++p) {
                uint32_t r[4];
                uint32_t o = (uint32_t)((((2 * ks + b_kqo) ^ bRsw[p]) << 4));
                ldsm4(r, aBhi[p] + stoff + o);
                bh[2 * p][0] = r[0]; bh[2 * p][1] = r[1];
                bh[2 * p + 1][0] = r[2]; bh[2 * p + 1][1] = r[3];
                ldsm4(r, aBlo[p] + stoff + o);
                bl[2 * p][0] = r[0]; bl[2 * p][1] = r[1];
                bl[2 * p + 1][0] = r[2]; bl[2 * p + 1][1] = r[3];
            }
#pragma unroll
            for (int mt = 0; mt < 4; ++mt)
#pragma unroll
                for (int nt = 0; nt < 4; ++nt) {
                    mma_f16(acc[mt][nt], ah[mt], bh[nt]);
                    mma_f16(acc[mt][nt], ah[mt], bl[nt]);
                    if (PASSES == 3) mma_f16(acc[mt][nt], al[mt], bh[nt]);
                }
        }
        __syncthreads();
        s = (s + 1) % 3;
    }

    const int mrow = bm + wm * 64;
    const int ncol = bn + wn * 32;
#pragma unroll
    for (int mt = 0; mt < 4; ++mt) {
#pragma unroll
        for (int nt = 0; nt < 4; ++nt) {
            float* d = acc[mt][nt];
            int r0 = mrow + mt * 16 + (lane >> 2);
            int cix = ncol + nt * 8 + (lane & 3) * 2;
            float b0 = bias[cix], b1 = bias[cix + 1];
            float v00 = d[0] + b0, v01 = d[1] + b1;
            float v10 = d[2] + b0, v11 = d[3] + b1;
            if (MODE == 0) {
                float2 p0{v00, v01}, p1{v10, v11};
                *(float2*)&Cf[(size_t)r0 * N + cix]       = p0;
                *(float2*)&Cf[(size_t)(r0 + 8) * N + cix] = p1;
            } else if (MODE == 1) {
                v00 = gelu_f(v00); v01 = gelu_f(v01);
                v10 = gelu_f(v10); v11 = gelu_f(v11);
                *(uint32_t*)&Chi[(size_t)r0 * N + cix]       = pack2h(v00, v01);
                *(uint32_t*)&Chi[(size_t)(r0 + 8) * N + cix] = pack2h(v10, v11);
            } else {
                uint32_t h0, l0, h1, l1;
                split2(v00, v01, h0, l0);
                split2(v10, v11, h1, l1);
                *(uint32_t*)&Chi[(size_t)r0 * N + cix]       = h0;
                *(uint32_t*)&Clo[(size_t)r0 * N + cix]       = l0;
                *(uint32_t*)&Chi[(size_t)(r0 + 8) * N + cix] = h1;
                *(uint32_t*)&Clo[(size_t)(r0 + 8) * N + cix] = l1;
            }
        }
    }
}

// ======================= HMMA causal attention (FA2-style, fp16 3-pass) ========
#define ASMEM 49152
__device__ __forceinline__ uint32_t asw(int row, int u) {
    return (uint32_t)(row * 128 + ((u ^ (row & 7)) << 4));
}

__global__ void __launch_bounds__(128, 3)
attn_mma_kernel(const __half* __restrict__ qkvh, const __half* __restrict__ qkvl,
                __half* __restrict__ ohi)
{
    extern __shared__ char asmem[];
    const uint32_t sb = smem_u32(asmem);

    const int t = threadIdx.x, wid = t >> 5, lane = t & 31;
    const int qb = blockIdx.x * 64;
    const int h  = blockIdx.y, b = blockIdx.z;

    const __half* Kh_g = qkvh + (size_t)b * TT * C3 + h * HDD;
    const __half* Kl_g = qkvl + (size_t)b * TT * C3 + h * HDD;
    const __half* Qh_g = Kh_g + CC;
    const __half* Ql_g = Kl_g + CC;
    const __half* Vh_g = Kh_g + 2 * CC;
    const __half* Vl_g = Kl_g + 2 * CC;

#pragma unroll
    for (int i = 0; i < 8; ++i) {
        int uu = t + i * 128;
        int arr = uu >> 9, v = uu & 511, row = v >> 3, u = v & 7;
        const __half* src = (arr ? Ql_g : Qh_g) + (size_t)(qb + row) * C3 + u * 8;
        cp16(sb + arr * 8192 + asw(row, u), src);
    }
    cp_commit();

    const int g = lane >> 3, lr = lane & 7;
    const int r = lane >> 2, c = lane & 3;
    const int qrow = wid * 16 + lr + ((g & 1) << 3);
    const int a_u  = g >> 1;
    const int krit = lr + ((g >> 1) << 3);
    const int b_u  = g & 1;
    const int vrit = lr + ((g & 1) << 3);
    const int v_u  = g >> 1;

    float O[8][4];
#pragma unroll
    for (int i = 0; i < 8; ++i)
#pragma unroll
        for (int j = 0; j < 4; ++j) O[i][j] = 0.0f;
    float m0 = -1e30f, m1 = -1e30f, l0 = 0.0f, l1 = 0.0f;

    const int ntiles = blockIdx.x + 1;
    for (int kt = 0; kt < ntiles; ++kt) {
        const int kb = kt * 64;
        __syncthreads();
#pragma unroll
        for (int i = 0; i < 16; ++i) {
            int uu = t + i * 128;
            int arr = uu >> 9, v = uu & 511, row = v >> 3, u = v & 7;
            const __half* src;
            if      (arr == 0) src = Kh_g + (size_t)(kb + row) * C3 + u * 8;
            else if (arr == 1) src = Kl_g + (size_t)(kb + row) * C3 + u * 8;
            else if (arr == 2) src = Vh_g + (size_t)(kb + row) * C3 + u * 8;
            else               src = Vl_g + (size_t)(kb + row) * C3 + u * 8;
            cp16(sb + 16384 + arr * 8192 + asw(row, u), src);
        }
        cp_commit();
        cp_wait<0>();
        __syncthreads();

        float S[8][4];
#pragma unroll
        for (int i = 0; i < 8; ++i)
#pragma unroll
            for (int j = 0; j < 4; ++j) S[i][j] = 0.0f;

#pragma unroll
        for (int kk = 0; kk < 4; ++kk) {
            uint32_t ah[4], al[4];
            uint32_t aoq = (uint32_t)(qrow * 128 + ((((kk << 1) | a_u) ^ (qrow & 7)) << 4));
            ldsm4(ah, sb + aoq);
            ldsm4(al, sb + 8192 + aoq);
#pragma unroll
            for (int p = 0; p < 4; ++p) {
                int krow = (p << 4) + krit;
                uint32_t ko = (uint32_t)(krow * 128 + ((((kk << 1) | b_u) ^ (krow & 7)) << 4));
                uint32_t bh[4], bl[4];
                ldsm4(bh, sb + 16384 + ko);
                ldsm4(bl, sb + 24576 + ko);
                mma_f16(S[2 * p],     ah, bh);
                mma_f16(S[2 * p],     ah, bl);
                mma_f16(S[2 * p],     al, bh);
                mma_f16(S[2 * p + 1], ah, bh + 2);
                mma_f16(S[2 * p + 1], ah, bl + 2);
                mma_f16(S[2 * p + 1], al, bh + 2);
            }
        }

#pragma unroll
        for (int nt = 0; nt < 8; ++nt)
#pragma unroll
            for (int e = 0; e < 4; ++e) S[nt][e] *= 0.125f;
        if (kt == blockIdx.x) {
            const int q0 = qb + wid * 16 + r, q1 = q0 + 8;
#pragma unroll
            for (int nt = 0; nt < 8; ++nt) {
                int k0 = kb + 8 * nt + 2 * c;
                if (k0     > q0) S[nt][0] = -1e30f;
                if (k0 + 1 > q0) S[nt][1] = -1e30f;
                if (k0     > q1) S[nt][2] = -1e30f;
                if (k0 + 1 > q1) S[nt][3] = -1e30f;
            }
        }

        float mx0 = -1e30f, mx1 = -1e30f;
#pragma unroll
        for (int nt = 0; nt < 8; ++nt) {
            mx0 = fmaxf(mx0, fmaxf(S[nt][0], S[nt][1]));
            mx1 = fmaxf(mx1, fmaxf(S[nt][2], S[nt][3]));
        }
        mx0 = fmaxf(mx0, __shfl_xor_sync(0xffffffffu, mx0, 1));
        mx0 = fmaxf(mx0, __shfl_xor_sync(0xffffffffu, mx0, 2));
        mx1 = fmaxf(mx1, __shfl_xor_sync(0xffffffffu, mx1, 1));
        mx1 = fmaxf(mx1, __shfl_xor_sync(0xffffffffu, mx1, 2));
        float mn0 = fmaxf(m0, mx0), mn1 = fmaxf(m1, mx1);
        float al0 = __expf(m0 - mn0), al1 = __expf(m1 - mn1);
        m0 = mn0; m1 = mn1;

        float s0 = 0.0f, s1 = 0.0f;
#pragma unroll
        for (int nt = 0; nt < 8; ++nt) {
            S[nt][0] = __expf(S[nt][0] - mn0);
            S[nt][1] = __expf(S[nt][1] - mn0);
            S[nt][2] = __expf(S[nt][2] - mn1);
            S[nt][3] = __expf(S[nt][3] - mn1);
            s0 += S[nt][0] + S[nt][1];
            s1 += S[nt][2] + S[nt][3];
        }
        l0 = l0 * al0 + s0;
        l1 = l1 * al1 + s1;
#pragma unroll
        for (int nt = 0; nt < 8; ++nt) {
            O[nt][0] *= al0; O[nt][1] *= al0;
            O[nt][2] *= al1; O[nt][3] *= al1;
        }

#pragma unroll
        for (int kk = 0; kk < 4; ++kk) {
            uint32_t ph[4], pl[4];
            split2(S[2 * kk][0],     S[2 * kk][1],     ph[0], pl[0]);
            split2(S[2 * kk][2],     S[2 * kk][3],     ph[1], pl[1]);
            split2(S[2 * kk + 1][0], S[2 * kk + 1][1], ph[2], pl[2]);
            split2(S[2 * kk + 1][2], S[2 * kk + 1][3], ph[3], pl[3]);
            int vrow = (kk << 4) + vrit;
#pragma unroll
            for (int p = 0; p < 4; ++p) {
                uint32_t vo = (uint32_t)(vrow * 128 + ((((p << 1) | v_u) ^ (vrow & 7)) << 4));
                uint32_t vh[4], vl[4];
                ldsm4t(vh, sb + 32768 + vo);
                ldsm4t(vl, sb + 40960 + vo);
                mma_f16(O[2 * p],     ph, vh);
                mma_f16(O[2 * p],     ph, vl);
                mma_f16(O[2 * p],     pl, vh);
                mma_f16(O[2 * p + 1], ph, vh + 2);
                mma_f16(O[2 * p + 1], ph, vl + 2);
                mma_f16(O[2 * p + 1], pl, vh + 2);
            }
        }
    }

    l0 += __shfl_xor_sync(0xffffffffu, l0, 1);
    l0 += __shfl_xor_sync(0xffffffffu, l0, 2);
    l1 += __shfl_xor_sync(0xffffffffu, l1, 1);
    l1 += __shfl_xor_sync(0xffffffffu, l1, 2);
    const float i0 = 1.0f / l0, i1 = 1.0f / l1;
    const int row0 = qb + wid * 16 + r, row1 = row0 + 8;
#pragma unroll
    for (int nt = 0; nt < 8; ++nt) {
        int col = h * HDD + 8 * nt + 2 * c;
        size_t idx0 = ((size_t)b * TT + row0) * CC + col;
        size_t idx1 = ((size_t)b * TT + row1) * CC + col;
        *(uint32_t*)&ohi[idx0] = pack2h(O[nt][0] * i0, O[nt][1] * i0);
        *(uint32_t*)&ohi[idx1] = pack2h(O[nt][2] * i1, O[nt][3] * i1);
    }
}

// ---------------- LayerNorm + residual ----------------
__device__ __forceinline__ float block_sum(float v, float* red) {
    const int lane = threadIdx.x & 31, w = threadIdx.x >> 5;
#pragma unroll
    for (int o = 16; o; o >>= 1) v += __shfl_xor_sync(0xffffffffu, v, o);
    if (lane == 0) red[w] = v;
    __syncthreads();
    if (w == 0) {
        float s = (lane < 8) ? red[lane] : 0.0f;
#pragma unroll
        for (int o = 4; o; o >>= 1) s += __shfl_xor_sync(0xffffffffu, s, o);
        if (lane == 0) red[0] = s;
    }
    __syncthreads();
    float rr = red[0];
    __syncthreads();
    return rr;
}

template<bool SPLIT>
__global__ void __launch_bounds__(256)
ln_res_kernel(const float* __restrict__ res, const float* __restrict__ y,
              const float* __restrict__ g, const float* __restrict__ be,
              float* __restrict__ out, __half* __restrict__ ohi)
{
    __shared__ float red[8];
    const int row = blockIdx.x;
    const int t = threadIdx.x;
    const float* yr = y + (size_t)row * CC;

    float v[4];
    float s = 0.0f;
#pragma unroll
    for (int i = 0; i < 4; ++i) { v[i] = yr[t + i * 256]; s += v[i]; }
    const float mean = block_sum(s, red) * (1.0f / CC);

    float sq = 0.0f;
#pragma unroll
    for (int i = 0; i < 4; ++i) { float d = v[i] - mean; sq += d * d; }
    const float var = block_sum(sq, red) * (1.0f / CC);
    const float rstd = rsqrtf(var + 1e-5f);

    const float* rr = res + (size_t)row * CC;
    float* orow = out + (size_t)row * CC;
#pragma unroll
    for (int i = 0; i < 4; ++i) {
        int cix = t + i * 256;
        float o = rr[cix] + (v[i] - mean) * rstd * g[cix] + be[cix];
        orow[cix] = o;
        if (SPLIT) ohi[(size_t)row * CC + cix] = __float2half_rn(o);
    }
}

// ---------------- launch ----------------
extern "C" void kernel_launch(void* const* d_in, const int* in_sizes, int n_in,
                              void* d_out, int out_size)
{
    const float* x      = (const float*)d_in[0];
    const float* w_attn = (const float*)d_in[1];
    const float* b_attn = (const float*)d_in[2];
    const float* wa1    = (const float*)d_in[3];
    const float* ba1    = (const float*)d_in[4];
    const float* wa2    = (const float*)d_in[5];
    const float* ba2    = (const float*)d_in[6];
    const float* g1     = (const float*)d_in[7];
    const float* be1    = (const float*)d_in[8];
    const float* wf1    = (const float*)d_in[9];
    const float* bf1    = (const float*)d_in[10];
    const float* wf2    = (const float*)d_in[11];
    const float* bf2    = (const float*)d_in[12];
    const float* g2     = (const float*)d_in[13];
    const float* be2    = (const float*)d_in[14];
    float* out = (float*)d_out;

    float *x1, *y;
    cudaGetSymbolAddress((void**)&x1, g_x1);
    cudaGetSymbolAddress((void**)&y,  g_y);

    __half *wqkv_hi, *wqkv_lo, *wa1_hi, *wa1_lo, *wa2_hi, *wa2_lo,
           *wf1_hi, *wf1_lo, *wf2_hi, *wf2_lo, *ahi, *alo, *hhi, *qkvh, *qkvl;
    cudaGetSymbolAddress((void**)&wqkv_hi, g_wqkv_hi);
    cudaGetSymbolAddress((void**)&wqkv_lo, g_wqkv_lo);
    cudaGetSymbolAddress((void**)&wa1_hi,  g_wa1_hi);
    cudaGetSymbolAddress((void**)&wa1_lo,  g_wa1_lo);
    cudaGetSymbolAddress((void**)&wa2_hi,  g_wa2_hi);
    cudaGetSymbolAddress((void**)&wa2_lo,  g_wa2_lo);
    cudaGetSymbolAddress((void**)&wf1_hi,  g_wf1_hi);
    cudaGetSymbolAddress((void**)&wf1_lo,  g_wf1_lo);
    cudaGetSymbolAddress((void**)&wf2_hi,  g_wf2_hi);
    cudaGetSymbolAddress((void**)&wf2_lo,  g_wf2_lo);
    cudaGetSymbolAddress((void**)&ahi,     g_ahi);
    cudaGetSymbolAddress((void**)&alo,     g_alo);
    cudaGetSymbolAddress((void**)&hhi,     g_hhi);
    cudaGetSymbolAddress((void**)&qkvh,    g_qkvh);
    cudaGetSymbolAddress((void**)&qkvl,    g_qkvl);

    const int GS3 = 3 * 32768;   // 3-pass stage triple
    const int GS2 = 3 * 24576;   // 2-pass stage triple
    cudaFuncSetAttribute(attn_mma_kernel, cudaFuncAttributeMaxDynamicSharedMemorySize, ASMEM);
    cudaFuncSetAttribute((gemm_mma_kernel<2, 3>), cudaFuncAttributeMaxDynamicSharedMemorySize, GS3);
    cudaFuncSetAttribute((gemm_mma_kernel<1, 2>), cudaFuncAttributeMaxDynamicSharedMemorySize, GS2);
    cudaFuncSetAttribute((gemm_mma_kernel<0, 2>), cudaFuncAttributeMaxDynamicSharedMemorySize, GS2);

    // weight transpose + fp16 split
    cvt_wt_kernel<<<dim3(C3 / 32, CC / 32), 256>>>(w_attn, wqkv_hi, wqkv_lo, CC, C3);
    cvt_wt_kernel<<<dim3(C4 / 32, CC / 32), 256>>>(wa1, wa1_hi, wa1_lo, CC, C4);
    cvt_wt_kernel<<<dim3(CC / 32, C4 / 32), 256>>>(wa2, wa2_hi, wa2_lo, C4, CC);
    cvt_wt_kernel<<<dim3(C4 / 32, CC / 32), 256>>>(wf1, wf1_hi, wf1_lo, CC, C4);
    cvt_wt_kernel<<<dim3(CC / 32, C4 / 32), 256>>>(wf2, wf2_hi, wf2_lo, C4, CC);

    // 1) qkv = x @ w_attn + b_attn  (3-pass, hi+lo out for attention)
    cvt_act_kernel<<<(MTOK * CC) / 1024, 256>>>(x, ahi, alo, MTOK * CC);
    gemm_mma_kernel<2, 3><<<dim3(C3 / 128, MTOK / 128), 256, GS3>>>(
        ahi, alo, wqkv_hi, wqkv_lo, b_attn, nullptr, qkvh, qkvl, C3, CC);
    // 2) attention (fp16 3-pass) -> hi-only att
    attn_mma_kernel<<<dim3(TT / 64, NHH, BB), 128, ASMEM>>>(qkvh, qkvl, ahi);
    // 3) h = gelu(att @ wa1 + ba1)  (2-pass)
    gemm_mma_kernel<1, 2><<<dim3(C4 / 128, MTOK / 128), 256, GS2>>>(
        ahi, nullptr, wa1_hi, wa1_lo, ba1, nullptr, hhi, nullptr, C4, CC);
    // 4) y = h @ wa2 + ba2  (2-pass)
    gemm_mma_kernel<0, 2><<<dim3(CC / 128, MTOK / 128), 256, GS2>>>(
        hhi, nullptr, wa2_hi, wa2_lo, ba2, y, nullptr, nullptr, CC, C4);
    // 5) x1 = x + ln(y); emit fp16 x1 hi
    ln_res_kernel<true><<<MTOK, 256>>>(x, y, g1, be1, x1, ahi);
    // 6) h = gelu(x1 @ wf1 + bf1)  (2-pass)
    gemm_mma_kernel<1, 2><<<dim3(C4 / 128, MTOK / 128), 256, GS2>>>(
        ahi, nullptr, wf1_hi, wf1_lo, bf1, nullptr, hhi, nullptr, C4, CC);
    // 7) y = h @ wf2 + bf2  (2-pass)
    gemm_mma_kernel<0, 2><<<dim3(CC / 128, MTOK / 128), 256, GS2>>>(
        hhi, nullptr, wf2_hi, wf2_lo, bf2, y, nullptr, nullptr, CC, C4);
    // 8) out = x1 + ln(y)
    ln_res_kernel<false><<<MTOK, 256>>>(x1, y, g2, be2, out, nullptr);
}

// round 8
// speedup vs baseline: 1.5230x; 1.0959x over previous
#include <cuda_runtime.h>
#include <cuda_fp16.h>
#include <math.h>
#include <stdint.h>

// Problem dims (fixed)
#define BB 2
#define TT 2048
#define CC 1024
#define NHH 16
#define HDD 64
#define MTOK 4096          // B*T
#define C3 3072
#define C4 4096

// ---------------- scratch (no allocation allowed) ----------------
__device__ float g_x1 [(size_t)MTOK * CC];
__device__ float g_y  [(size_t)MTOK * CC];

// fp16 split weights, transposed to [N][K]
__device__ __half g_wqkv_hi[(size_t)C3 * CC], g_wqkv_lo[(size_t)C3 * CC];
__device__ __half g_wa1_hi [(size_t)C4 * CC], g_wa1_lo [(size_t)C4 * CC];
__device__ __half g_wa2_hi [(size_t)CC * C4], g_wa2_lo [(size_t)CC * C4];
__device__ __half g_wf1_hi [(size_t)C4 * CC], g_wf1_lo [(size_t)C4 * CC];
__device__ __half g_wf2_hi [(size_t)CC * C4], g_wf2_lo [(size_t)CC * C4];
// fp16 activations
__device__ __half g_ahi [(size_t)MTOK * CC];
__device__ __half g_hhi [(size_t)MTOK * C4];
__device__ __half g_qkvh[(size_t)MTOK * C3], g_qkvl[(size_t)MTOK * C3];

__device__ __forceinline__ float gelu_f(float v) {
    return 0.5f * v * (1.0f + erff(v * 0.7071067811865475f));
}

// ======================= PTX helpers =======================
__device__ __forceinline__ uint32_t smem_u32(const void* p) {
    uint32_t a;
    asm("{ .reg .u64 t; cvta.to.shared.u64 t, %1; cvt.u32.u64 %0, t; }" : "=r"(a) : "l"(p));
    return a;
}
__device__ __forceinline__ void ldsm4(uint32_t* r, uint32_t addr) {
    asm volatile("ldmatrix.sync.aligned.m8n8.x4.shared.b16 {%0,%1,%2,%3}, [%4];"
                 : "=r"(r[0]), "=r"(r[1]), "=r"(r[2]), "=r"(r[3]) : "r"(addr));
}
__device__ __forceinline__ void ldsm4t(uint32_t* r, uint32_t addr) {
    asm volatile("ldmatrix.sync.aligned.m8n8.x4.trans.shared.b16 {%0,%1,%2,%3}, [%4];"
                 : "=r"(r[0]), "=r"(r[1]), "=r"(r[2]), "=r"(r[3]) : "r"(addr));
}
__device__ __forceinline__ void mma_f16(float* d, const uint32_t* a, const uint32_t* b) {
    asm volatile(
        "mma.sync.aligned.m16n8k16.row.col.f32.f16.f16.f32 "
        "{%0,%1,%2,%3}, {%4,%5,%6,%7}, {%8,%9}, {%0,%1,%2,%3};"
        : "+f"(d[0]), "+f"(d[1]), "+f"(d[2]), "+f"(d[3])
        : "r"(a[0]), "r"(a[1]), "r"(a[2]), "r"(a[3]), "r"(b[0]), "r"(b[1]));
}
__device__ __forceinline__ void cp16(uint32_t dst, const void* src) {
    unsigned long long g = __cvta_generic_to_global(src);
    asm volatile("cp.async.ca.shared.global [%0], [%1], 16;" :: "r"(dst), "l"(g) : "memory");
}
__device__ __forceinline__ void cp_commit() {
    asm volatile("cp.async.commit_group;" ::: "memory");
}
template<int N>
__device__ __forceinline__ void cp_wait() {
    asm volatile("cp.async.wait_group %0;" :: "n"(N) : "memory");
}
__device__ __forceinline__ void split2(float a, float b, uint32_t& hi, uint32_t& lo) {
    __half ha = __float2half_rn(a), hb = __float2half_rn(b);
    __half2 H = __halves2half2(ha, hb);
    __half2 L = __halves2half2(__float2half_rn(a - __half2float(ha)),
                               __float2half_rn(b - __half2float(hb)));
    hi = *(uint32_t*)&H;
    lo = *(uint32_t*)&L;
}
__device__ __forceinline__ uint32_t pack2h(float a, float b) {
    __half2 H = __halves2half2(__float2half_rn(a), __float2half_rn(b));
    return *(uint32_t*)&H;
}

// ======================= conversion kernels =======================
__global__ void __launch_bounds__(256)
cvt_act_kernel(const float* __restrict__ in, __half* __restrict__ hi, int n)
{
    int i = (blockIdx.x * 256 + threadIdx.x) * 4;
    if (i >= n) return;
    float4 v = *(const float4*)(in + i);
    *(uint32_t*)(hi + i)     = pack2h(v.x, v.y);
    *(uint32_t*)(hi + i + 2) = pack2h(v.z, v.w);
}

// all five weights, transposed+split, in ONE launch (19456 blocks)
__global__ void __launch_bounds__(256)
cvt_wt_all_kernel(const float* __restrict__ W0, __half* __restrict__ h0, __half* __restrict__ l0,
                  const float* __restrict__ W1, __half* __restrict__ h1, __half* __restrict__ l1,
                  const float* __restrict__ W2, __half* __restrict__ h2, __half* __restrict__ l2,
                  const float* __restrict__ W3, __half* __restrict__ h3, __half* __restrict__ l3,
                  const float* __restrict__ W4, __half* __restrict__ h4, __half* __restrict__ l4)
{
    __shared__ float tile[32][33];
    const int bid = blockIdx.x;
    const float* W; __half* hi; __half* lo; int K, N, local;
    if      (bid < 3072)  { W = W0; hi = h0; lo = l0; K = CC; N = C3; local = bid; }
    else if (bid < 7168)  { W = W1; hi = h1; lo = l1; K = CC; N = C4; local = bid - 3072; }
    else if (bid < 11264) { W = W2; hi = h2; lo = l2; K = C4; N = CC; local = bid - 7168; }
    else if (bid < 15360) { W = W3; hi = h3; lo = l3; K = CC; N = C4; local = bid - 11264; }
    else                  { W = W4; hi = h4; lo = l4; K = C4; N = CC; local = bid - 15360; }
    const int nb = N >> 5;
    const int n0 = (local % nb) * 32, k0 = (local / nb) * 32;
    const int tx = threadIdx.x & 31, ty = threadIdx.x >> 5;
#pragma unroll
    for (int r = 0; r < 4; ++r)
        tile[ty + r * 8][tx] = W[(size_t)(k0 + ty + r * 8) * N + n0 + tx];
    __syncthreads();
#pragma unroll
    for (int r = 0; r < 4; ++r) {
        int n = n0 + ty + r * 8;
        float v = tile[tx][ty + r * 8];
        __half h = __float2half_rn(v);
        hi[(size_t)n * K + k0 + tx] = h;
        lo[(size_t)n * K + k0 + tx] = __float2half_rn(v - __half2float(h));
    }
}

// shared swizzle for 64B-row operand tiles
__device__ __forceinline__ uint32_t sw_off(int row, int kq) {
    return (uint32_t)(row * 64 + (((kq) ^ ((row >> 1) & 3)) << 4));
}

// ======================= HMMA split-fp16 GEMM, CTA 128x128 =======================
// 8 warps (2x4), warp tile 64x32, 3-stage cp.async, 2 CTAs/SM.
// 2-pass: D = Ah*Bh + Ah*Bl.
// MODE 0: fp32 out.  MODE 1: exact-GELU, fp16 hi out.  MODE 2: fp16 hi+lo out.
#define GS2 (3 * 24576)
template<int MODE>
__global__ void __launch_bounds__(256, 2)
gemm_mma_kernel(const __half* __restrict__ Ahi,
                const __half* __restrict__ Bhi, const __half* __restrict__ Blo,
                const float* __restrict__ bias, float* __restrict__ Cf,
                __half* __restrict__ Chi, __half* __restrict__ Clo,
                int N, int K)
{
    constexpr uint32_t STAGE   = 24576u;
    constexpr uint32_t BHI_OFF = 8192u;
    constexpr uint32_t BLO_OFF = 16384u;

    extern __shared__ char smem[];
    const uint32_t sb = smem_u32(smem);

    const int t = threadIdx.x;
    const int wid = t >> 5, lane = t & 31;
    const int bm = blockIdx.y * 128;
    const int bn = blockIdx.x * 128;
    const int wm = wid >> 2, wn = wid & 3;

    float acc[4][4][4];
#pragma unroll
    for (int i = 0; i < 4; ++i)
#pragma unroll
        for (int j = 0; j < 4; ++j)
#pragma unroll
            for (int k = 0; k < 4; ++k) acc[i][j][k] = 0.0f;

    const int nc = K >> 5;

    const int g  = lane >> 3, lr = lane & 7;
    const int a_rit = lr + (g & 1) * 8, a_kqo = g >> 1;
    const int b_rit = lr + (g >> 1) * 8, b_kqo = g & 1;

    uint32_t aAhi[4], aBhi[2], aBlo[2];
    int aRsw[4], bRsw[2];
#pragma unroll
    for (int mt = 0; mt < 4; ++mt) {
        int row = wm * 64 + mt * 16 + a_rit;
        aAhi[mt] = sb + row * 64;
        aRsw[mt] = (row >> 1) & 3;
    }
#pragma unroll
    for (int p = 0; p < 2; ++p) {
        int row = wn * 32 + p * 16 + b_rit;
        aBhi[p] = sb + BHI_OFF + row * 64;
        aBlo[p] = sb + BLO_OFF + row * 64;
        bRsw[p] = (row >> 1) & 3;
    }

    auto issue = [&](int c, int s) {
        const uint32_t st = sb + s * STAGE;
        const int kb = c * 32;
#pragma unroll
        for (int i = 0; i < 6; ++i) {
            int u = t + i * 256;
            const __half* src;
            uint32_t off;
            if (u < 512) {
                int row = u >> 2, kq = u & 3;
                src = Ahi + (size_t)(bm + row) * K + kb + kq * 8;
                off = sw_off(row, kq);
            } else {
                int w = u - 512;
                int arr = w >> 9, v = w & 511, row = v >> 2, kq = v & 3;
                src = (arr ? Blo : Bhi) + (size_t)(bn + row) * K + kb + kq * 8;
                off = BHI_OFF + arr * 8192u + sw_off(row, kq);
            }
            cp16(st + off, src);
        }
        cp_commit();
    };

    issue(0, 0);
    issue(1, 1);
    int s = 0;
    for (int c = 0; c < nc; ++c) {
        if (c + 2 < nc) { issue(c + 2, (c + 2) % 3); cp_wait<2>(); }
        else if (c + 1 < nc) cp_wait<1>();
        else cp_wait<0>();
        __syncthreads();

        const uint32_t stoff = (uint32_t)(s * STAGE);
#pragma unroll
        for (int ks = 0; ks < 2; ++ks) {
            uint32_t ah[4][4], bh[4][2], bl[4][2];
#pragma unroll
            for (int mt = 0; mt < 4; ++mt) {
                uint32_t o = (uint32_t)((((2 * ks + a_kqo) ^ aRsw[mt]) << 4));
                ldsm4(ah[mt], aAhi[mt] + stoff + o);
            }
#pragma unroll
            for (int p = 0; p < 2; ++p) {
                uint32_t r[4];
                uint32_t o = (uint32_t)((((2 * ks + b_kqo) ^ bRsw[p]) << 4));
                ldsm4(r, aBhi[p] + stoff + o);
                bh[2 * p][0] = r[0]; bh[2 * p][1] = r[1];
                bh[2 * p + 1][0] = r[2]; bh[2 * p + 1][1] = r[3];
                ldsm4(r, aBlo[p] + stoff + o);
                bl[2 * p][0] = r[0]; bl[2 * p][1] = r[1];
                bl[2 * p + 1][0] = r[2]; bl[2 * p + 1][1] = r[3];
            }
#pragma unroll
            for (int mt = 0; mt < 4; ++mt)
#pragma unroll
                for (int nt = 0; nt < 4; ++nt) {
                    mma_f16(acc[mt][nt], ah[mt], bh[nt]);
                    mma_f16(acc[mt][nt], ah[mt], bl[nt]);
                }
        }
        __syncthreads();
        s = (s + 1) % 3;
    }

    const int mrow = bm + wm * 64;
    const int ncol = bn + wn * 32;
#pragma unroll
    for (int mt = 0; mt < 4; ++mt) {
#pragma unroll
        for (int nt = 0; nt < 4; ++nt) {
            float* d = acc[mt][nt];
            int r0 = mrow + mt * 16 + (lane >> 2);
            int cix = ncol + nt * 8 + (lane & 3) * 2;
            float b0 = bias[cix], b1 = bias[cix + 1];
            float v00 = d[0] + b0, v01 = d[1] + b1;
            float v10 = d[2] + b0, v11 = d[3] + b1;
            if (MODE == 0) {
                float2 p0{v00, v01}, p1{v10, v11};
                *(float2*)&Cf[(size_t)r0 * N + cix]       = p0;
                *(float2*)&Cf[(size_t)(r0 + 8) * N + cix] = p1;
            } else if (MODE == 1) {
                v00 = gelu_f(v00); v01 = gelu_f(v01);
                v10 = gelu_f(v10); v11 = gelu_f(v11);
                *(uint32_t*)&Chi[(size_t)r0 * N + cix]       = pack2h(v00, v01);
                *(uint32_t*)&Chi[(size_t)(r0 + 8) * N + cix] = pack2h(v10, v11);
            } else {
                uint32_t h0, l0, h1, l1;
                split2(v00, v01, h0, l0);
                split2(v10, v11, h1, l1);
                *(uint32_t*)&Chi[(size_t)r0 * N + cix]       = h0;
                *(uint32_t*)&Clo[(size_t)r0 * N + cix]       = l0;
                *(uint32_t*)&Chi[(size_t)(r0 + 8) * N + cix] = h1;
                *(uint32_t*)&Clo[(size_t)(r0 + 8) * N + cix] = l1;
            }
        }
    }
}

// ======================= HMMA causal attention (FA2-style) =======================
// QK: 3-pass split fp16.  PV: 2-pass (P hi-only x (Vh + Vl)).
// Heavy query tiles scheduled first (reverse blockIdx.x mapping).
#define ASMEM 49152
__device__ __forceinline__ uint32_t asw(int row, int u) {
    return (uint32_t)(row * 128 + ((u ^ (row & 7)) << 4));
}

__global__ void __launch_bounds__(128, 3)
attn_mma_kernel(const __half* __restrict__ qkvh, const __half* __restrict__ qkvl,
                __half* __restrict__ ohi)
{
    extern __shared__ char asmem[];
    const uint32_t sb = smem_u32(asmem);

    const int t = threadIdx.x, wid = t >> 5, lane = t & 31;
    const int qi = gridDim.x - 1 - blockIdx.x;   // heavy tiles first
    const int qb = qi * 64;
    const int h  = blockIdx.y, b = blockIdx.z;

    const __half* Kh_g = qkvh + (size_t)b * TT * C3 + h * HDD;
    const __half* Kl_g = qkvl + (size_t)b * TT * C3 + h * HDD;
    const __half* Qh_g = Kh_g + CC;
    const __half* Ql_g = Kl_g + CC;
    const __half* Vh_g = Kh_g + 2 * CC;
    const __half* Vl_g = Kl_g + 2 * CC;

#pragma unroll
    for (int i = 0; i < 8; ++i) {
        int uu = t + i * 128;
        int arr = uu >> 9, v = uu & 511, row = v >> 3, u = v & 7;
        const __half* src = (arr ? Ql_g : Qh_g) + (size_t)(qb + row) * C3 + u * 8;
        cp16(sb + arr * 8192 + asw(row, u), src);
    }
    cp_commit();

    const int g = lane >> 3, lr = lane & 7;
    const int r = lane >> 2, c = lane & 3;
    const int qrow = wid * 16 + lr + ((g & 1) << 3);
    const int a_u  = g >> 1;
    const int krit = lr + ((g >> 1) << 3);
    const int b_u  = g & 1;
    const int vrit = lr + ((g & 1) << 3);
    const int v_u  = g >> 1;

    float O[8][4];
#pragma unroll
    for (int i = 0; i < 8; ++i)
#pragma unroll
        for (int j = 0; j < 4; ++j) O[i][j] = 0.0f;
    float m0 = -1e30f, m1 = -1e30f, l0 = 0.0f, l1 = 0.0f;

    const int ntiles = qi + 1;
    for (int kt = 0; kt < ntiles; ++kt) {
        const int kb = kt * 64;
        __syncthreads();
#pragma unroll
        for (int i = 0; i < 16; ++i) {
            int uu = t + i * 128;
            int arr = uu >> 9, v = uu & 511, row = v >> 3, u = v & 7;
            const __half* src;
            if      (arr == 0) src = Kh_g + (size_t)(kb + row) * C3 + u * 8;
            else if (arr == 1) src = Kl_g + (size_t)(kb + row) * C3 + u * 8;
            else if (arr == 2) src = Vh_g + (size_t)(kb + row) * C3 + u * 8;
            else               src = Vl_g + (size_t)(kb + row) * C3 + u * 8;
            cp16(sb + 16384 + arr * 8192 + asw(row, u), src);
        }
        cp_commit();
        cp_wait<0>();
        __syncthreads();

        float S[8][4];
#pragma unroll
        for (int i = 0; i < 8; ++i)
#pragma unroll
            for (int j = 0; j < 4; ++j) S[i][j] = 0.0f;

#pragma unroll
        for (int kk = 0; kk < 4; ++kk) {
            uint32_t ah[4], al[4];
            uint32_t aoq = (uint32_t)(qrow * 128 + ((((kk << 1) | a_u) ^ (qrow & 7)) << 4));
            ldsm4(ah, sb + aoq);
            ldsm4(al, sb + 8192 + aoq);
#pragma unroll
            for (int p = 0; p < 4; ++p) {
                int krow = (p << 4) + krit;
                uint32_t ko = (uint32_t)(krow * 128 + ((((kk << 1) | b_u) ^ (krow & 7)) << 4));
                uint32_t bh[4], bl[4];
                ldsm4(bh, sb + 16384 + ko);
                ldsm4(bl, sb + 24576 + ko);
                mma_f16(S[2 * p],     ah, bh);
                mma_f16(S[2 * p],     ah, bl);
                mma_f16(S[2 * p],     al, bh);
                mma_f16(S[2 * p + 1], ah, bh + 2);
                mma_f16(S[2 * p + 1], ah, bl + 2);
                mma_f16(S[2 * p + 1], al, bh + 2);
            }
        }

#pragma unroll
        for (int nt = 0; nt < 8; ++nt)
#pragma unroll
            for (int e = 0; e < 4; ++e) S[nt][e] *= 0.125f;
        if (kt == qi) {
            const int q0 = qb + wid * 16 + r, q1 = q0 + 8;
#pragma unroll
            for (int nt = 0; nt < 8; ++nt) {
                int k0 = kb + 8 * nt + 2 * c;
                if (k0     > q0) S[nt][0] = -1e30f;
                if (k0 + 1 > q0) S[nt][1] = -1e30f;
                if (k0     > q1) S[nt][2] = -1e30f;
                if (k0 + 1 > q1) S[nt][3] = -1e30f;
            }
        }

        float mx0 = -1e30f, mx1 = -1e30f;
#pragma unroll
        for (int nt = 0; nt < 8; ++nt) {
            mx0 = fmaxf(mx0, fmaxf(S[nt][0], S[nt][1]));
            mx1 = fmaxf(mx1, fmaxf(S[nt][2], S[nt][3]));
        }
        mx0 = fmaxf(mx0, __shfl_xor_sync(0xffffffffu, mx0, 1));
        mx0 = fmaxf(mx0, __shfl_xor_sync(0xffffffffu, mx0, 2));
        mx1 = fmaxf(mx1, __shfl_xor_sync(0xffffffffu, mx1, 1));
        mx1 = fmaxf(mx1, __shfl_xor_sync(0xffffffffu, mx1, 2));
        float mn0 = fmaxf(m0, mx0), mn1 = fmaxf(m1, mx1);
        float al0 = __expf(m0 - mn0), al1 = __expf(m1 - mn1);
        m0 = mn0; m1 = mn1;

        float s0 = 0.0f, s1 = 0.0f;
#pragma unroll
        for (int nt = 0; nt < 8; ++nt) {
            S[nt][0] = __expf(S[nt][0] - mn0);
            S[nt][1] = __expf(S[nt][1] - mn0);
            S[nt][2] = __expf(S[nt][2] - mn1);
            S[nt][3] = __expf(S[nt][3] - mn1);
            s0 += S[nt][0] + S[nt][1];
            s1 += S[nt][2] + S[nt][3];
        }
        l0 = l0 * al0 + s0;
        l1 = l1 * al1 + s1;
#pragma unroll
        for (int nt = 0; nt < 8; ++nt) {
            O[nt][0] *= al0; O[nt][1] *= al0;
            O[nt][2] *= al1; O[nt][3] *= al1;
        }

        // O += P * (Vh + Vl), P in fp16 hi only
#pragma unroll
        for (int kk = 0; kk < 4; ++kk) {
            uint32_t ph[4];
            ph[0] = pack2h(S[2 * kk][0],     S[2 * kk][1]);
            ph[1] = pack2h(S[2 * kk][2],     S[2 * kk][3]);
            ph[2] = pack2h(S[2 * kk + 1][0], S[2 * kk + 1][1]);
            ph[3] = pack2h(S[2 * kk + 1][2], S[2 * kk + 1][3]);
            int vrow = (kk << 4) + vrit;
#pragma unroll
            for (int p = 0; p < 4; ++p) {
                uint32_t vo = (uint32_t)(vrow * 128 + ((((p << 1) | v_u) ^ (vrow & 7)) << 4));
                uint32_t vh[4], vl[4];
                ldsm4t(vh, sb + 32768 + vo);
                ldsm4t(vl, sb + 40960 + vo);
                mma_f16(O[2 * p],     ph, vh);
                mma_f16(O[2 * p],     ph, vl);
                mma_f16(O[2 * p + 1], ph, vh + 2);
                mma_f16(O[2 * p + 1], ph, vl + 2);
            }
        }
    }

    l0 += __shfl_xor_sync(0xffffffffu, l0, 1);
    l0 += __shfl_xor_sync(0xffffffffu, l0, 2);
    l1 += __shfl_xor_sync(0xffffffffu, l1, 1);
    l1 += __shfl_xor_sync(0xffffffffu, l1, 2);
    const float i0 = 1.0f / l0, i1 = 1.0f / l1;
    const int row0 = qb + wid * 16 + r, row1 = row0 + 8;
#pragma unroll
    for (int nt = 0; nt < 8; ++nt) {
        int col = h * HDD + 8 * nt + 2 * c;
        size_t idx0 = ((size_t)b * TT + row0) * CC + col;
        size_t idx1 = ((size_t)b * TT + row1) * CC + col;
        *(uint32_t*)&ohi[idx0] = pack2h(O[nt][0] * i0, O[nt][1] * i0);
        *(uint32_t*)&ohi[idx1] = pack2h(O[nt][2] * i1, O[nt][3] * i1);
    }
}

// ---------------- LayerNorm + residual ----------------
__device__ __forceinline__ float block_sum(float v, float* red) {
    const int lane = threadIdx.x & 31, w = threadIdx.x >> 5;
#pragma unroll
    for (int o = 16; o; o >>= 1) v += __shfl_xor_sync(0xffffffffu, v, o);
    if (lane == 0) red[w] = v;
    __syncthreads();
    if (w == 0) {
        float s = (lane < 8) ? red[lane] : 0.0f;
#pragma unroll
        for (int o = 4; o; o >>= 1) s += __shfl_xor_sync(0xffffffffu, s, o);
        if (lane == 0) red[0] = s;
    }
    __syncthreads();
    float rr = red[0];
    __syncthreads();
    return rr;
}

template<bool SPLIT>
__global__ void __launch_bounds__(256)
ln_res_kernel(const float* __restrict__ res, const float* __restrict__ y,
              const float* __restrict__ g, const float* __restrict__ be,
              float* __restrict__ out, __half* __restrict__ ohi)
{
    __shared__ float red[8];
    const int row = blockIdx.x;
    const int t = threadIdx.x;
    const float* yr = y + (size_t)row * CC;

    float v[4];
    float s = 0.0f;
#pragma unroll
    for (int i = 0; i < 4; ++i) { v[i] = yr[t + i * 256]; s += v[i]; }
    const float mean = block_sum(s, red) * (1.0f / CC);

    float sq = 0.0f;
#pragma unroll
    for (int i = 0; i < 4; ++i) { float d = v[i] - mean; sq += d * d; }
    const float var = block_sum(sq, red) * (1.0f / CC);
    const float rstd = rsqrtf(var + 1e-5f);

    const float* rr = res + (size_t)row * CC;
    float* orow = out + (size_t)row * CC;
#pragma unroll
    for (int i = 0; i < 4; ++i) {
        int cix = t + i * 256;
        float o = rr[cix] + (v[i] - mean) * rstd * g[cix] + be[cix];
        orow[cix] = o;
        if (SPLIT) ohi[(size_t)row * CC + cix] = __float2half_rn(o);
    }
}

// ---------------- launch ----------------
extern "C" void kernel_launch(void* const* d_in, const int* in_sizes, int n_in,
                              void* d_out, int out_size)
{
    const float* x      = (const float*)d_in[0];
    const float* w_attn = (const float*)d_in[1];
    const float* b_attn = (const float*)d_in[2];
    const float* wa1    = (const float*)d_in[3];
    const float* ba1    = (const float*)d_in[4];
    const float* wa2    = (const float*)d_in[5];
    const float* ba2    = (const float*)d_in[6];
    const float* g1     = (const float*)d_in[7];
    const float* be1    = (const float*)d_in[8];
    const float* wf1    = (const float*)d_in[9];
    const float* bf1    = (const float*)d_in[10];
    const float* wf2    = (const float*)d_in[11];
    const float* bf2    = (const float*)d_in[12];
    const float* g2     = (const float*)d_in[13];
    const float* be2    = (const float*)d_in[14];
    float* out = (float*)d_out;

    float *x1, *y;
    cudaGetSymbolAddress((void**)&x1, g_x1);
    cudaGetSymbolAddress((void**)&y,  g_y);

    __half *wqkv_hi, *wqkv_lo, *wa1_hi, *wa1_lo, *wa2_hi, *wa2_lo,
           *wf1_hi, *wf1_lo, *wf2_hi, *wf2_lo, *ahi, *hhi, *qkvh, *qkvl;
    cudaGetSymbolAddress((void**)&wqkv_hi, g_wqkv_hi);
    cudaGetSymbolAddress((void**)&wqkv_lo, g_wqkv_lo);
    cudaGetSymbolAddress((void**)&wa1_hi,  g_wa1_hi);
    cudaGetSymbolAddress((void**)&wa1_lo,  g_wa1_lo);
    cudaGetSymbolAddress((void**)&wa2_hi,  g_wa2_hi);
    cudaGetSymbolAddress((void**)&wa2_lo,  g_wa2_lo);
    cudaGetSymbolAddress((void**)&wf1_hi,  g_wf1_hi);
    cudaGetSymbolAddress((void**)&wf1_lo,  g_wf1_lo);
    cudaGetSymbolAddress((void**)&wf2_hi,  g_wf2_hi);
    cudaGetSymbolAddress((void**)&wf2_lo,  g_wf2_lo);
    cudaGetSymbolAddress((void**)&ahi,     g_ahi);
    cudaGetSymbolAddress((void**)&hhi,     g_hhi);
    cudaGetSymbolAddress((void**)&qkvh,    g_qkvh);
    cudaGetSymbolAddress((void**)&qkvl,    g_qkvl);

    cudaFuncSetAttribute(attn_mma_kernel, cudaFuncAttributeMaxDynamicSharedMemorySize, ASMEM);
    cudaFuncSetAttribute(gemm_mma_kernel<0>, cudaFuncAttributeMaxDynamicSharedMemorySize, GS2);
    cudaFuncSetAttribute(gemm_mma_kernel<1>, cudaFuncAttributeMaxDynamicSharedMemorySize, GS2);
    cudaFuncSetAttribute(gemm_mma_kernel<2>, cudaFuncAttributeMaxDynamicSharedMemorySize, GS2);

    // all weight transposes + fp16 splits in one launch
    cvt_wt_all_kernel<<<19456, 256>>>(
        w_attn, wqkv_hi, wqkv_lo,
        wa1, wa1_hi, wa1_lo,
        wa2, wa2_hi, wa2_lo,
        wf1, wf1_hi, wf1_lo,
        wf2, wf2_hi, wf2_lo);

    // 1) qkv = x @ w_attn + b_attn  (2-pass, hi+lo out for attention)
    cvt_act_kernel<<<(MTOK * CC) / 1024, 256>>>(x, ahi, MTOK * CC);
    gemm_mma_kernel<2><<<dim3(C3 / 128, MTOK / 128), 256, GS2>>>(
        ahi, wqkv_hi, wqkv_lo, b_attn, nullptr, qkvh, qkvl, C3, CC);
    // 2) attention -> hi-only att
    attn_mma_kernel<<<dim3(TT / 64, NHH, BB), 128, ASMEM>>>(qkvh, qkvl, ahi);
    // 3) h = gelu(att @ wa1 + ba1)
    gemm_mma_kernel<1><<<dim3(C4 / 128, MTOK / 128), 256, GS2>>>(
        ahi, wa1_hi, wa1_lo, ba1, nullptr, hhi, nullptr, C4, CC);
    // 4) y = h @ wa2 + ba2
    gemm_mma_kernel<0><<<dim3(CC / 128, MTOK / 128), 256, GS2>>>(
        hhi, wa2_hi, wa2_lo, ba2, y, nullptr, nullptr, CC, C4);
    // 5) x1 = x + ln(y); emit fp16 x1 hi
    ln_res_kernel<true><<<MTOK, 256>>>(x, y, g1, be1, x1, ahi);
    // 6) h = gelu(x1 @ wf1 + bf1)
    gemm_mma_kernel<1><<<dim3(C4 / 128, MTOK / 128), 256, GS2>>>(
        ahi, wf1_hi, wf1_lo, bf1, nullptr, hhi, nullptr, C4, CC);
    // 7) y = h @ wf2 + bf2
    gemm_mma_kernel<0><<<dim3(CC / 128, MTOK / 128), 256, GS2>>>(
        hhi, wf2_hi, wf2_lo, bf2, y, nullptr, nullptr, CC, C4);
    // 8) out = x1 + ln(y)
    ln_res_kernel<false><<<MTOK, 256>>>(x1, y, g2, be2, out, nullptr);
}

// round 9
// speedup vs baseline: 1.7387x; 1.1416x over previous
#include <cuda_runtime.h>
#include <cuda_fp16.h>
#include <math.h>
#include <stdint.h>

// Problem dims (fixed)
#define BB 2
#define TT 2048
#define CC 1024
#define NHH 16
#define HDD 64
#define MTOK 4096          // B*T
#define C3 3072
#define C4 4096

// ---------------- scratch (no allocation allowed) ----------------
__device__ float g_x1 [(size_t)MTOK * CC];
__device__ float g_y  [(size_t)MTOK * CC];

// fp16 split weights, transposed to [N][K] (lo unused for wa2/wf2)
__device__ __half g_wqkv_hi[(size_t)C3 * CC], g_wqkv_lo[(size_t)C3 * CC];
__device__ __half g_wa1_hi [(size_t)C4 * CC], g_wa1_lo [(size_t)C4 * CC];
__device__ __half g_wa2_hi [(size_t)CC * C4];
__device__ __half g_wf1_hi [(size_t)C4 * CC], g_wf1_lo [(size_t)C4 * CC];
__device__ __half g_wf2_hi [(size_t)CC * C4];
// fp16 activations
__device__ __half g_ahi [(size_t)MTOK * CC];
__device__ __half g_hhi [(size_t)MTOK * C4];
__device__ __half g_qkvh[(size_t)MTOK * C3], g_qkvl[(size_t)MTOK * C3];

__device__ __forceinline__ float gelu_f(float v) {
    return 0.5f * v * (1.0f + erff(v * 0.7071067811865475f));
}

// ======================= PTX helpers =======================
__device__ __forceinline__ uint32_t smem_u32(const void* p) {
    uint32_t a;
    asm("{ .reg .u64 t; cvta.to.shared.u64 t, %1; cvt.u32.u64 %0, t; }" : "=r"(a) : "l"(p));
    return a;
}
__device__ __forceinline__ void ldsm4(uint32_t* r, uint32_t addr) {
    asm volatile("ldmatrix.sync.aligned.m8n8.x4.shared.b16 {%0,%1,%2,%3}, [%4];"
                 : "=r"(r[0]), "=r"(r[1]), "=r"(r[2]), "=r"(r[3]) : "r"(addr));
}
__device__ __forceinline__ void ldsm4t(uint32_t* r, uint32_t addr) {
    asm volatile("ldmatrix.sync.aligned.m8n8.x4.trans.shared.b16 {%0,%1,%2,%3}, [%4];"
                 : "=r"(r[0]), "=r"(r[1]), "=r"(r[2]), "=r"(r[3]) : "r"(addr));
}
__device__ __forceinline__ void mma_f16(float* d, const uint32_t* a, const uint32_t* b) {
    asm volatile(
        "mma.sync.aligned.m16n8k16.row.col.f32.f16.f16.f32 "
        "{%0,%1,%2,%3}, {%4,%5,%6,%7}, {%8,%9}, {%0,%1,%2,%3};"
        : "+f"(d[0]), "+f"(d[1]), "+f"(d[2]), "+f"(d[3])
        : "r"(a[0]), "r"(a[1]), "r"(a[2]), "r"(a[3]), "r"(b[0]), "r"(b[1]));
}
__device__ __forceinline__ void cp16(uint32_t dst, const void* src) {
    unsigned long long g = __cvta_generic_to_global(src);
    asm volatile("cp.async.ca.shared.global [%0], [%1], 16;" :: "r"(dst), "l"(g) : "memory");
}
__device__ __forceinline__ void cp_commit() {
    asm volatile("cp.async.commit_group;" ::: "memory");
}
template<int N>
__device__ __forceinline__ void cp_wait() {
    asm volatile("cp.async.wait_group %0;" :: "n"(N) : "memory");
}
__device__ __forceinline__ void split2(float a, float b, uint32_t& hi, uint32_t& lo) {
    __half ha = __float2half_rn(a), hb = __float2half_rn(b);
    __half2 H = __halves2half2(ha, hb);
    __half2 L = __halves2half2(__float2half_rn(a - __half2float(ha)),
                               __float2half_rn(b - __half2float(hb)));
    hi = *(uint32_t*)&H;
    lo = *(uint32_t*)&L;
}
__device__ __forceinline__ uint32_t pack2h(float a, float b) {
    __half2 H = __halves2half2(__float2half_rn(a), __float2half_rn(b));
    return *(uint32_t*)&H;
}

// ======================= fused conversion kernel =======================
// blocks [0, 19456): five weight transposes+splits (wa2/wf2 hi-only).
// blocks [19456, 19456+4096): x fp32 -> fp16 hi (1024 floats per block).
#define CVT_BLOCKS (19456 + 4096)
__global__ void __launch_bounds__(256)
cvt_all_kernel(const float* __restrict__ W0, __half* __restrict__ h0, __half* __restrict__ l0,
               const float* __restrict__ W1, __half* __restrict__ h1, __half* __restrict__ l1,
               const float* __restrict__ W2, __half* __restrict__ h2,
               const float* __restrict__ W3, __half* __restrict__ h3, __half* __restrict__ l3,
               const float* __restrict__ W4, __half* __restrict__ h4,
               const float* __restrict__ x,  __half* __restrict__ xh)
{
    const int bid = blockIdx.x;
    if (bid >= 19456) {
        int i = ((bid - 19456) * 256 + threadIdx.x) * 4;
        float4 v = *(const float4*)(x + i);
        *(uint32_t*)(xh + i)     = pack2h(v.x, v.y);
        *(uint32_t*)(xh + i + 2) = pack2h(v.z, v.w);
        return;
    }
    __shared__ float tile[32][33];
    const float* W; __half* hi; __half* lo; int K, N, local;
    if      (bid < 3072)  { W = W0; hi = h0; lo = l0;      K = CC; N = C3; local = bid; }
    else if (bid < 7168)  { W = W1; hi = h1; lo = l1;      K = CC; N = C4; local = bid - 3072; }
    else if (bid < 11264) { W = W2; hi = h2; lo = nullptr; K = C4; N = CC; local = bid - 7168; }
    else if (bid < 15360) { W = W3; hi = h3; lo = l3;      K = CC; N = C4; local = bid - 11264; }
    else                  { W = W4; hi = h4; lo = nullptr; K = C4; N = CC; local = bid - 15360; }
    const int nb = N >> 5;
    const int n0 = (local % nb) * 32, k0 = (local / nb) * 32;
    const int tx = threadIdx.x & 31, ty = threadIdx.x >> 5;
#pragma unroll
    for (int r = 0; r < 4; ++r)
        tile[ty + r * 8][tx] = W[(size_t)(k0 + ty + r * 8) * N + n0 + tx];
    __syncthreads();
#pragma unroll
    for (int r = 0; r < 4; ++r) {
        int n = n0 + ty + r * 8;
        float v = tile[tx][ty + r * 8];
        __half h = __float2half_rn(v);
        hi[(size_t)n * K + k0 + tx] = h;
        if (lo) lo[(size_t)n * K + k0 + tx] = __float2half_rn(v - __half2float(h));
    }
}

// shared swizzle for 64B-row operand tiles
__device__ __forceinline__ uint32_t sw_off(int row, int kq) {
    return (uint32_t)(row * 64 + (((kq) ^ ((row >> 1) & 3)) << 4));
}

// ======================= HMMA fp16 GEMM, CTA 128x128 =======================
// 8 warps (2x4), warp tile 64x32, 3-stage cp.async, 2 CTAs/SM.
// PASSES=2: D = Ah*Bh + Ah*Bl.  PASSES=1: D = Ah*Bh (Blo unused).
// MODE 0: fp32 out.  MODE 1: exact-GELU, fp16 hi out.  MODE 2: fp16 hi+lo out.
#define GS2 (3 * 24576)
#define GS1 (3 * 16384)
template<int MODE, int PASSES>
__global__ void __launch_bounds__(256, 2)
gemm_mma_kernel(const __half* __restrict__ Ahi,
                const __half* __restrict__ Bhi, const __half* __restrict__ Blo,
                const float* __restrict__ bias, float* __restrict__ Cf,
                __half* __restrict__ Chi, __half* __restrict__ Clo,
                int N, int K)
{
    constexpr uint32_t STAGE   = (PASSES == 2) ? 24576u : 16384u;
    constexpr uint32_t BHI_OFF = 8192u;
    constexpr uint32_t BLO_OFF = 16384u;
    constexpr int ITER = (PASSES == 2) ? 6 : 4;

    extern __shared__ char smem[];
    const uint32_t sb = smem_u32(smem);

    const int t = threadIdx.x;
    const int wid = t >> 5, lane = t & 31;
    const int bm = blockIdx.y * 128;
    const int bn = blockIdx.x * 128;
    const int wm = wid >> 2, wn = wid & 3;

    float acc[4][4][4];
#pragma unroll
    for (int i = 0; i < 4; ++i)
#pragma unroll
        for (int j = 0; j < 4; ++j)
#pragma unroll
            for (int k = 0; k < 4; ++k) acc[i][j][k] = 0.0f;

    const int nc = K >> 5;

    const int g  = lane >> 3, lr = lane & 7;
    const int a_rit = lr + (g & 1) * 8, a_kqo = g >> 1;
    const int b_rit = lr + (g >> 1) * 8, b_kqo = g & 1;

    uint32_t aAhi[4], aBhi[2], aBlo[2];
    int aRsw[4], bRsw[2];
#pragma unroll
    for (int mt = 0; mt < 4; ++mt) {
        int row = wm * 64 + mt * 16 + a_rit;
        aAhi[mt] = sb + row * 64;
        aRsw[mt] = (row >> 1) & 3;
    }
#pragma unroll
    for (int p = 0; p < 2; ++p) {
        int row = wn * 32 + p * 16 + b_rit;
        aBhi[p] = sb + BHI_OFF + row * 64;
        aBlo[p] = sb + BLO_OFF + row * 64;
        bRsw[p] = (row >> 1) & 3;
    }

    auto issue = [&](int c, int s) {
        const uint32_t st = sb + s * STAGE;
        const int kb = c * 32;
#pragma unroll
        for (int i = 0; i < ITER; ++i) {
            int u = t + i * 256;
            const __half* src;
            uint32_t off;
            if (u < 512) {
                int row = u >> 2, kq = u & 3;
                src = Ahi + (size_t)(bm + row) * K + kb + kq * 8;
                off = sw_off(row, kq);
            } else {
                int w = u - 512;
                int arr = w >> 9, v = w & 511, row = v >> 2, kq = v & 3;
                src = (arr ? Blo : Bhi) + (size_t)(bn + row) * K + kb + kq * 8;
                off = BHI_OFF + arr * 8192u + sw_off(row, kq);
            }
            cp16(st + off, src);
        }
        cp_commit();
    };

    issue(0, 0);
    issue(1, 1);
    int s = 0;
    for (int c = 0; c < nc; ++c) {
        if (c + 2 < nc) { issue(c + 2, (c + 2) % 3); cp_wait<2>(); }
        else if (c + 1 < nc) cp_wait<1>();
        else cp_wait<0>();
        __syncthreads();

        const uint32_t stoff = (uint32_t)(s * STAGE);
#pragma unroll
        for (int ks = 0; ks < 2; ++ks) {
            uint32_t ah[4][4], bh[4][2], bl[4][2];
#pragma unroll
            for (int mt = 0; mt < 4; ++mt) {
                uint32_t o = (uint32_t)((((2 * ks + a_kqo) ^ aRsw[mt]) << 4));
                ldsm4(ah[mt], aAhi[mt] + stoff + o);
            }
#pragma unroll
            for (int p = 0; p < 2; ++p) {
                uint32_t r[4];
                uint32_t o = (uint32_t)((((2 * ks + b_kqo) ^ bRsw[p]) << 4));
                ldsm4(r, aBhi[p] + stoff + o);
                bh[2 * p][0] = r[0]; bh[2 * p][1] = r[1];
                bh[2 * p + 1][0] = r[2]; bh[2 * p + 1][1] = r[3];
                if (PASSES == 2) {
                    ldsm4(r, aBlo[p] + stoff + o);
                    bl[2 * p][0] = r[0]; bl[2 * p][1] = r[1];
                    bl[2 * p + 1][0] = r[2]; bl[2 * p + 1][1] = r[3];
                }
            }
#pragma unroll
            for (int mt = 0; mt < 4; ++mt)
#pragma unroll
                for (int nt = 0; nt < 4; ++nt) {
                    mma_f16(acc[mt][nt], ah[mt], bh[nt]);
                    if (PASSES == 2) mma_f16(acc[mt][nt], ah[mt], bl[nt]);
                }
        }
        __syncthreads();
        s = (s + 1) % 3;
    }

    const int mrow = bm + wm * 64;
    const int ncol = bn + wn * 32;
#pragma unroll
    for (int mt = 0; mt < 4; ++mt) {
#pragma unroll
        for (int nt = 0; nt < 4; ++nt) {
            float* d = acc[mt][nt];
            int r0 = mrow + mt * 16 + (lane >> 2);
            int cix = ncol + nt * 8 + (lane & 3) * 2;
            float b0 = bias[cix], b1 = bias[cix + 1];
            float v00 = d[0] + b0, v01 = d[1] + b1;
            float v10 = d[2] + b0, v11 = d[3] + b1;
            if (MODE == 0) {
                float2 p0{v00, v01}, p1{v10, v11};
                *(float2*)&Cf[(size_t)r0 * N + cix]       = p0;
                *(float2*)&Cf[(size_t)(r0 + 8) * N + cix] = p1;
            } else if (MODE == 1) {
                v00 = gelu_f(v00); v01 = gelu_f(v01);
                v10 = gelu_f(v10); v11 = gelu_f(v11);
                *(uint32_t*)&Chi[(size_t)r0 * N + cix]       = pack2h(v00, v01);
                *(uint32_t*)&Chi[(size_t)(r0 + 8) * N + cix] = pack2h(v10, v11);
            } else {
                uint32_t h0, l0, h1, l1;
                split2(v00, v01, h0, l0);
                split2(v10, v11, h1, l1);
                *(uint32_t*)&Chi[(size_t)r0 * N + cix]       = h0;
                *(uint32_t*)&Clo[(size_t)r0 * N + cix]       = l0;
                *(uint32_t*)&Chi[(size_t)(r0 + 8) * N + cix] = h1;
                *(uint32_t*)&Clo[(size_t)(r0 + 8) * N + cix] = l1;
            }
        }
    }
}

// ======================= HMMA causal attention (FA2-style) =======================
// QK: 3-pass split fp16.  PV: 2-pass (P hi-only x (Vh + Vl)).
#define ASMEM 49152
__device__ __forceinline__ uint32_t asw(int row, int u) {
    return (uint32_t)(row * 128 + ((u ^ (row & 7)) << 4));
}

__global__ void __launch_bounds__(128, 3)
attn_mma_kernel(const __half* __restrict__ qkvh, const __half* __restrict__ qkvl,
                __half* __restrict__ ohi)
{
    extern __shared__ char asmem[];
    const uint32_t sb = smem_u32(asmem);

    const int t = threadIdx.x, wid = t >> 5, lane = t & 31;
    const int qi = gridDim.x - 1 - blockIdx.x;   // heavy tiles first
    const int qb = qi * 64;
    const int h  = blockIdx.y, b = blockIdx.z;

    const __half* Kh_g = qkvh + (size_t)b * TT * C3 + h * HDD;
    const __half* Kl_g = qkvl + (size_t)b * TT * C3 + h * HDD;
    const __half* Qh_g = Kh_g + CC;
    const __half* Ql_g = Kl_g + CC;
    const __half* Vh_g = Kh_g + 2 * CC;
    const __half* Vl_g = Kl_g + 2 * CC;

#pragma unroll
    for (int i = 0; i < 8; ++i) {
        int uu = t + i * 128;
        int arr = uu >> 9, v = uu & 511, row = v >> 3, u = v & 7;
        const __half* src = (arr ? Ql_g : Qh_g) + (size_t)(qb + row) * C3 + u * 8;
        cp16(sb + arr * 8192 + asw(row, u), src);
    }
    cp_commit();

    const int g = lane >> 3, lr = lane & 7;
    const int r = lane >> 2, c = lane & 3;
    const int qrow = wid * 16 + lr + ((g & 1) << 3);
    const int a_u  = g >> 1;
    const int krit = lr + ((g >> 1) << 3);
    const int b_u  = g & 1;
    const int vrit = lr + ((g & 1) << 3);
    const int v_u  = g >> 1;

    float O[8][4];
#pragma unroll
    for (int i = 0; i < 8; ++i)
#pragma unroll
        for (int j = 0; j < 4; ++j) O[i][j] = 0.0f;
    float m0 = -1e30f, m1 = -1e30f, l0 = 0.0f, l1 = 0.0f;

    const int ntiles = qi + 1;
    for (int kt = 0; kt < ntiles; ++kt) {
        const int kb = kt * 64;
        __syncthreads();
#pragma unroll
        for (int i = 0; i < 16; ++i) {
            int uu = t + i * 128;
            int arr = uu >> 9, v = uu & 511, row = v >> 3, u = v & 7;
            const __half* src;
            if      (arr == 0) src = Kh_g + (size_t)(kb + row) * C3 + u * 8;
            else if (arr == 1) src = Kl_g + (size_t)(kb + row) * C3 + u * 8;
            else if (arr == 2) src = Vh_g + (size_t)(kb + row) * C3 + u * 8;
            else               src = Vl_g + (size_t)(kb + row) * C3 + u * 8;
            cp16(sb + 16384 + arr * 8192 + asw(row, u), src);
        }
        cp_commit();
        cp_wait<0>();
        __syncthreads();

        float S[8][4];
#pragma unroll
        for (int i = 0; i < 8; ++i)
#pragma unroll
            for (int j = 0; j < 4; ++j) S[i][j] = 0.0f;

#pragma unroll
        for (int kk = 0; kk < 4; ++kk) {
            uint32_t ah[4], al[4];
            uint32_t aoq = (uint32_t)(qrow * 128 + ((((kk << 1) | a_u) ^ (qrow & 7)) << 4));
            ldsm4(ah, sb + aoq);
            ldsm4(al, sb + 8192 + aoq);
#pragma unroll
            for (int p = 0; p < 4; ++p) {
                int krow = (p << 4) + krit;
                uint32_t ko = (uint32_t)(krow * 128 + ((((kk << 1) | b_u) ^ (krow & 7)) << 4));
                uint32_t bh[4], bl[4];
                ldsm4(bh, sb + 16384 + ko);
                ldsm4(bl, sb + 24576 + ko);
                mma_f16(S[2 * p],     ah, bh);
                mma_f16(S[2 * p],     ah, bl);
                mma_f16(S[2 * p],     al, bh);
                mma_f16(S[2 * p + 1], ah, bh + 2);
                mma_f16(S[2 * p + 1], ah, bl + 2);
                mma_f16(S[2 * p + 1], al, bh + 2);
            }
        }

#pragma unroll
        for (int nt = 0; nt < 8; ++nt)
#pragma unroll
            for (int e = 0; e < 4; ++e) S[nt][e] *= 0.125f;
        if (kt == qi) {
            const int q0 = qb + wid * 16 + r, q1 = q0 + 8;
#pragma unroll
            for (int nt = 0; nt < 8; ++nt) {
                int k0 = kb + 8 * nt + 2 * c;
                if (k0     > q0) S[nt][0] = -1e30f;
                if (k0 + 1 > q0) S[nt][1] = -1e30f;
                if (k0     > q1) S[nt][2] = -1e30f;
                if (k0 + 1 > q1) S[nt][3] = -1e30f;
            }
        }

        float mx0 = -1e30f, mx1 = -1e30f;
#pragma unroll
        for (int nt = 0; nt < 8; ++nt) {
            mx0 = fmaxf(mx0, fmaxf(S[nt][0], S[nt][1]));
            mx1 = fmaxf(mx1, fmaxf(S[nt][2], S[nt][3]));
        }
        mx0 = fmaxf(mx0, __shfl_xor_sync(0xffffffffu, mx0, 1));
        mx0 = fmaxf(mx0, __shfl_xor_sync(0xffffffffu, mx0, 2));
        mx1 = fmaxf(mx1, __shfl_xor_sync(0xffffffffu, mx1, 1));
        mx1 = fmaxf(mx1, __shfl_xor_sync(0xffffffffu, mx1, 2));
        float mn0 = fmaxf(m0, mx0), mn1 = fmaxf(m1, mx1);
        float al0 = __expf(m0 - mn0), al1 = __expf(m1 - mn1);
        m0 = mn0; m1 = mn1;

        float s0 = 0.0f, s1 = 0.0f;
#pragma unroll
        for (int nt = 0; nt < 8; ++nt) {
            S[nt][0] = __expf(S[nt][0] - mn0);
            S[nt][1] = __expf(S[nt][1] - mn0);
            S[nt][2] = __expf(S[nt][2] - mn1);
            S[nt][3] = __expf(S[nt][3] - mn1);
            s0 += S[nt][0] + S[nt][1];
            s1 += S[nt][2] + S[nt][3];
        }
        l0 = l0 * al0 + s0;
        l1 = l1 * al1 + s1;
#pragma unroll
        for (int nt = 0; nt < 8; ++nt) {
            O[nt][0] *= al0; O[nt][1] *= al0;
            O[nt][2] *= al1; O[nt][3] *= al1;
        }

        // O += P * (Vh + Vl), P in fp16 hi only
#pragma unroll
        for (int kk = 0; kk < 4; ++kk) {
            uint32_t ph[4];
            ph[0] = pack2h(S[2 * kk][0],     S[2 * kk][1]);
            ph[1] = pack2h(S[2 * kk][2],     S[2 * kk][3]);
            ph[2] = pack2h(S[2 * kk + 1][0], S[2 * kk + 1][1]);
            ph[3] = pack2h(S[2 * kk + 1][2], S[2 * kk + 1][3]);
            int vrow = (kk << 4) + vrit;
#pragma unroll
            for (int p = 0; p < 4; ++p) {
                uint32_t vo = (uint32_t)(vrow * 128 + ((((p << 1) | v_u) ^ (vrow & 7)) << 4));
                uint32_t vh[4], vl[4];
                ldsm4t(vh, sb + 32768 + vo);
                ldsm4t(vl, sb + 40960 + vo);
                mma_f16(O[2 * p],     ph, vh);
                mma_f16(O[2 * p],     ph, vl);
                mma_f16(O[2 * p + 1], ph, vh + 2);
                mma_f16(O[2 * p + 1], ph, vl + 2);
            }
        }
    }

    l0 += __shfl_xor_sync(0xffffffffu, l0, 1);
    l0 += __shfl_xor_sync(0xffffffffu, l0, 2);
    l1 += __shfl_xor_sync(0xffffffffu, l1, 1);
    l1 += __shfl_xor_sync(0xffffffffu, l1, 2);
    const float i0 = 1.0f / l0, i1 = 1.0f / l1;
    const int row0 = qb + wid * 16 + r, row1 = row0 + 8;
#pragma unroll
    for (int nt = 0; nt < 8; ++nt) {
        int col = h * HDD + 8 * nt + 2 * c;
        size_t idx0 = ((size_t)b * TT + row0) * CC + col;
        size_t idx1 = ((size_t)b * TT + row1) * CC + col;
        *(uint32_t*)&ohi[idx0] = pack2h(O[nt][0] * i0, O[nt][1] * i0);
        *(uint32_t*)&ohi[idx1] = pack2h(O[nt][2] * i1, O[nt][3] * i1);
    }
}

// ---------------- LayerNorm + residual ----------------
__device__ __forceinline__ float block_sum(float v, float* red) {
    const int lane = threadIdx.x & 31, w = threadIdx.x >> 5;
#pragma unroll
    for (int o = 16; o; o >>= 1) v += __shfl_xor_sync(0xffffffffu, v, o);
    if (lane == 0) red[w] = v;
    __syncthreads();
    if (w == 0) {
        float s = (lane < 8) ? red[lane] : 0.0f;
#pragma unroll
        for (int o = 4; o; o >>= 1) s += __shfl_xor_sync(0xffffffffu, s, o);
        if (lane == 0) red[0] = s;
    }
    __syncthreads();
    float rr = red[0];
    __syncthreads();
    return rr;
}

template<bool SPLIT>
__global__ void __launch_bounds__(256)
ln_res_kernel(const float* __restrict__ res, const float* __restrict__ y,
              const float* __restrict__ g, const float* __restrict__ be,
              float* __restrict__ out, __half* __restrict__ ohi)
{
    __shared__ float red[8];
    const int row = blockIdx.x;
    const int t = threadIdx.x;
    const float* yr = y + (size_t)row * CC;

    float v[4];
    float s = 0.0f;
#pragma unroll
    for (int i = 0; i < 4; ++i) { v[i] = yr[t + i * 256]; s += v[i]; }
    const float mean = block_sum(s, red) * (1.0f / CC);

    float sq = 0.0f;
#pragma unroll
    for (int i = 0; i < 4; ++i) { float d = v[i] - mean; sq += d * d; }
    const float var = block_sum(sq, red) * (1.0f / CC);
    const float rstd = rsqrtf(var + 1e-5f);

    const float* rr = res + (size_t)row * CC;
    float* orow = out + (size_t)row * CC;
#pragma unroll
    for (int i = 0; i < 4; ++i) {
        int cix = t + i * 256;
        float o = rr[cix] + (v[i] - mean) * rstd * g[cix] + be[cix];
        orow[cix] = o;
        if (SPLIT) ohi[(size_t)row * CC + cix] = __float2half_rn(o);
    }
}

// ---------------- launch ----------------
extern "C" void kernel_launch(void* const* d_in, const int* in_sizes, int n_in,
                              void* d_out, int out_size)
{
    const float* x      = (const float*)d_in[0];
    const float* w_attn = (const float*)d_in[1];
    const float* b_attn = (const float*)d_in[2];
    const float* wa1    = (const float*)d_in[3];
    const float* ba1    = (const float*)d_in[4];
    const float* wa2    = (const float*)d_in[5];
    const float* ba2    = (const float*)d_in[6];
    const float* g1     = (const float*)d_in[7];
    const float* be1    = (const float*)d_in[8];
    const float* wf1    = (const float*)d_in[9];
    const float* bf1    = (const float*)d_in[10];
    const float* wf2    = (const float*)d_in[11];
    const float* bf2    = (const float*)d_in[12];
    const float* g2     = (const float*)d_in[13];
    const float* be2    = (const float*)d_in[14];
    float* out = (float*)d_out;

    float *x1, *y;
    cudaGetSymbolAddress((void**)&x1, g_x1);
    cudaGetSymbolAddress((void**)&y,  g_y);

    __half *wqkv_hi, *wqkv_lo, *wa1_hi, *wa1_lo, *wa2_hi,
           *wf1_hi, *wf1_lo, *wf2_hi, *ahi, *hhi, *qkvh, *qkvl;
    cudaGetSymbolAddress((void**)&wqkv_hi, g_wqkv_hi);
    cudaGetSymbolAddress((void**)&wqkv_lo, g_wqkv_lo);
    cudaGetSymbolAddress((void**)&wa1_hi,  g_wa1_hi);
    cudaGetSymbolAddress((void**)&wa1_lo,  g_wa1_lo);
    cudaGetSymbolAddress((void**)&wa2_hi,  g_wa2_hi);
    cudaGetSymbolAddress((void**)&wf1_hi,  g_wf1_hi);
    cudaGetSymbolAddress((void**)&wf1_lo,  g_wf1_lo);
    cudaGetSymbolAddress((void**)&wf2_hi,  g_wf2_hi);
    cudaGetSymbolAddress((void**)&ahi,     g_ahi);
    cudaGetSymbolAddress((void**)&hhi,     g_hhi);
    cudaGetSymbolAddress((void**)&qkvh,    g_qkvh);
    cudaGetSymbolAddress((void**)&qkvl,    g_qkvl);

    cudaFuncSetAttribute(attn_mma_kernel, cudaFuncAttributeMaxDynamicSharedMemorySize, ASMEM);
    cudaFuncSetAttribute((gemm_mma_kernel<2, 2>), cudaFuncAttributeMaxDynamicSharedMemorySize, GS2);
    cudaFuncSetAttribute((gemm_mma_kernel<1, 2>), cudaFuncAttributeMaxDynamicSharedMemorySize, GS2);
    cudaFuncSetAttribute((gemm_mma_kernel<0, 1>), cudaFuncAttributeMaxDynamicSharedMemorySize, GS1);

    // all conversions (5 weights + x) in one launch
    cvt_all_kernel<<<CVT_BLOCKS, 256>>>(
        w_attn, wqkv_hi, wqkv_lo,
        wa1, wa1_hi, wa1_lo,
        wa2, wa2_hi,
        wf1, wf1_hi, wf1_lo,
        wf2, wf2_hi,
        x, ahi);

    // 1) qkv = x @ w_attn + b_attn  (2-pass, hi+lo out)
    gemm_mma_kernel<2, 2><<<dim3(C3 / 128, MTOK / 128), 256, GS2>>>(
        ahi, wqkv_hi, wqkv_lo, b_attn, nullptr, qkvh, qkvl, C3, CC);
    // 2) attention -> hi-only att
    attn_mma_kernel<<<dim3(TT / 64, NHH, BB), 128, ASMEM>>>(qkvh, qkvl, ahi);
    // 3) h = gelu(att @ wa1 + ba1)  (2-pass)
    gemm_mma_kernel<1, 2><<<dim3(C4 / 128, MTOK / 128), 256, GS2>>>(
        ahi, wa1_hi, wa1_lo, ba1, nullptr, hhi, nullptr, C4, CC);
    // 4) y = h @ wa2 + ba2  (1-pass)
    gemm_mma_kernel<0, 1><<<dim3(CC / 128, MTOK / 128), 256, GS1>>>(
        hhi, wa2_hi, nullptr, ba2, y, nullptr, nullptr, CC, C4);
    // 5) x1 = x + ln(y); emit fp16 x1 hi
    ln_res_kernel<true><<<MTOK, 256>>>(x, y, g1, be1, x1, ahi);
    // 6) h = gelu(x1 @ wf1 + bf1)  (2-pass)
    gemm_mma_kernel<1, 2><<<dim3(C4 / 128, MTOK / 128), 256, GS2>>>(
        ahi, wf1_hi, wf1_lo, bf1, nullptr, hhi, nullptr, C4, CC);
    // 7) y = h @ wf2 + bf2  (1-pass)
    gemm_mma_kernel<0, 1><<<dim3(CC / 128, MTOK / 128), 256, GS1>>>(
        hhi, wf2_hi, nullptr, bf2, y, nullptr, nullptr, CC, C4);
    // 8) out = x1 + ln(y)
    ln_res_kernel<false><<<MTOK, 256>>>(x1, y, g2, be2, out, nullptr);
}

// round 10
// speedup vs baseline: 1.7926x; 1.0310x over previous
#include <cuda_runtime.h>
#include <cuda_fp16.h>
#include <math.h>
#include <stdint.h>

// Problem dims (fixed)
#define BB 2
#define TT 2048
#define CC 1024
#define NHH 16
#define HDD 64
#define MTOK 4096          // B*T
#define C3 3072
#define C4 4096

// ---------------- scratch (no allocation allowed) ----------------
__device__ float g_x1 [(size_t)MTOK * CC];
__device__ float g_y  [(size_t)MTOK * CC];

// fp16 split weights, transposed to [N][K] (lo unused for wa2/wf2)
__device__ __half g_wqkv_hi[(size_t)C3 * CC], g_wqkv_lo[(size_t)C3 * CC];
__device__ __half g_wa1_hi [(size_t)C4 * CC], g_wa1_lo [(size_t)C4 * CC];
__device__ __half g_wa2_hi [(size_t)CC * C4];
__device__ __half g_wf1_hi [(size_t)C4 * CC], g_wf1_lo [(size_t)C4 * CC];
__device__ __half g_wf2_hi [(size_t)CC * C4];
// fp16 activations
__device__ __half g_ahi [(size_t)MTOK * CC];
__device__ __half g_hhi [(size_t)MTOK * C4];
__device__ __half g_qkvh[(size_t)MTOK * C3], g_qkvl[(size_t)MTOK * C3];

__device__ __forceinline__ float gelu_f(float v) {
    return 0.5f * v * (1.0f + erff(v * 0.7071067811865475f));
}

// ======================= PTX helpers =======================
__device__ __forceinline__ uint32_t smem_u32(const void* p) {
    uint32_t a;
    asm("{ .reg .u64 t; cvta.to.shared.u64 t, %1; cvt.u32.u64 %0, t; }" : "=r"(a) : "l"(p));
    return a;
}
__device__ __forceinline__ void ldsm4(uint32_t* r, uint32_t addr) {
    asm volatile("ldmatrix.sync.aligned.m8n8.x4.shared.b16 {%0,%1,%2,%3}, [%4];"
                 : "=r"(r[0]), "=r"(r[1]), "=r"(r[2]), "=r"(r[3]) : "r"(addr));
}
__device__ __forceinline__ void ldsm4t(uint32_t* r, uint32_t addr) {
    asm volatile("ldmatrix.sync.aligned.m8n8.x4.trans.shared.b16 {%0,%1,%2,%3}, [%4];"
                 : "=r"(r[0]), "=r"(r[1]), "=r"(r[2]), "=r"(r[3]) : "r"(addr));
}
__device__ __forceinline__ void mma_f16(float* d, const uint32_t* a, const uint32_t* b) {
    asm volatile(
        "mma.sync.aligned.m16n8k16.row.col.f32.f16.f16.f32 "
        "{%0,%1,%2,%3}, {%4,%5,%6,%7}, {%8,%9}, {%0,%1,%2,%3};"
        : "+f"(d[0]), "+f"(d[1]), "+f"(d[2]), "+f"(d[3])
        : "r"(a[0]), "r"(a[1]), "r"(a[2]), "r"(a[3]), "r"(b[0]), "r"(b[1]));
}
__device__ __forceinline__ void cp16(uint32_t dst, const void* src) {
    unsigned long long g = __cvta_generic_to_global(src);
    asm volatile("cp.async.ca.shared.global [%0], [%1], 16;" :: "r"(dst), "l"(g) : "memory");
}
__device__ __forceinline__ void cp_commit() {
    asm volatile("cp.async.commit_group;" ::: "memory");
}
template<int N>
__device__ __forceinline__ void cp_wait() {
    asm volatile("cp.async.wait_group %0;" :: "n"(N) : "memory");
}
__device__ __forceinline__ void split2(float a, float b, uint32_t& hi, uint32_t& lo) {
    __half ha = __float2half_rn(a), hb = __float2half_rn(b);
    __half2 H = __halves2half2(ha, hb);
    __half2 L = __halves2half2(__float2half_rn(a - __half2float(ha)),
                               __float2half_rn(b - __half2float(hb)));
    hi = *(uint32_t*)&H;
    lo = *(uint32_t*)&L;
}
__device__ __forceinline__ uint32_t pack2h(float a, float b) {
    __half2 H = __halves2half2(__float2half_rn(a), __float2half_rn(b));
    return *(uint32_t*)&H;
}

// ======================= fused conversion kernel =======================
#define CVT_BLOCKS (19456 + 4096)
__global__ void __launch_bounds__(256)
cvt_all_kernel(const float* __restrict__ W0, __half* __restrict__ h0, __half* __restrict__ l0,
               const float* __restrict__ W1, __half* __restrict__ h1, __half* __restrict__ l1,
               const float* __restrict__ W2, __half* __restrict__ h2,
               const float* __restrict__ W3, __half* __restrict__ h3, __half* __restrict__ l3,
               const float* __restrict__ W4, __half* __restrict__ h4,
               const float* __restrict__ x,  __half* __restrict__ xh)
{
    const int bid = blockIdx.x;
    if (bid >= 19456) {
        int i = ((bid - 19456) * 256 + threadIdx.x) * 4;
        float4 v = *(const float4*)(x + i);
        *(uint32_t*)(xh + i)     = pack2h(v.x, v.y);
        *(uint32_t*)(xh + i + 2) = pack2h(v.z, v.w);
        return;
    }
    __shared__ float tile[32][33];
    const float* W; __half* hi; __half* lo; int K, N, local;
    if      (bid < 3072)  { W = W0; hi = h0; lo = l0;      K = CC; N = C3; local = bid; }
    else if (bid < 7168)  { W = W1; hi = h1; lo = l1;      K = CC; N = C4; local = bid - 3072; }
    else if (bid < 11264) { W = W2; hi = h2; lo = nullptr; K = C4; N = CC; local = bid - 7168; }
    else if (bid < 15360) { W = W3; hi = h3; lo = l3;      K = CC; N = C4; local = bid - 11264; }
    else                  { W = W4; hi = h4; lo = nullptr; K = C4; N = CC; local = bid - 15360; }
    const int nb = N >> 5;
    const int n0 = (local % nb) * 32, k0 = (local / nb) * 32;
    const int tx = threadIdx.x & 31, ty = threadIdx.x >> 5;
#pragma unroll
    for (int r = 0; r < 4; ++r)
        tile[ty + r * 8][tx] = W[(size_t)(k0 + ty + r * 8) * N + n0 + tx];
    __syncthreads();
#pragma unroll
    for (int r = 0; r < 4; ++r) {
        int n = n0 + ty + r * 8;
        float v = tile[tx][ty + r * 8];
        __half h = __float2half_rn(v);
        hi[(size_t)n * K + k0 + tx] = h;
        if (lo) lo[(size_t)n * K + k0 + tx] = __float2half_rn(v - __half2float(h));
    }
}

// shared swizzle for 64B-row operand tiles
__device__ __forceinline__ uint32_t sw_off(int row, int kq) {
    return (uint32_t)(row * 64 + (((kq) ^ ((row >> 1) & 3)) << 4));
}

// ======================= HMMA fp16 GEMM, CTA 128x128 =======================
// 8 warps (2x4), warp tile 64x32, 3-stage cp.async, 2 CTAs/SM,
// SINGLE __syncthreads per K-chunk (issue moved after the barrier).
#define GS2 (3 * 24576)
#define GS1 (3 * 16384)
template<int MODE, int PASSES>
__global__ void __launch_bounds__(256, 2)
gemm_mma_kernel(const __half* __restrict__ Ahi,
                const __half* __restrict__ Bhi, const __half* __restrict__ Blo,
                const float* __restrict__ bias, float* __restrict__ Cf,
                __half* __restrict__ Chi, __half* __restrict__ Clo,
                int N, int K)
{
    constexpr uint32_t STAGE   = (PASSES == 2) ? 24576u : 16384u;
    constexpr uint32_t BHI_OFF = 8192u;
    constexpr uint32_t BLO_OFF = 16384u;
    constexpr int ITER = (PASSES == 2) ? 6 : 4;

    extern __shared__ char smem[];
    const uint32_t sb = smem_u32(smem);

    const int t = threadIdx.x;
    const int wid = t >> 5, lane = t & 31;
    const int bm = blockIdx.y * 128;
    const int bn = blockIdx.x * 128;
    const int wm = wid >> 2, wn = wid & 3;

    float acc[4][4][4];
#pragma unroll
    for (int i = 0; i < 4; ++i)
#pragma unroll
        for (int j = 0; j < 4; ++j)
#pragma unroll
            for (int k = 0; k < 4; ++k) acc[i][j][k] = 0.0f;

    const int nc = K >> 5;

    const int g  = lane >> 3, lr = lane & 7;
    const int a_rit = lr + (g & 1) * 8, a_kqo = g >> 1;
    const int b_rit = lr + (g >> 1) * 8, b_kqo = g & 1;

    uint32_t aAhi[4], aBhi[2], aBlo[2];
    int aRsw[4], bRsw[2];
#pragma unroll
    for (int mt = 0; mt < 4; ++mt) {
        int row = wm * 64 + mt * 16 + a_rit;
        aAhi[mt] = sb + row * 64;
        aRsw[mt] = (row >> 1) & 3;
    }
#pragma unroll
    for (int p = 0; p < 2; ++p) {
        int row = wn * 32 + p * 16 + b_rit;
        aBhi[p] = sb + BHI_OFF + row * 64;
        aBlo[p] = sb + BLO_OFF + row * 64;
        bRsw[p] = (row >> 1) & 3;
    }

    auto issue = [&](int c, int s) {
        const uint32_t st = sb + s * STAGE;
        const int kb = c * 32;
#pragma unroll
        for (int i = 0; i < ITER; ++i) {
            int u = t + i * 256;
            const __half* src;
            uint32_t off;
            if (u < 512) {
                int row = u >> 2, kq = u & 3;
                src = Ahi + (size_t)(bm + row) * K + kb + kq * 8;
                off = sw_off(row, kq);
            } else {
                int w = u - 512;
                int arr = w >> 9, v = w & 511, row = v >> 2, kq = v & 3;
                src = (arr ? Blo : Bhi) + (size_t)(bn + row) * K + kb + kq * 8;
                off = BHI_OFF + arr * 8192u + sw_off(row, kq);
            }
            cp16(st + off, src);
        }
        cp_commit();
    };

    issue(0, 0);
    issue(1, 1);
    int s = 0;
    for (int c = 0; c < nc; ++c) {
        cp_wait<1>();            // stage s data landed
        __syncthreads();         // visible to all; also: all warps done reading stage (c+2)%3
        if (c + 2 < nc) issue(c + 2, (c + 2) % 3);
        else if (c + 1 == nc) cp_wait<0>();   // (defensive; no groups matter here)

        const uint32_t stoff = (uint32_t)(s * STAGE);
#pragma unroll
        for (int ks = 0; ks < 2; ++ks) {
            uint32_t ah[4][4], bh[4][2], bl[4][2];
#pragma unroll
            for (int mt = 0; mt < 4; ++mt) {
                uint32_t o = (uint32_t)((((2 * ks + a_kqo) ^ aRsw[mt]) << 4));
                ldsm4(ah[mt], aAhi[mt] + stoff + o);
            }
#pragma unroll
            for (int p = 0; p < 2; ++p) {
                uint32_t r[4];
                uint32_t o = (uint32_t)((((2 * ks + b_kqo) ^ bRsw[p]) << 4));
                ldsm4(r, aBhi[p] + stoff + o);
                bh[2 * p][0] = r[0]; bh[2 * p][1] = r[1];
                bh[2 * p + 1][0] = r[2]; bh[2 * p + 1][1] = r[3];
                if (PASSES == 2) {
                    ldsm4(r, aBlo[p] + stoff + o);
                    bl[2 * p][0] = r[0]; bl[2 * p][1] = r[1];
                    bl[2 * p + 1][0] = r[2]; bl[2 * p + 1][1] = r[3];
                }
            }
#pragma unroll
            for (int mt = 0; mt < 4; ++mt)
#pragma unroll
                for (int nt = 0; nt < 4; ++nt) {
                    mma_f16(acc[mt][nt], ah[mt], bh[nt]);
                    if (PASSES == 2) mma_f16(acc[mt][nt], ah[mt], bl[nt]);
                }
        }
        s = (s + 1) % 3;
    }

    const int mrow = bm + wm * 64;
    const int ncol = bn + wn * 32;
#pragma unroll
    for (int mt = 0; mt < 4; ++mt) {
#pragma unroll
        for (int nt = 0; nt < 4; ++nt) {
            float* d = acc[mt][nt];
            int r0 = mrow + mt * 16 + (lane >> 2);
            int cix = ncol + nt * 8 + (lane & 3) * 2;
            float b0 = bias[cix], b1 = bias[cix + 1];
            float v00 = d[0] + b0, v01 = d[1] + b1;
            float v10 = d[2] + b0, v11 = d[3] + b1;
            if (MODE == 0) {
                float2 p0{v00, v01}, p1{v10, v11};
                *(float2*)&Cf[(size_t)r0 * N + cix]       = p0;
                *(float2*)&Cf[(size_t)(r0 + 8) * N + cix] = p1;
            } else if (MODE == 1) {
                v00 = gelu_f(v00); v01 = gelu_f(v01);
                v10 = gelu_f(v10); v11 = gelu_f(v11);
                *(uint32_t*)&Chi[(size_t)r0 * N + cix]       = pack2h(v00, v01);
                *(uint32_t*)&Chi[(size_t)(r0 + 8) * N + cix] = pack2h(v10, v11);
            } else {
                uint32_t h0, l0, h1, l1;
                split2(v00, v01, h0, l0);
                split2(v10, v11, h1, l1);
                *(uint32_t*)&Chi[(size_t)r0 * N + cix]       = h0;
                *(uint32_t*)&Clo[(size_t)r0 * N + cix]       = l0;
                *(uint32_t*)&Chi[(size_t)(r0 + 8) * N + cix] = h1;
                *(uint32_t*)&Clo[(size_t)(r0 + 8) * N + cix] = l1;
            }
        }
    }
}

// ======================= HMMA causal attention (FA2-style) =======================
// QK: 3-pass split fp16.  PV: 2-pass (P hi-only x (Vh + Vl)).
#define ASMEM 49152
__device__ __forceinline__ uint32_t asw(int row, int u) {
    return (uint32_t)(row * 128 + ((u ^ (row & 7)) << 4));
}

__global__ void __launch_bounds__(128, 3)
attn_mma_kernel(const __half* __restrict__ qkvh, const __half* __restrict__ qkvl,
                __half* __restrict__ ohi)
{
    extern __shared__ char asmem[];
    const uint32_t sb = smem_u32(asmem);

    const int t = threadIdx.x, wid = t >> 5, lane = t & 31;
    const int qi = gridDim.x - 1 - blockIdx.x;   // heavy tiles first
    const int qb = qi * 64;
    const int h  = blockIdx.y, b = blockIdx.z;

    const __half* Kh_g = qkvh + (size_t)b * TT * C3 + h * HDD;
    const __half* Kl_g = qkvl + (size_t)b * TT * C3 + h * HDD;
    const __half* Qh_g = Kh_g + CC;
    const __half* Ql_g = Kl_g + CC;
    const __half* Vh_g = Kh_g + 2 * CC;
    const __half* Vl_g = Kl_g + 2 * CC;

#pragma unroll
    for (int i = 0; i < 8; ++i) {
        int uu = t + i * 128;
        int arr = uu >> 9, v = uu & 511, row = v >> 3, u = v & 7;
        const __half* src = (arr ? Ql_g : Qh_g) + (size_t)(qb + row) * C3 + u * 8;
        cp16(sb + arr * 8192 + asw(row, u), src);
    }
    cp_commit();

    const int g = lane >> 3, lr = lane & 7;
    const int r = lane >> 2, c = lane & 3;
    const int qrow = wid * 16 + lr + ((g & 1) << 3);
    const int a_u  = g >> 1;
    const int krit = lr + ((g >> 1) << 3);
    const int b_u  = g & 1;
    const int vrit = lr + ((g & 1) << 3);
    const int v_u  = g >> 1;

    float O[8][4];
#pragma unroll
    for (int i = 0; i < 8; ++i)
#pragma unroll
        for (int j = 0; j < 4; ++j) O[i][j] = 0.0f;
    float m0 = -1e30f, m1 = -1e30f, l0 = 0.0f, l1 = 0.0f;

    const int ntiles = qi + 1;
    for (int kt = 0; kt < ntiles; ++kt) {
        const int kb = kt * 64;
        __syncthreads();
#pragma unroll
        for (int i = 0; i < 16; ++i) {
            int uu = t + i * 128;
            int arr = uu >> 9, v = uu & 511, row = v >> 3, u = v & 7;
            const __half* src;
            if      (arr == 0) src = Kh_g + (size_t)(kb + row) * C3 + u * 8;
            else if (arr == 1) src = Kl_g + (size_t)(kb + row) * C3 + u * 8;
            else if (arr == 2) src = Vh_g + (size_t)(kb + row) * C3 + u * 8;
            else               src = Vl_g + (size_t)(kb + row) * C3 + u * 8;
            cp16(sb + 16384 + arr * 8192 + asw(row, u), src);
        }
        cp_commit();
        cp_wait<0>();
        __syncthreads();

        float S[8][4];
#pragma unroll
        for (int i = 0; i < 8; ++i)
#pragma unroll
            for (int j = 0; j < 4; ++j) S[i][j] = 0.0f;

#pragma unroll
        for (int kk = 0; kk < 4; ++kk) {
            uint32_t ah[4], al[4];
            uint32_t aoq = (uint32_t)(qrow * 128 + ((((kk << 1) | a_u) ^ (qrow & 7)) << 4));
            ldsm4(ah, sb + aoq);
            ldsm4(al, sb + 8192 + aoq);
#pragma unroll
            for (int p = 0; p < 4; ++p) {
                int krow = (p << 4) + krit;
                uint32_t ko = (uint32_t)(krow * 128 + ((((kk << 1) | b_u) ^ (krow & 7)) << 4));
                uint32_t bh[4], bl[4];
                ldsm4(bh, sb + 16384 + ko);
                ldsm4(bl, sb + 24576 + ko);
                mma_f16(S[2 * p],     ah, bh);
                mma_f16(S[2 * p],     ah, bl);
                mma_f16(S[2 * p],     al, bh);
                mma_f16(S[2 * p + 1], ah, bh + 2);
                mma_f16(S[2 * p + 1], ah, bl + 2);
                mma_f16(S[2 * p + 1], al, bh + 2);
            }
        }

#pragma unroll
        for (int nt = 0; nt < 8; ++nt)
#pragma unroll
            for (int e = 0; e < 4; ++e) S[nt][e] *= 0.125f;
        if (kt == qi) {
            const int q0 = qb + wid * 16 + r, q1 = q0 + 8;
#pragma unroll
            for (int nt = 0; nt < 8; ++nt) {
                int k0 = kb + 8 * nt + 2 * c;
                if (k0     > q0) S[nt][0] = -1e30f;
                if (k0 + 1 > q0) S[nt][1] = -1e30f;
                if (k0     > q1) S[nt][2] = -1e30f;
                if (k0 + 1 > q1) S[nt][3] = -1e30f;
            }
        }

        float mx0 = -1e30f, mx1 = -1e30f;
#pragma unroll
        for (int nt = 0; nt < 8; ++nt) {
            mx0 = fmaxf(mx0, fmaxf(S[nt][0], S[nt][1]));
            mx1 = fmaxf(mx1, fmaxf(S[nt][2], S[nt][3]));
        }
        mx0 = fmaxf(mx0, __shfl_xor_sync(0xffffffffu, mx0, 1));
        mx0 = fmaxf(mx0, __shfl_xor_sync(0xffffffffu, mx0, 2));
        mx1 = fmaxf(mx1, __shfl_xor_sync(0xffffffffu, mx1, 1));
        mx1 = fmaxf(mx1, __shfl_xor_sync(0xffffffffu, mx1, 2));
        float mn0 = fmaxf(m0, mx0), mn1 = fmaxf(m1, mx1);
        float al0 = __expf(m0 - mn0), al1 = __expf(m1 - mn1);
        m0 = mn0; m1 = mn1;

        float s0 = 0.0f, s1 = 0.0f;
#pragma unroll
        for (int nt = 0; nt < 8; ++nt) {
            S[nt][0] = __expf(S[nt][0] - mn0);
            S[nt][1] = __expf(S[nt][1] - mn0);
            S[nt][2] = __expf(S[nt][2] - mn1);
            S[nt][3] = __expf(S[nt][3] - mn1);
            s0 += S[nt][0] + S[nt][1];
            s1 += S[nt][2] + S[nt][3];
        }
        l0 = l0 * al0 + s0;
        l1 = l1 * al1 + s1;
#pragma unroll
        for (int nt = 0; nt < 8; ++nt) {
            O[nt][0] *= al0; O[nt][1] *= al0;
            O[nt][2] *= al1; O[nt][3] *= al1;
        }

        // O += P * (Vh + Vl), P in fp16 hi only
#pragma unroll
        for (int kk = 0; kk < 4; ++kk) {
            uint32_t ph[4];
            ph[0] = pack2h(S[2 * kk][0],     S[2 * kk][1]);
            ph[1] = pack2h(S[2 * kk][2],     S[2 * kk][3]);
            ph[2] = pack2h(S[2 * kk + 1][0], S[2 * kk + 1][1]);
            ph[3] = pack2h(S[2 * kk + 1][2], S[2 * kk + 1][3]);
            int vrow = (kk << 4) + vrit;
#pragma unroll
            for (int p = 0; p < 4; ++p) {
                uint32_t vo = (uint32_t)(vrow * 128 + ((((p << 1) | v_u) ^ (vrow & 7)) << 4));
                uint32_t vh[4], vl[4];
                ldsm4t(vh, sb + 32768 + vo);
                ldsm4t(vl, sb + 40960 + vo);
                mma_f16(O[2 * p],     ph, vh);
                mma_f16(O[2 * p],     ph, vl);
                mma_f16(O[2 * p + 1], ph, vh + 2);
                mma_f16(O[2 * p + 1], ph, vl + 2);
            }
        }
    }

    l0 += __shfl_xor_sync(0xffffffffu, l0, 1);
    l0 += __shfl_xor_sync(0xffffffffu, l0, 2);
    l1 += __shfl_xor_sync(0xffffffffu, l1, 1);
    l1 += __shfl_xor_sync(0xffffffffu, l1, 2);
    const float i0 = 1.0f / l0, i1 = 1.0f / l1;
    const int row0 = qb + wid * 16 + r, row1 = row0 + 8;
#pragma unroll
    for (int nt = 0; nt < 8; ++nt) {
        int col = h * HDD + 8 * nt + 2 * c;
        size_t idx0 = ((size_t)b * TT + row0) * CC + col;
        size_t idx1 = ((size_t)b * TT + row1) * CC + col;
        *(uint32_t*)&ohi[idx0] = pack2h(O[nt][0] * i0, O[nt][1] * i0);
        *(uint32_t*)&ohi[idx1] = pack2h(O[nt][2] * i1, O[nt][3] * i1);
    }
}

// ---------------- LayerNorm + residual ----------------
__device__ __forceinline__ float block_sum(float v, float* red) {
    const int lane = threadIdx.x & 31, w = threadIdx.x >> 5;
#pragma unroll
    for (int o = 16; o; o >>= 1) v += __shfl_xor_sync(0xffffffffu, v, o);
    if (lane == 0) red[w] = v;
    __syncthreads();
    if (w == 0) {
        float s = (lane < 8) ? red[lane] : 0.0f;
#pragma unroll
        for (int o = 4; o; o >>= 1) s += __shfl_xor_sync(0xffffffffu, s, o);
        if (lane == 0) red[0] = s;
    }
    __syncthreads();
    float rr = red[0];
    __syncthreads();
    return rr;
}

template<bool SPLIT>
__global__ void __launch_bounds__(256)
ln_res_kernel(const float* __restrict__ res, const float* __restrict__ y,
              const float* __restrict__ g, const float* __restrict__ be,
              float* __restrict__ out, __half* __restrict__ ohi)
{
    __shared__ float red[8];
    const int row = blockIdx.x;
    const int t = threadIdx.x;
    const float* yr = y + (size_t)row * CC;

    float v[4];
    float s = 0.0f;
#pragma unroll
    for (int i = 0; i < 4; ++i) { v[i] = yr[t + i * 256]; s += v[i]; }
    const float mean = block_sum(s, red) * (1.0f / CC);

    float sq = 0.0f;
#pragma unroll
    for (int i = 0; i < 4; ++i) { float d = v[i] - mean; sq += d * d; }
    const float var = block_sum(sq, red) * (1.0f / CC);
    const float rstd = rsqrtf(var + 1e-5f);

    const float* rr = res + (size_t)row * CC;
    float* orow = out + (size_t)row * CC;
#pragma unroll
    for (int i = 0; i < 4; ++i) {
        int cix = t + i * 256;
        float o = rr[cix] + (v[i] - mean) * rstd * g[cix] + be[cix];
        orow[cix] = o;
        if (SPLIT) ohi[(size_t)row * CC + cix] = __float2half_rn(o);
    }
}

// ---------------- launch ----------------
extern "C" void kernel_launch(void* const* d_in, const int* in_sizes, int n_in,
                              void* d_out, int out_size)
{
    const float* x      = (const float*)d_in[0];
    const float* w_attn = (const float*)d_in[1];
    const float* b_attn = (const float*)d_in[2];
    const float* wa1    = (const float*)d_in[3];
    const float* ba1    = (const float*)d_in[4];
    const float* wa2    = (const float*)d_in[5];
    const float* ba2    = (const float*)d_in[6];
    const float* g1     = (const float*)d_in[7];
    const float* be1    = (const float*)d_in[8];
    const float* wf1    = (const float*)d_in[9];
    const float* bf1    = (const float*)d_in[10];
    const float* wf2    = (const float*)d_in[11];
    const float* bf2    = (const float*)d_in[12];
    const float* g2     = (const float*)d_in[13];
    const float* be2    = (const float*)d_in[14];
    float* out = (float*)d_out;

    float *x1, *y;
    cudaGetSymbolAddress((void**)&x1, g_x1);
    cudaGetSymbolAddress((void**)&y,  g_y);

    __half *wqkv_hi, *wqkv_lo, *wa1_hi, *wa1_lo, *wa2_hi,
           *wf1_hi, *wf1_lo, *wf2_hi, *ahi, *hhi, *qkvh, *qkvl;
    cudaGetSymbolAddress((void**)&wqkv_hi, g_wqkv_hi);
    cudaGetSymbolAddress((void**)&wqkv_lo, g_wqkv_lo);
    cudaGetSymbolAddress((void**)&wa1_hi,  g_wa1_hi);
    cudaGetSymbolAddress((void**)&wa1_lo,  g_wa1_lo);
    cudaGetSymbolAddress((void**)&wa2_hi,  g_wa2_hi);
    cudaGetSymbolAddress((void**)&wf1_hi,  g_wf1_hi);
    cudaGetSymbolAddress((void**)&wf1_lo,  g_wf1_lo);
    cudaGetSymbolAddress((void**)&wf2_hi,  g_wf2_hi);
    cudaGetSymbolAddress((void**)&ahi,     g_ahi);
    cudaGetSymbolAddress((void**)&hhi,     g_hhi);
    cudaGetSymbolAddress((void**)&qkvh,    g_qkvh);
    cudaGetSymbolAddress((void**)&qkvl,    g_qkvl);

    cudaFuncSetAttribute(attn_mma_kernel, cudaFuncAttributeMaxDynamicSharedMemorySize, ASMEM);
    cudaFuncSetAttribute((gemm_mma_kernel<2, 2>), cudaFuncAttributeMaxDynamicSharedMemorySize, GS2);
    cudaFuncSetAttribute((gemm_mma_kernel<1, 2>), cudaFuncAttributeMaxDynamicSharedMemorySize, GS2);
    cudaFuncSetAttribute((gemm_mma_kernel<0, 1>), cudaFuncAttributeMaxDynamicSharedMemorySize, GS1);

    // all conversions (5 weights + x) in one launch
    cvt_all_kernel<<<CVT_BLOCKS, 256>>>(
        w_attn, wqkv_hi, wqkv_lo,
        wa1, wa1_hi, wa1_lo,
        wa2, wa2_hi,
        wf1, wf1_hi, wf1_lo,
        wf2, wf2_hi,
        x, ahi);

    // 1) qkv = x @ w_attn + b_attn  (2-pass, hi+lo out)
    gemm_mma_kernel<2, 2><<<dim3(C3 / 128, MTOK / 128), 256, GS2>>>(
        ahi, wqkv_hi, wqkv_lo, b_attn, nullptr, qkvh, qkvl, C3, CC);
    // 2) attention -> hi-only att
    attn_mma_kernel<<<dim3(TT / 64, NHH, BB), 128, ASMEM>>>(qkvh, qkvl, ahi);
    // 3) h = gelu(att @ wa1 + ba1)  (2-pass)
    gemm_mma_kernel<1, 2><<<dim3(C4 / 128, MTOK / 128), 256, GS2>>>(
        ahi, wa1_hi, wa1_lo, ba1, nullptr, hhi, nullptr, C4, CC);
    // 4) y = h @ wa2 + ba2  (1-pass)
    gemm_mma_kernel<0, 1><<<dim3(CC / 128, MTOK / 128), 256, GS1>>>(
        hhi, wa2_hi, nullptr, ba2, y, nullptr, nullptr, CC, C4);
    // 5) x1 = x + ln(y); emit fp16 x1 hi
    ln_res_kernel<true><<<MTOK, 256>>>(x, y, g1, be1, x1, ahi);
    // 6) h = gelu(x1 @ wf1 + bf1)  (2-pass)
    gemm_mma_kernel<1, 2><<<dim3(C4 / 128, MTOK / 128), 256, GS2>>>(
        ahi, wf1_hi, wf1_lo, bf1, nullptr, hhi, nullptr, C4, CC);
    // 7) y = h @ wf2 + bf2  (1-pass)
    gemm_mma_kernel<0, 1><<<dim3(CC / 128, MTOK / 128), 256, GS1>>>(
        hhi, wf2_hi, nullptr, bf2, y, nullptr, nullptr, CC, C4);
    // 8) out = x1 + ln(y)
    ln_res_kernel<false><<<MTOK, 256>>>(x1, y, g2, be2, out, nullptr);
}

// round 11
// speedup vs baseline: 1.9796x; 1.1043x over previous
#include <cuda_runtime.h>
#include <cuda_fp16.h>
#include <math.h>
#include <stdint.h>

// Problem dims (fixed)
#define BB 2
#define TT 2048
#define CC 1024
#define NHH 16
#define HDD 64
#define MTOK 4096          // B*T
#define C3 3072
#define C4 4096

// ---------------- scratch (no allocation allowed) ----------------
__device__ float g_x1 [(size_t)MTOK * CC];
__device__ float g_y  [(size_t)MTOK * CC];

// fp16 split weights, transposed to [N][K] (lo unused for wa2/wf2)
__device__ __half g_wqkv_hi[(size_t)C3 * CC], g_wqkv_lo[(size_t)C3 * CC];
__device__ __half g_wa1_hi [(size_t)C4 * CC], g_wa1_lo [(size_t)C4 * CC];
__device__ __half g_wa2_hi [(size_t)CC * C4];
__device__ __half g_wf1_hi [(size_t)C4 * CC], g_wf1_lo [(size_t)C4 * CC];
__device__ __half g_wf2_hi [(size_t)CC * C4];
// fp16 activations
__device__ __half g_ahi [(size_t)MTOK * CC];
__device__ __half g_hhi [(size_t)MTOK * C4];
__device__ __half g_qkvh[(size_t)MTOK * C3], g_qkvl[(size_t)MTOK * C3];

__device__ __forceinline__ float gelu_f(float v) {
    return 0.5f * v * (1.0f + erff(v * 0.7071067811865475f));
}

// ======================= PTX helpers =======================
__device__ __forceinline__ uint32_t smem_u32(const void* p) {
    uint32_t a;
    asm("{ .reg .u64 t; cvta.to.shared.u64 t, %1; cvt.u32.u64 %0, t; }" : "=r"(a) : "l"(p));
    return a;
}
__device__ __forceinline__ void ldsm4(uint32_t* r, uint32_t addr) {
    asm volatile("ldmatrix.sync.aligned.m8n8.x4.shared.b16 {%0,%1,%2,%3}, [%4];"
                 : "=r"(r[0]), "=r"(r[1]), "=r"(r[2]), "=r"(r[3]) : "r"(addr));
}
__device__ __forceinline__ void ldsm4t(uint32_t* r, uint32_t addr) {
    asm volatile("ldmatrix.sync.aligned.m8n8.x4.trans.shared.b16 {%0,%1,%2,%3}, [%4];"
                 : "=r"(r[0]), "=r"(r[1]), "=r"(r[2]), "=r"(r[3]) : "r"(addr));
}
__device__ __forceinline__ void mma_f16(float* d, const uint32_t* a, const uint32_t* b) {
    asm volatile(
        "mma.sync.aligned.m16n8k16.row.col.f32.f16.f16.f32 "
        "{%0,%1,%2,%3}, {%4,%5,%6,%7}, {%8,%9}, {%0,%1,%2,%3};"
        : "+f"(d[0]), "+f"(d[1]), "+f"(d[2]), "+f"(d[3])
        : "r"(a[0]), "r"(a[1]), "r"(a[2]), "r"(a[3]), "r"(b[0]), "r"(b[1]));
}
__device__ __forceinline__ void cp16(uint32_t dst, const void* src) {
    unsigned long long g = __cvta_generic_to_global(src);
    asm volatile("cp.async.ca.shared.global [%0], [%1], 16;" :: "r"(dst), "l"(g) : "memory");
}
__device__ __forceinline__ void cp_commit() {
    asm volatile("cp.async.commit_group;" ::: "memory");
}
template<int N>
__device__ __forceinline__ void cp_wait() {
    asm volatile("cp.async.wait_group %0;" :: "n"(N) : "memory");
}
__device__ __forceinline__ void split2(float a, float b, uint32_t& hi, uint32_t& lo) {
    __half ha = __float2half_rn(a), hb = __float2half_rn(b);
    __half2 H = __halves2half2(ha, hb);
    __half2 L = __halves2half2(__float2half_rn(a - __half2float(ha)),
                               __float2half_rn(b - __half2float(hb)));
    hi = *(uint32_t*)&H;
    lo = *(uint32_t*)&L;
}
__device__ __forceinline__ uint32_t pack2h(float a, float b) {
    __half2 H = __halves2half2(__float2half_rn(a), __float2half_rn(b));
    return *(uint32_t*)&H;
}

// ======================= fused conversion kernel =======================
#define CVT_BLOCKS (19456 + 4096)
__global__ void __launch_bounds__(256)
cvt_all_kernel(const float* __restrict__ W0, __half* __restrict__ h0, __half* __restrict__ l0,
               const float* __restrict__ W1, __half* __restrict__ h1, __half* __restrict__ l1,
               const float* __restrict__ W2, __half* __restrict__ h2,
               const float* __restrict__ W3, __half* __restrict__ h3, __half* __restrict__ l3,
               const float* __restrict__ W4, __half* __restrict__ h4,
               const float* __restrict__ x,  __half* __restrict__ xh)
{
    const int bid = blockIdx.x;
    if (bid >= 19456) {
        int i = ((bid - 19456) * 256 + threadIdx.x) * 4;
        float4 v = *(const float4*)(x + i);
        *(uint32_t*)(xh + i)     = pack2h(v.x, v.y);
        *(uint32_t*)(xh + i + 2) = pack2h(v.z, v.w);
        return;
    }
    __shared__ float tile[32][33];
    const float* W; __half* hi; __half* lo; int K, N, local;
    if      (bid < 3072)  { W = W0; hi = h0; lo = l0;      K = CC; N = C3; local = bid; }
    else if (bid < 7168)  { W = W1; hi = h1; lo = l1;      K = CC; N = C4; local = bid - 3072; }
    else if (bid < 11264) { W = W2; hi = h2; lo = nullptr; K = C4; N = CC; local = bid - 7168; }
    else if (bid < 15360) { W = W3; hi = h3; lo = l3;      K = CC; N = C4; local = bid - 11264; }
    else                  { W = W4; hi = h4; lo = nullptr; K = C4; N = CC; local = bid - 15360; }
    const int nb = N >> 5;
    const int n0 = (local % nb) * 32, k0 = (local / nb) * 32;
    const int tx = threadIdx.x & 31, ty = threadIdx.x >> 5;
#pragma unroll
    for (int r = 0; r < 4; ++r)
        tile[ty + r * 8][tx] = W[(size_t)(k0 + ty + r * 8) * N + n0 + tx];
    __syncthreads();
#pragma unroll
    for (int r = 0; r < 4; ++r) {
        int n = n0 + ty + r * 8;
        float v = tile[tx][ty + r * 8];
        __half h = __float2half_rn(v);
        hi[(size_t)n * K + k0 + tx] = h;
        if (lo) lo[(size_t)n * K + k0 + tx] = __float2half_rn(v - __half2float(h));
    }
}

// 128B-row swizzle (8 16B units per row, 8-way xor)
__device__ __forceinline__ uint32_t asw(int row, int u) {
    return (uint32_t)(row * 128 + ((u ^ (row & 7)) << 4));
}

// ======================= HMMA fp16 GEMM, CTA 128x128, BK=64 =======================
// 8 warps (2x4), warp tile 64x32, 2-stage cp.async double buffer, 2 CTAs/SM,
// ONE __syncthreads per 64-wide K-chunk (128 MMAs per barrier at PASSES=2).
// PASSES=2: D = Ah*Bh + Ah*Bl.  PASSES=1: D = Ah*Bh.
// Stage: A 16K | Bhi 16K | [Blo 16K]
#define GS2 (2 * 49152)
#define GS1 (2 * 32768)
template<int MODE, int PASSES>
__global__ void __launch_bounds__(256, 2)
gemm_mma_kernel(const __half* __restrict__ Ahi,
                const __half* __restrict__ Bhi, const __half* __restrict__ Blo,
                const float* __restrict__ bias, float* __restrict__ Cf,
                __half* __restrict__ Chi, __half* __restrict__ Clo,
                int N, int K)
{
    constexpr uint32_t STAGE   = (PASSES == 2) ? 49152u : 32768u;
    constexpr uint32_t BHI_OFF = 16384u;
    constexpr uint32_t BLO_OFF = 32768u;
    constexpr int ITER = (PASSES == 2) ? 12 : 8;   // 16B units per thread per stage

    extern __shared__ char smem[];
    const uint32_t sb = smem_u32(smem);

    const int t = threadIdx.x;
    const int wid = t >> 5, lane = t & 31;
    const int bm = blockIdx.y * 128;
    const int bn = blockIdx.x * 128;
    const int wm = wid >> 2, wn = wid & 3;

    float acc[4][4][4];
#pragma unroll
    for (int i = 0; i < 4; ++i)
#pragma unroll
        for (int j = 0; j < 4; ++j)
#pragma unroll
            for (int k = 0; k < 4; ++k) acc[i][j][k] = 0.0f;

    const int nc = K >> 6;   // 64-wide chunks

    const int g  = lane >> 3, lr = lane & 7;
    const int a_rit = lr + (g & 1) * 8, a_kqo = g >> 1;
    const int b_rit = lr + (g >> 1) * 8, b_kqo = g & 1;

    uint32_t aA[4], aBh[2], aBl[2];
    int aRsw[4], bRsw[2];
#pragma unroll
    for (int mt = 0; mt < 4; ++mt) {
        int row = wm * 64 + mt * 16 + a_rit;
        aA[mt] = sb + row * 128;
        aRsw[mt] = row & 7;
    }
#pragma unroll
    for (int p = 0; p < 2; ++p) {
        int row = wn * 32 + p * 16 + b_rit;
        aBh[p] = sb + BHI_OFF + row * 128;
        aBl[p] = sb + BLO_OFF + row * 128;
        bRsw[p] = row & 7;
    }

    // per stage: A 1024 units, Bhi 1024, [Blo 1024]
    auto issue = [&](int c, int s) {
        const uint32_t st = sb + s * STAGE;
        const int kb = c * 64;
#pragma unroll
        for (int i = 0; i < ITER; ++i) {
            int u = t + i * 256;
            int arr = u >> 10, v = u & 1023, row = v >> 3, kq = v & 7;
            const __half* src;
            if      (arr == 0) src = Ahi + (size_t)(bm + row) * K + kb + kq * 8;
            else if (arr == 1) src = Bhi + (size_t)(bn + row) * K + kb + kq * 8;
            else               src = Blo + (size_t)(bn + row) * K + kb + kq * 8;
            cp16(st + arr * 16384u + asw(row, kq), src);
        }
        cp_commit();
    };

    issue(0, 0);
    int s = 0;
    for (int c = 0; c < nc; ++c) {
        cp_wait<0>();            // stage s data landed (only group outstanding)
        __syncthreads();         // visible to all; all warps done reading stage s^1
        if (c + 1 < nc) issue(c + 1, s ^ 1);

        const uint32_t stoff = (uint32_t)(s * STAGE);
#pragma unroll
        for (int kk = 0; kk < 4; ++kk) {
            uint32_t ah[4][4], bh[4][2], bl[4][2];
#pragma unroll
            for (int mt = 0; mt < 4; ++mt) {
                uint32_t o = (uint32_t)(((((kk << 1) | a_kqo) ^ aRsw[mt]) << 4));
                ldsm4(ah[mt], aA[mt] + stoff + o);
            }
#pragma unroll
            for (int p = 0; p < 2; ++p) {
                uint32_t r[4];
                uint32_t o = (uint32_t)(((((kk << 1) | b_kqo) ^ bRsw[p]) << 4));
                ldsm4(r, aBh[p] + stoff + o);
                bh[2 * p][0] = r[0]; bh[2 * p][1] = r[1];
                bh[2 * p + 1][0] = r[2]; bh[2 * p + 1][1] = r[3];
                if (PASSES == 2) {
                    ldsm4(r, aBl[p] + stoff + o);
                    bl[2 * p][0] = r[0]; bl[2 * p][1] = r[1];
                    bl[2 * p + 1][0] = r[2]; bl[2 * p + 1][1] = r[3];
                }
            }
#pragma unroll
            for (int mt = 0; mt < 4; ++mt)
#pragma unroll
                for (int nt = 0; nt < 4; ++nt) {
                    mma_f16(acc[mt][nt], ah[mt], bh[nt]);
                    if (PASSES == 2) mma_f16(acc[mt][nt], ah[mt], bl[nt]);
                }
        }
        s ^= 1;
    }

    const int mrow = bm + wm * 64;
    const int ncol = bn + wn * 32;
#pragma unroll
    for (int mt = 0; mt < 4; ++mt) {
#pragma unroll
        for (int nt = 0; nt < 4; ++nt) {
            float* d = acc[mt][nt];
            int r0 = mrow + mt * 16 + (lane >> 2);
            int cix = ncol + nt * 8 + (lane & 3) * 2;
            float b0 = bias[cix], b1 = bias[cix + 1];
            float v00 = d[0] + b0, v01 = d[1] + b1;
            float v10 = d[2] + b0, v11 = d[3] + b1;
            if (MODE == 0) {
                float2 p0{v00, v01}, p1{v10, v11};
                *(float2*)&Cf[(size_t)r0 * N + cix]       = p0;
                *(float2*)&Cf[(size_t)(r0 + 8) * N + cix] = p1;
            } else if (MODE == 1) {
                v00 = gelu_f(v00); v01 = gelu_f(v01);
                v10 = gelu_f(v10); v11 = gelu_f(v11);
                *(uint32_t*)&Chi[(size_t)r0 * N + cix]       = pack2h(v00, v01);
                *(uint32_t*)&Chi[(size_t)(r0 + 8) * N + cix] = pack2h(v10, v11);
            } else {
                uint32_t h0, l0, h1, l1;
                split2(v00, v01, h0, l0);
                split2(v10, v11, h1, l1);
                *(uint32_t*)&Chi[(size_t)r0 * N + cix]       = h0;
                *(uint32_t*)&Clo[(size_t)r0 * N + cix]       = l0;
                *(uint32_t*)&Chi[(size_t)(r0 + 8) * N + cix] = h1;
                *(uint32_t*)&Clo[(size_t)(r0 + 8) * N + cix] = l1;
            }
        }
    }
}

// ======================= HMMA causal attention (FA2-style) =======================
// QK: 3-pass split fp16.  PV: 2-pass (P hi-only x (Vh + Vl)).
#define ASMEM 49152

__global__ void __launch_bounds__(128, 3)
attn_mma_kernel(const __half* __restrict__ qkvh, const __half* __restrict__ qkvl,
                __half* __restrict__ ohi)
{
    extern __shared__ char asmem[];
    const uint32_t sb = smem_u32(asmem);

    const int t = threadIdx.x, wid = t >> 5, lane = t & 31;
    const int qi = gridDim.x - 1 - blockIdx.x;   // heavy tiles first
    const int qb = qi * 64;
    const int h  = blockIdx.y, b = blockIdx.z;

    const __half* Kh_g = qkvh + (size_t)b * TT * C3 + h * HDD;
    const __half* Kl_g = qkvl + (size_t)b * TT * C3 + h * HDD;
    const __half* Qh_g = Kh_g + CC;
    const __half* Ql_g = Kl_g + CC;
    const __half* Vh_g = Kh_g + 2 * CC;
    const __half* Vl_g = Kl_g + 2 * CC;

#pragma unroll
    for (int i = 0; i < 8; ++i) {
        int uu = t + i * 128;
        int arr = uu >> 9, v = uu & 511, row = v >> 3, u = v & 7;
        const __half* src = (arr ? Ql_g : Qh_g) + (size_t)(qb + row) * C3 + u * 8;
        cp16(sb + arr * 8192 + asw(row, u), src);
    }
    cp_commit();

    const int g = lane >> 3, lr = lane & 7;
    const int r = lane >> 2, c = lane & 3;
    const int qrow = wid * 16 + lr + ((g & 1) << 3);
    const int a_u  = g >> 1;
    const int krit = lr + ((g >> 1) << 3);
    const int b_u  = g & 1;
    const int vrit = lr + ((g & 1) << 3);
    const int v_u  = g >> 1;

    float O[8][4];
#pragma unroll
    for (int i = 0; i < 8; ++i)
#pragma unroll
        for (int j = 0; j < 4; ++j) O[i][j] = 0.0f;
    float m0 = -1e30f, m1 = -1e30f, l0 = 0.0f, l1 = 0.0f;

    const int ntiles = qi + 1;
    for (int kt = 0; kt < ntiles; ++kt) {
        const int kb = kt * 64;
        __syncthreads();
#pragma unroll
        for (int i = 0; i < 16; ++i) {
            int uu = t + i * 128;
            int arr = uu >> 9, v = uu & 511, row = v >> 3, u = v & 7;
            const __half* src;
            if      (arr == 0) src = Kh_g + (size_t)(kb + row) * C3 + u * 8;
            else if (arr == 1) src = Kl_g + (size_t)(kb + row) * C3 + u * 8;
            else if (arr == 2) src = Vh_g + (size_t)(kb + row) * C3 + u * 8;
            else               src = Vl_g + (size_t)(kb + row) * C3 + u * 8;
            cp16(sb + 16384 + arr * 8192 + asw(row, u), src);
        }
        cp_commit();
        cp_wait<0>();
        __syncthreads();

        float S[8][4];
#pragma unroll
        for (int i = 0; i < 8; ++i)
#pragma unroll
            for (int j = 0; j < 4; ++j) S[i][j] = 0.0f;

#pragma unroll
        for (int kk = 0; kk < 4; ++kk) {
            uint32_t ah[4], al[4];
            uint32_t aoq = (uint32_t)(qrow * 128 + ((((kk << 1) | a_u) ^ (qrow & 7)) << 4));
            ldsm4(ah, sb + aoq);
            ldsm4(al, sb + 8192 + aoq);
#pragma unroll
            for (int p = 0; p < 4; ++p) {
                int krow = (p << 4) + krit;
                uint32_t ko = (uint32_t)(krow * 128 + ((((kk << 1) | b_u) ^ (krow & 7)) << 4));
                uint32_t bh[4], bl[4];
                ldsm4(bh, sb + 16384 + ko);
                ldsm4(bl, sb + 24576 + ko);
                mma_f16(S[2 * p],     ah, bh);
                mma_f16(S[2 * p],     ah, bl);
                mma_f16(S[2 * p],     al, bh);
                mma_f16(S[2 * p + 1], ah, bh + 2);
                mma_f16(S[2 * p + 1], ah, bl + 2);
                mma_f16(S[2 * p + 1], al, bh + 2);
            }
        }

#pragma unroll
        for (int nt = 0; nt < 8; ++nt)
#pragma unroll
            for (int e = 0; e < 4; ++e) S[nt][e] *= 0.125f;
        if (kt == qi) {
            const int q0 = qb + wid * 16 + r, q1 = q0 + 8;
#pragma unroll
            for (int nt = 0; nt < 8; ++nt) {
                int k0 = kb + 8 * nt + 2 * c;
                if (k0     > q0) S[nt][0] = -1e30f;
                if (k0 + 1 > q0) S[nt][1] = -1e30f;
                if (k0     > q1) S[nt][2] = -1e30f;
                if (k0 + 1 > q1) S[nt][3] = -1e30f;
            }
        }

        float mx0 = -1e30f, mx1 = -1e30f;
#pragma unroll
        for (int nt = 0; nt < 8; ++nt) {
            mx0 = fmaxf(mx0, fmaxf(S[nt][0], S[nt][1]));
            mx1 = fmaxf(mx1, fmaxf(S[nt][2], S[nt][3]));
        }
        mx0 = fmaxf(mx0, __shfl_xor_sync(0xffffffffu, mx0, 1));
        mx0 = fmaxf(mx0, __shfl_xor_sync(0xffffffffu, mx0, 2));
        mx1 = fmaxf(mx1, __shfl_xor_sync(0xffffffffu, mx1, 1));
        mx1 = fmaxf(mx1, __shfl_xor_sync(0xffffffffu, mx1, 2));
        float mn0 = fmaxf(m0, mx0), mn1 = fmaxf(m1, mx1);
        float al0 = __expf(m0 - mn0), al1 = __expf(m1 - mn1);
        m0 = mn0; m1 = mn1;

        float s0 = 0.0f, s1 = 0.0f;
#pragma unroll
        for (int nt = 0; nt < 8; ++nt) {
            S[nt][0] = __expf(S[nt][0] - mn0);
            S[nt][1] = __expf(S[nt][1] - mn0);
            S[nt][2] = __expf(S[nt][2] - mn1);
            S[nt][3] = __expf(S[nt][3] - mn1);
            s0 += S[nt][0] + S[nt][1];
            s1 += S[nt][2] + S[nt][3];
        }
        l0 = l0 * al0 + s0;
        l1 = l1 * al1 + s1;
#pragma unroll
        for (int nt = 0; nt < 8; ++nt) {
            O[nt][0] *= al0; O[nt][1] *= al0;
            O[nt][2] *= al1; O[nt][3] *= al1;
        }

        // O += P * (Vh + Vl), P in fp16 hi only
#pragma unroll
        for (int kk = 0; kk < 4; ++kk) {
            uint32_t ph[4];
            ph[0] = pack2h(S[2 * kk][0],     S[2 * kk][1]);
            ph[1] = pack2h(S[2 * kk][2],     S[2 * kk][3]);
            ph[2] = pack2h(S[2 * kk + 1][0], S[2 * kk + 1][1]);
            ph[3] = pack2h(S[2 * kk + 1][2], S[2 * kk + 1][3]);
            int vrow = (kk << 4) + vrit;
#pragma unroll
            for (int p = 0; p < 4; ++p) {
                uint32_t vo = (uint32_t)(vrow * 128 + ((((p << 1) | v_u) ^ (vrow & 7)) << 4));
                uint32_t vh[4], vl[4];
                ldsm4t(vh, sb + 32768 + vo);
                ldsm4t(vl, sb + 40960 + vo);
                mma_f16(O[2 * p],     ph, vh);
                mma_f16(O[2 * p],     ph, vl);
                mma_f16(O[2 * p + 1], ph, vh + 2);
                mma_f16(O[2 * p + 1], ph, vl + 2);
            }
        }
    }

    l0 += __shfl_xor_sync(0xffffffffu, l0, 1);
    l0 += __shfl_xor_sync(0xffffffffu, l0, 2);
    l1 += __shfl_xor_sync(0xffffffffu, l1, 1);
    l1 += __shfl_xor_sync(0xffffffffu, l1, 2);
    const float i0 = 1.0f / l0, i1 = 1.0f / l1;
    const int row0 = qb + wid * 16 + r, row1 = row0 + 8;
#pragma unroll
    for (int nt = 0; nt < 8; ++nt) {
        int col = h * HDD + 8 * nt + 2 * c;
        size_t idx0 = ((size_t)b * TT + row0) * CC + col;
        size_t idx1 = ((size_t)b * TT + row1) * CC + col;
        *(uint32_t*)&ohi[idx0] = pack2h(O[nt][0] * i0, O[nt][1] * i0);
        *(uint32_t*)&ohi[idx1] = pack2h(O[nt][2] * i1, O[nt][3] * i1);
    }
}

// ---------------- LayerNorm + residual ----------------
__device__ __forceinline__ float block_sum(float v, float* red) {
    const int lane = threadIdx.x & 31, w = threadIdx.x >> 5;
#pragma unroll
    for (int o = 16; o; o >>= 1) v += __shfl_xor_sync(0xffffffffu, v, o);
    if (lane == 0) red[w] = v;
    __syncthreads();
    if (w == 0) {
        float s = (lane < 8) ? red[lane] : 0.0f;
#pragma unroll
        for (int o = 4; o; o >>= 1) s += __shfl_xor_sync(0xffffffffu, s, o);
        if (lane == 0) red[0] = s;
    }
    __syncthreads();
    float rr = red[0];
    __syncthreads();
    return rr;
}

template<bool SPLIT>
__global__ void __launch_bounds__(256)
ln_res_kernel(const float* __restrict__ res, const float* __restrict__ y,
              const float* __restrict__ g, const float* __restrict__ be,
              float* __restrict__ out, __half* __restrict__ ohi)
{
    __shared__ float red[8];
    const int row = blockIdx.x;
    const int t = threadIdx.x;
    const float* yr = y + (size_t)row * CC;

    float v[4];
    float s = 0.0f;
#pragma unroll
    for (int i = 0; i < 4; ++i) { v[i] = yr[t + i * 256]; s += v[i]; }
    const float mean = block_sum(s, red) * (1.0f / CC);

    float sq = 0.0f;
#pragma unroll
    for (int i = 0; i < 4; ++i) { float d = v[i] - mean; sq += d * d; }
    const float var = block_sum(sq, red) * (1.0f / CC);
    const float rstd = rsqrtf(var + 1e-5f);

    const float* rr = res + (size_t)row * CC;
    float* orow = out + (size_t)row * CC;
#pragma unroll
    for (int i = 0; i < 4; ++i) {
        int cix = t + i * 256;
        float o = rr[cix] + (v[i] - mean) * rstd * g[cix] + be[cix];
        orow[cix] = o;
        if (SPLIT) ohi[(size_t)row * CC + cix] = __float2half_rn(o);
    }
}

// ---------------- launch ----------------
extern "C" void kernel_launch(void* const* d_in, const int* in_sizes, int n_in,
                              void* d_out, int out_size)
{
    const float* x      = (const float*)d_in[0];
    const float* w_attn = (const float*)d_in[1];
    const float* b_attn = (const float*)d_in[2];
    const float* wa1    = (const float*)d_in[3];
    const float* ba1    = (const float*)d_in[4];
    const float* wa2    = (const float*)d_in[5];
    const float* ba2    = (const float*)d_in[6];
    const float* g1     = (const float*)d_in[7];
    const float* be1    = (const float*)d_in[8];
    const float* wf1    = (const float*)d_in[9];
    const float* bf1    = (const float*)d_in[10];
    const float* wf2    = (const float*)d_in[11];
    const float* bf2    = (const float*)d_in[12];
    const float* g2     = (const float*)d_in[13];
    const float* be2    = (const float*)d_in[14];
    float* out = (float*)d_out;

    float *x1, *y;
    cudaGetSymbolAddress((void**)&x1, g_x1);
    cudaGetSymbolAddress((void**)&y,  g_y);

    __half *wqkv_hi, *wqkv_lo, *wa1_hi, *wa1_lo, *wa2_hi,
           *wf1_hi, *wf1_lo, *wf2_hi, *ahi, *hhi, *qkvh, *qkvl;
    cudaGetSymbolAddress((void**)&wqkv_hi, g_wqkv_hi);
    cudaGetSymbolAddress((void**)&wqkv_lo, g_wqkv_lo);
    cudaGetSymbolAddress((void**)&wa1_hi,  g_wa1_hi);
    cudaGetSymbolAddress((void**)&wa1_lo,  g_wa1_lo);
    cudaGetSymbolAddress((void**)&wa2_hi,  g_wa2_hi);
    cudaGetSymbolAddress((void**)&wf1_hi,  g_wf1_hi);
    cudaGetSymbolAddress((void**)&wf1_lo,  g_wf1_lo);
    cudaGetSymbolAddress((void**)&wf2_hi,  g_wf2_hi);
    cudaGetSymbolAddress((void**)&ahi,     g_ahi);
    cudaGetSymbolAddress((void**)&hhi,     g_hhi);
    cudaGetSymbolAddress((void**)&qkvh,    g_qkvh);
    cudaGetSymbolAddress((void**)&qkvl,    g_qkvl);

    cudaFuncSetAttribute(attn_mma_kernel, cudaFuncAttributeMaxDynamicSharedMemorySize, ASMEM);
    cudaFuncSetAttribute((gemm_mma_kernel<2, 2>), cudaFuncAttributeMaxDynamicSharedMemorySize, GS2);
    cudaFuncSetAttribute((gemm_mma_kernel<1, 2>), cudaFuncAttributeMaxDynamicSharedMemorySize, GS2);
    cudaFuncSetAttribute((gemm_mma_kernel<0, 1>), cudaFuncAttributeMaxDynamicSharedMemorySize, GS1);

    // all conversions (5 weights + x) in one launch
    cvt_all_kernel<<<CVT_BLOCKS, 256>>>(
        w_attn, wqkv_hi, wqkv_lo,
        wa1, wa1_hi, wa1_lo,
        wa2, wa2_hi,
        wf1, wf1_hi, wf1_lo,
        wf2, wf2_hi,
        x, ahi);

    // 1) qkv = x @ w_attn + b_attn  (2-pass, hi+lo out)
    gemm_mma_kernel<2, 2><<<dim3(C3 / 128, MTOK / 128), 256, GS2>>>(
        ahi, wqkv_hi, wqkv_lo, b_attn, nullptr, qkvh, qkvl, C3, CC);
    // 2) attention -> hi-only att
    attn_mma_kernel<<<dim3(TT / 64, NHH, BB), 128, ASMEM>>>(qkvh, qkvl, ahi);
    // 3) h = gelu(att @ wa1 + ba1)  (2-pass)
    gemm_mma_kernel<1, 2><<<dim3(C4 / 128, MTOK / 128), 256, GS2>>>(
        ahi, wa1_hi, wa1_lo, ba1, nullptr, hhi, nullptr, C4, CC);
    // 4) y = h @ wa2 + ba2  (1-pass)
    gemm_mma_kernel<0, 1><<<dim3(CC / 128, MTOK / 128), 256, GS1>>>(
        hhi, wa2_hi, nullptr, ba2, y, nullptr, nullptr, CC, C4);
    // 5) x1 = x + ln(y); emit fp16 x1 hi
    ln_res_kernel<true><<<MTOK, 256>>>(x, y, g1, be1, x1, ahi);
    // 6) h = gelu(x1 @ wf1 + bf1)  (2-pass)
    gemm_mma_kernel<1, 2><<<dim3(C4 / 128, MTOK / 128), 256, GS2>>>(
        ahi, wf1_hi, wf1_lo, bf1, nullptr, hhi, nullptr, C4, CC);
    // 7) y = h @ wf2 + bf2  (1-pass)
    gemm_mma_kernel<0, 1><<<dim3(CC / 128, MTOK / 128), 256, GS1>>>(
        hhi, wf2_hi, nullptr, bf2, y, nullptr, nullptr, CC, C4);
    // 8) out = x1 + ln(y)
    ln_res_kernel<false><<<MTOK, 256>>>(x1, y, g2, be2, out, nullptr);
}

// round 12
// speedup vs baseline: 2.3648x; 1.1946x over previous
#include <cuda_runtime.h>
#include <cuda_fp16.h>
#include <math.h>
#include <stdint.h>

// Problem dims (fixed)
#define BB 2
#define TT 2048
#define CC 1024
#define NHH 16
#define HDD 64
#define MTOK 4096          // B*T
#define C3 3072
#define C4 4096

// ---------------- scratch (no allocation allowed) ----------------
__device__ float g_x1 [(size_t)MTOK * CC];
__device__ float g_y  [(size_t)MTOK * CC];

// fp16 weights, transposed to [N][K] (lo only for wqkv)
__device__ __half g_wqkv_hi[(size_t)C3 * CC], g_wqkv_lo[(size_t)C3 * CC];
__device__ __half g_wa1_hi [(size_t)C4 * CC];
__device__ __half g_wa2_hi [(size_t)CC * C4];
__device__ __half g_wf1_hi [(size_t)C4 * CC];
__device__ __half g_wf2_hi [(size_t)CC * C4];
// fp16 activations
__device__ __half g_ahi [(size_t)MTOK * CC];
__device__ __half g_hhi [(size_t)MTOK * C4];
__device__ __half g_qkvh[(size_t)MTOK * C3], g_qkvl[(size_t)MTOK * C3];

__device__ __forceinline__ float gelu_f(float v) {
    return 0.5f * v * (1.0f + erff(v * 0.7071067811865475f));
}

// ======================= PTX helpers =======================
__device__ __forceinline__ uint32_t smem_u32(const void* p) {
    uint32_t a;
    asm("{ .reg .u64 t; cvta.to.shared.u64 t, %1; cvt.u32.u64 %0, t; }" : "=r"(a) : "l"(p));
    return a;
}
__device__ __forceinline__ void ldsm4(uint32_t* r, uint32_t addr) {
    asm volatile("ldmatrix.sync.aligned.m8n8.x4.shared.b16 {%0,%1,%2,%3}, [%4];"
                 : "=r"(r[0]), "=r"(r[1]), "=r"(r[2]), "=r"(r[3]) : "r"(addr));
}
__device__ __forceinline__ void ldsm4t(uint32_t* r, uint32_t addr) {
    asm volatile("ldmatrix.sync.aligned.m8n8.x4.trans.shared.b16 {%0,%1,%2,%3}, [%4];"
                 : "=r"(r[0]), "=r"(r[1]), "=r"(r[2]), "=r"(r[3]) : "r"(addr));
}
__device__ __forceinline__ void mma_f16(float* d, const uint32_t* a, const uint32_t* b) {
    asm volatile(
        "mma.sync.aligned.m16n8k16.row.col.f32.f16.f16.f32 "
        "{%0,%1,%2,%3}, {%4,%5,%6,%7}, {%8,%9}, {%0,%1,%2,%3};"
        : "+f"(d[0]), "+f"(d[1]), "+f"(d[2]), "+f"(d[3])
        : "r"(a[0]), "r"(a[1]), "r"(a[2]), "r"(a[3]), "r"(b[0]), "r"(b[1]));
}
__device__ __forceinline__ void cp16(uint32_t dst, const void* src) {
    unsigned long long g = __cvta_generic_to_global(src);
    asm volatile("cp.async.ca.shared.global [%0], [%1], 16;" :: "r"(dst), "l"(g) : "memory");
}
__device__ __forceinline__ void cp_commit() {
    asm volatile("cp.async.commit_group;" ::: "memory");
}
template<int N>
__device__ __forceinline__ void cp_wait() {
    asm volatile("cp.async.wait_group %0;" :: "n"(N) : "memory");
}
__device__ __forceinline__ void split2(float a, float b, uint32_t& hi, uint32_t& lo) {
    __half ha = __float2half_rn(a), hb = __float2half_rn(b);
    __half2 H = __halves2half2(ha, hb);
    __half2 L = __halves2half2(__float2half_rn(a - __half2float(ha)),
                               __float2half_rn(b - __half2float(hb)));
    hi = *(uint32_t*)&H;
    lo = *(uint32_t*)&L;
}
__device__ __forceinline__ uint32_t pack2h(float a, float b) {
    __half2 H = __halves2half2(__float2half_rn(a), __float2half_rn(b));
    return *(uint32_t*)&H;
}

// ======================= fused conversion kernel =======================
#define CVT_BLOCKS (19456 + 4096)
__global__ void __launch_bounds__(256)
cvt_all_kernel(const float* __restrict__ W0, __half* __restrict__ h0, __half* __restrict__ l0,
               const float* __restrict__ W1, __half* __restrict__ h1,
               const float* __restrict__ W2, __half* __restrict__ h2,
               const float* __restrict__ W3, __half* __restrict__ h3,
               const float* __restrict__ W4, __half* __restrict__ h4,
               const float* __restrict__ x,  __half* __restrict__ xh)
{
    const int bid = blockIdx.x;
    if (bid >= 19456) {
        int i = ((bid - 19456) * 256 + threadIdx.x) * 4;
        float4 v = *(const float4*)(x + i);
        *(uint32_t*)(xh + i)     = pack2h(v.x, v.y);
        *(uint32_t*)(xh + i + 2) = pack2h(v.z, v.w);
        return;
    }
    __shared__ float tile[32][33];
    const float* W; __half* hi; __half* lo; int K, N, local;
    if      (bid < 3072)  { W = W0; hi = h0; lo = l0;      K = CC; N = C3; local = bid; }
    else if (bid < 7168)  { W = W1; hi = h1; lo = nullptr; K = CC; N = C4; local = bid - 3072; }
    else if (bid < 11264) { W = W2; hi = h2; lo = nullptr; K = C4; N = CC; local = bid - 7168; }
    else if (bid < 15360) { W = W3; hi = h3; lo = nullptr; K = CC; N = C4; local = bid - 11264; }
    else                  { W = W4; hi = h4; lo = nullptr; K = C4; N = CC; local = bid - 15360; }
    const int nb = N >> 5;
    const int n0 = (local % nb) * 32, k0 = (local / nb) * 32;
    const int tx = threadIdx.x & 31, ty = threadIdx.x >> 5;
#pragma unroll
    for (int r = 0; r < 4; ++r)
        tile[ty + r * 8][tx] = W[(size_t)(k0 + ty + r * 8) * N + n0 + tx];
    __syncthreads();
#pragma unroll
    for (int r = 0; r < 4; ++r) {
        int n = n0 + ty + r * 8;
        float v = tile[tx][ty + r * 8];
        __half h = __float2half_rn(v);
        hi[(size_t)n * K + k0 + tx] = h;
        if (lo) lo[(size_t)n * K + k0 + tx] = __float2half_rn(v - __half2float(h));
    }
}

// 128B-row swizzle (8 16B units per row, 8-way xor)
__device__ __forceinline__ uint32_t asw(int row, int u) {
    return (uint32_t)(row * 128 + ((u ^ (row & 7)) << 4));
}

// ======================= HMMA fp16 GEMM, CTA 128x128, BK=64 =======================
// 8 warps (2x4), warp tile 64x32, 2-stage cp.async double buffer, 2 CTAs/SM,
// ONE __syncthreads per 64-wide K-chunk.
// PASSES=2: D = Ah*Bh + Ah*Bl.  PASSES=1: D = Ah*Bh.
#define GS2 (2 * 49152)
#define GS1 (2 * 32768)
template<int MODE, int PASSES>
__global__ void __launch_bounds__(256, 2)
gemm_mma_kernel(const __half* __restrict__ Ahi,
                const __half* __restrict__ Bhi, const __half* __restrict__ Blo,
                const float* __restrict__ bias, float* __restrict__ Cf,
                __half* __restrict__ Chi, __half* __restrict__ Clo,
                int N, int K)
{
    constexpr uint32_t STAGE   = (PASSES == 2) ? 49152u : 32768u;
    constexpr uint32_t BHI_OFF = 16384u;
    constexpr uint32_t BLO_OFF = 32768u;
    constexpr int ITER = (PASSES == 2) ? 12 : 8;

    extern __shared__ char smem[];
    const uint32_t sb = smem_u32(smem);

    const int t = threadIdx.x;
    const int wid = t >> 5, lane = t & 31;
    const int bm = blockIdx.y * 128;
    const int bn = blockIdx.x * 128;
    const int wm = wid >> 2, wn = wid & 3;

    float acc[4][4][4];
#pragma unroll
    for (int i = 0; i < 4; ++i)
#pragma unroll
        for (int j = 0; j < 4; ++j)
#pragma unroll
            for (int k = 0; k < 4; ++k) acc[i][j][k] = 0.0f;

    const int nc = K >> 6;

    const int g  = lane >> 3, lr = lane & 7;
    const int a_rit = lr + (g & 1) * 8, a_kqo = g >> 1;
    const int b_rit = lr + (g >> 1) * 8, b_kqo = g & 1;

    uint32_t aA[4], aBh[2], aBl[2];
    int aRsw[4], bRsw[2];
#pragma unroll
    for (int mt = 0; mt < 4; ++mt) {
        int row = wm * 64 + mt * 16 + a_rit;
        aA[mt] = sb + row * 128;
        aRsw[mt] = row & 7;
    }
#pragma unroll
    for (int p = 0; p < 2; ++p) {
        int row = wn * 32 + p * 16 + b_rit;
        aBh[p] = sb + BHI_OFF + row * 128;
        aBl[p] = sb + BLO_OFF + row * 128;
        bRsw[p] = row & 7;
    }

    auto issue = [&](int c, int s) {
        const uint32_t st = sb + s * STAGE;
        const int kb = c * 64;
#pragma unroll
        for (int i = 0; i < ITER; ++i) {
            int u = t + i * 256;
            int arr = u >> 10, v = u & 1023, row = v >> 3, kq = v & 7;
            const __half* src;
            if      (arr == 0) src = Ahi + (size_t)(bm + row) * K + kb + kq * 8;
            else if (arr == 1) src = Bhi + (size_t)(bn + row) * K + kb + kq * 8;
            else               src = Blo + (size_t)(bn + row) * K + kb + kq * 8;
            cp16(st + arr * 16384u + asw(row, kq), src);
        }
        cp_commit();
    };

    issue(0, 0);
    int s = 0;
    for (int c = 0; c < nc; ++c) {
        cp_wait<0>();
        __syncthreads();
        if (c + 1 < nc) issue(c + 1, s ^ 1);

        const uint32_t stoff = (uint32_t)(s * STAGE);
#pragma unroll
        for (int kk = 0; kk < 4; ++kk) {
            uint32_t ah[4][4], bh[4][2], bl[4][2];
#pragma unroll
            for (int mt = 0; mt < 4; ++mt) {
                uint32_t o = (uint32_t)(((((kk << 1) | a_kqo) ^ aRsw[mt]) << 4));
                ldsm4(ah[mt], aA[mt] + stoff + o);
            }
#pragma unroll
            for (int p = 0; p < 2; ++p) {
                uint32_t r[4];
                uint32_t o = (uint32_t)(((((kk << 1) | b_kqo) ^ bRsw[p]) << 4));
                ldsm4(r, aBh[p] + stoff + o);
                bh[2 * p][0] = r[0]; bh[2 * p][1] = r[1];
                bh[2 * p + 1][0] = r[2]; bh[2 * p + 1][1] = r[3];
                if (PASSES == 2) {
                    ldsm4(r, aBl[p] + stoff + o);
                    bl[2 * p][0] = r[0]; bl[2 * p][1] = r[1];
                    bl[2 * p + 1][0] = r[2]; bl[2 * p + 1][1] = r[3];
                }
            }
#pragma unroll
            for (int mt = 0; mt < 4; ++mt)
#pragma unroll
                for (int nt = 0; nt < 4; ++nt) {
                    mma_f16(acc[mt][nt], ah[mt], bh[nt]);
                    if (PASSES == 2) mma_f16(acc[mt][nt], ah[mt], bl[nt]);
                }
        }
        s ^= 1;
    }

    const int mrow = bm + wm * 64;
    const int ncol = bn + wn * 32;
#pragma unroll
    for (int mt = 0; mt < 4; ++mt) {
#pragma unroll
        for (int nt = 0; nt < 4; ++nt) {
            float* d = acc[mt][nt];
            int r0 = mrow + mt * 16 + (lane >> 2);
            int cix = ncol + nt * 8 + (lane & 3) * 2;
            float b0 = bias[cix], b1 = bias[cix + 1];
            float v00 = d[0] + b0, v01 = d[1] + b1;
            float v10 = d[2] + b0, v11 = d[3] + b1;
            if (MODE == 0) {
                float2 p0{v00, v01}, p1{v10, v11};
                *(float2*)&Cf[(size_t)r0 * N + cix]       = p0;
                *(float2*)&Cf[(size_t)(r0 + 8) * N + cix] = p1;
            } else if (MODE == 1) {
                v00 = gelu_f(v00); v01 = gelu_f(v01);
                v10 = gelu_f(v10); v11 = gelu_f(v11);
                *(uint32_t*)&Chi[(size_t)r0 * N + cix]       = pack2h(v00, v01);
                *(uint32_t*)&Chi[(size_t)(r0 + 8) * N + cix] = pack2h(v10, v11);
            } else {
                uint32_t h0, l0, h1, l1;
                split2(v00, v01, h0, l0);
                split2(v10, v11, h1, l1);
                *(uint32_t*)&Chi[(size_t)r0 * N + cix]       = h0;
                *(uint32_t*)&Clo[(size_t)r0 * N + cix]       = l0;
                *(uint32_t*)&Chi[(size_t)(r0 + 8) * N + cix] = h1;
                *(uint32_t*)&Clo[(size_t)(r0 + 8) * N + cix] = l1;
            }
        }
    }
}

// ======================= HMMA causal attention (FA2-style) =======================
// QK: 3-pass split fp16.  PV: 2-pass (P hi-only x (Vh + Vl)).
#define ASMEM 49152

__global__ void __launch_bounds__(128, 3)
attn_mma_kernel(const __half* __restrict__ qkvh, const __half* __restrict__ qkvl,
                __half* __restrict__ ohi)
{
    extern __shared__ char asmem[];
    const uint32_t sb = smem_u32(asmem);

    const int t = threadIdx.x, wid = t >> 5, lane = t & 31;
    const int qi = gridDim.x - 1 - blockIdx.x;
    const int qb = qi * 64;
    const int h  = blockIdx.y, b = blockIdx.z;

    const __half* Kh_g = qkvh + (size_t)b * TT * C3 + h * HDD;
    const __half* Kl_g = qkvl + (size_t)b * TT * C3 + h * HDD;
    const __half* Qh_g = Kh_g + CC;
    const __half* Ql_g = Kl_g + CC;
    const __half* Vh_g = Kh_g + 2 * CC;
    const __half* Vl_g = Kl_g + 2 * CC;

#pragma unroll
    for (int i = 0; i < 8; ++i) {
        int uu = t + i * 128;
        int arr = uu >> 9, v = uu & 511, row = v >> 3, u = v & 7;
        const __half* src = (arr ? Ql_g : Qh_g) + (size_t)(qb + row) * C3 + u * 8;
        cp16(sb + arr * 8192 + asw(row, u), src);
    }
    cp_commit();

    const int g = lane >> 3, lr = lane & 7;
    const int r = lane >> 2, c = lane & 3;
    const int qrow = wid * 16 + lr + ((g & 1) << 3);
    const int a_u  = g >> 1;
    const int krit = lr + ((g >> 1) << 3);
    const int b_u  = g & 1;
    const int vrit = lr + ((g & 1) << 3);
    const int v_u  = g >> 1;

    float O[8][4];
#pragma unroll
    for (int i = 0; i < 8; ++i)
#pragma unroll
        for (int j = 0; j < 4; ++j) O[i][j] = 0.0f;
    float m0 = -1e30f, m1 = -1e30f, l0 = 0.0f, l1 = 0.0f;

    const int ntiles = qi + 1;
    for (int kt = 0; kt < ntiles; ++kt) {
        const int kb = kt * 64;
        __syncthreads();
#pragma unroll
        for (int i = 0; i < 16; ++i) {
            int uu = t + i * 128;
            int arr = uu >> 9, v = uu & 511, row = v >> 3, u = v & 7;
            const __half* src;
            if      (arr == 0) src = Kh_g + (size_t)(kb + row) * C3 + u * 8;
            else if (arr == 1) src = Kl_g + (size_t)(kb + row) * C3 + u * 8;
            else if (arr == 2) src = Vh_g + (size_t)(kb + row) * C3 + u * 8;
            else               src = Vl_g + (size_t)(kb + row) * C3 + u * 8;
            cp16(sb + 16384 + arr * 8192 + asw(row, u), src);
        }
        cp_commit();
        cp_wait<0>();
        __syncthreads();

        float S[8][4];
#pragma unroll
        for (int i = 0; i < 8; ++i)
#pragma unroll
            for (int j = 0; j < 4; ++j) S[i][j] = 0.0f;

#pragma unroll
        for (int kk = 0; kk < 4; ++kk) {
            uint32_t ah[4], al[4];
            uint32_t aoq = (uint32_t)(qrow * 128 + ((((kk << 1) | a_u) ^ (qrow & 7)) << 4));
            ldsm4(ah, sb + aoq);
            ldsm4(al, sb + 8192 + aoq);
#pragma unroll
            for (int p = 0; p < 4; ++p) {
                int krow = (p << 4) + krit;
                uint32_t ko = (uint32_t)(krow * 128 + ((((kk << 1) | b_u) ^ (krow & 7)) << 4));
                uint32_t bh[4], bl[4];
                ldsm4(bh, sb + 16384 + ko);
                ldsm4(bl, sb + 24576 + ko);
                mma_f16(S[2 * p],     ah, bh);
                mma_f16(S[2 * p],     ah, bl);
                mma_f16(S[2 * p],     al, bh);
                mma_f16(S[2 * p + 1], ah, bh + 2);
                mma_f16(S[2 * p + 1], ah, bl + 2);
                mma_f16(S[2 * p + 1], al, bh + 2);
            }
        }

#pragma unroll
        for (int nt = 0; nt < 8; ++nt)
#pragma unroll
            for (int e = 0; e < 4; ++e) S[nt][e] *= 0.125f;
        if (kt == qi) {
            const int q0 = qb + wid * 16 + r, q1 = q0 + 8;
#pragma unroll
            for (int nt = 0; nt < 8; ++nt) {
                int k0 = kb + 8 * nt + 2 * c;
                if (k0     > q0) S[nt][0] = -1e30f;
                if (k0 + 1 > q0) S[nt][1] = -1e30f;
                if (k0     > q1) S[nt][2] = -1e30f;
                if (k0 + 1 > q1) S[nt][3] = -1e30f;
            }
        }

        float mx0 = -1e30f, mx1 = -1e30f;
#pragma unroll
        for (int nt = 0; nt < 8; ++nt) {
            mx0 = fmaxf(mx0, fmaxf(S[nt][0], S[nt][1]));
            mx1 = fmaxf(mx1, fmaxf(S[nt][2], S[nt][3]));
        }
        mx0 = fmaxf(mx0, __shfl_xor_sync(0xffffffffu, mx0, 1));
        mx0 = fmaxf(mx0, __shfl_xor_sync(0xffffffffu, mx0, 2));
        mx1 = fmaxf(mx1, __shfl_xor_sync(0xffffffffu, mx1, 1));
        mx1 = fmaxf(mx1, __shfl_xor_sync(0xffffffffu, mx1, 2));
        float mn0 = fmaxf(m0, mx0), mn1 = fmaxf(m1, mx1);
        float al0 = __expf(m0 - mn0), al1 = __expf(m1 - mn1);
        m0 = mn0; m1 = mn1;

        float s0 = 0.0f, s1 = 0.0f;
#pragma unroll
        for (int nt = 0; nt < 8; ++nt) {
            S[nt][0] = __expf(S[nt][0] - mn0);
            S[nt][1] = __expf(S[nt][1] - mn0);
            S[nt][2] = __expf(S[nt][2] - mn1);
            S[nt][3] = __expf(S[nt][3] - mn1);
            s0 += S[nt][0] + S[nt][1];
            s1 += S[nt][2] + S[nt][3];
        }
        l0 = l0 * al0 + s0;
        l1 = l1 * al1 + s1;
#pragma unroll
        for (int nt = 0; nt < 8; ++nt) {
            O[nt][0] *= al0; O[nt][1] *= al0;
            O[nt][2] *= al1; O[nt][3] *= al1;
        }

#pragma unroll
        for (int kk = 0; kk < 4; ++kk) {
            uint32_t ph[4];
            ph[0] = pack2h(S[2 * kk][0],     S[2 * kk][1]);
            ph[1] = pack2h(S[2 * kk][2],     S[2 * kk][3]);
            ph[2] = pack2h(S[2 * kk + 1][0], S[2 * kk + 1][1]);
            ph[3] = pack2h(S[2 * kk + 1][2], S[2 * kk + 1][3]);
            int vrow = (kk << 4) + vrit;
#pragma unroll
            for (int p = 0; p < 4; ++p) {
                uint32_t vo = (uint32_t)(vrow * 128 + ((((p << 1) | v_u) ^ (vrow & 7)) << 4));
                uint32_t vh[4], vl[4];
                ldsm4t(vh, sb + 32768 + vo);
                ldsm4t(vl, sb + 40960 + vo);
                mma_f16(O[2 * p],     ph, vh);
                mma_f16(O[2 * p],     ph, vl);
                mma_f16(O[2 * p + 1], ph, vh + 2);
                mma_f16(O[2 * p + 1], ph, vl + 2);
            }
        }
    }

    l0 += __shfl_xor_sync(0xffffffffu, l0, 1);
    l0 += __shfl_xor_sync(0xffffffffu, l0, 2);
    l1 += __shfl_xor_sync(0xffffffffu, l1, 1);
    l1 += __shfl_xor_sync(0xffffffffu, l1, 2);
    const float i0 = 1.0f / l0, i1 = 1.0f / l1;
    const int row0 = qb + wid * 16 + r, row1 = row0 + 8;
#pragma unroll
    for (int nt = 0; nt < 8; ++nt) {
        int col = h * HDD + 8 * nt + 2 * c;
        size_t idx0 = ((size_t)b * TT + row0) * CC + col;
        size_t idx1 = ((size_t)b * TT + row1) * CC + col;
        *(uint32_t*)&ohi[idx0] = pack2h(O[nt][0] * i0, O[nt][1] * i0);
        *(uint32_t*)&ohi[idx1] = pack2h(O[nt][2] * i1, O[nt][3] * i1);
    }
}

// ---------------- LayerNorm + residual ----------------
__device__ __forceinline__ float block_sum(float v, float* red) {
    const int lane = threadIdx.x & 31, w = threadIdx.x >> 5;
#pragma unroll
    for (int o = 16; o; o >>= 1) v += __shfl_xor_sync(0xffffffffu, v, o);
    if (lane == 0) red[w] = v;
    __syncthreads();
    if (w == 0) {
        float s = (lane < 8) ? red[lane] : 0.0f;
#pragma unroll
        for (int o = 4; o; o >>= 1) s += __shfl_xor_sync(0xffffffffu, s, o);
        if (lane == 0) red[0] = s;
    }
    __syncthreads();
    float rr = red[0];
    __syncthreads();
    return rr;
}

template<bool SPLIT>
__global__ void __launch_bounds__(256)
ln_res_kernel(const float* __restrict__ res, const float* __restrict__ y,
              const float* __restrict__ g, const float* __restrict__ be,
              float* __restrict__ out, __half* __restrict__ ohi)
{
    __shared__ float red[8];
    const int row = blockIdx.x;
    const int t = threadIdx.x;
    const float* yr = y + (size_t)row * CC;

    float v[4];
    float s = 0.0f;
#pragma unroll
    for (int i = 0; i < 4; ++i) { v[i] = yr[t + i * 256]; s += v[i]; }
    const float mean = block_sum(s, red) * (1.0f / CC);

    float sq = 0.0f;
#pragma unroll
    for (int i = 0; i < 4; ++i) { float d = v[i] - mean; sq += d * d; }
    const float var = block_sum(sq, red) * (1.0f / CC);
    const float rstd = rsqrtf(var + 1e-5f);

    const float* rr = res + (size_t)row * CC;
    float* orow = out + (size_t)row * CC;
#pragma unroll
    for (int i = 0; i < 4; ++i) {
        int cix = t + i * 256;
        float o = rr[cix] + (v[i] - mean) * rstd * g[cix] + be[cix];
        orow[cix] = o;
        if (SPLIT) ohi[(size_t)row * CC + cix] = __float2half_rn(o);
    }
}

// ---------------- launch ----------------
extern "C" void kernel_launch(void* const* d_in, const int* in_sizes, int n_in,
                              void* d_out, int out_size)
{
    const float* x      = (const float*)d_in[0];
    const float* w_attn = (const float*)d_in[1];
    const float* b_attn = (const float*)d_in[2];
    const float* wa1    = (const float*)d_in[3];
    const float* ba1    = (const float*)d_in[4];
    const float* wa2    = (const float*)d_in[5];
    const float* ba2    = (const float*)d_in[6];
    const float* g1     = (const float*)d_in[7];
    const float* be1    = (const float*)d_in[8];
    const float* wf1    = (const float*)d_in[9];
    const float* bf1    = (const float*)d_in[10];
    const float* wf2    = (const float*)d_in[11];
    const float* bf2    = (const float*)d_in[12];
    const float* g2     = (const float*)d_in[13];
    const float* be2    = (const float*)d_in[14];
    float* out = (float*)d_out;

    float *x1, *y;
    cudaGetSymbolAddress((void**)&x1, g_x1);
    cudaGetSymbolAddress((void**)&y,  g_y);

    __half *wqkv_hi, *wqkv_lo, *wa1_hi, *wa2_hi, *wf1_hi, *wf2_hi,
           *ahi, *hhi, *qkvh, *qkvl;
    cudaGetSymbolAddress((void**)&wqkv_hi, g_wqkv_hi);
    cudaGetSymbolAddress((void**)&wqkv_lo, g_wqkv_lo);
    cudaGetSymbolAddress((void**)&wa1_hi,  g_wa1_hi);
    cudaGetSymbolAddress((void**)&wa2_hi,  g_wa2_hi);
    cudaGetSymbolAddress((void**)&wf1_hi,  g_wf1_hi);
    cudaGetSymbolAddress((void**)&wf2_hi,  g_wf2_hi);
    cudaGetSymbolAddress((void**)&ahi,     g_ahi);
    cudaGetSymbolAddress((void**)&hhi,     g_hhi);
    cudaGetSymbolAddress((void**)&qkvh,    g_qkvh);
    cudaGetSymbolAddress((void**)&qkvl,    g_qkvl);

    cudaFuncSetAttribute(attn_mma_kernel, cudaFuncAttributeMaxDynamicSharedMemorySize, ASMEM);
    cudaFuncSetAttribute((gemm_mma_kernel<2, 2>), cudaFuncAttributeMaxDynamicSharedMemorySize, GS2);
    cudaFuncSetAttribute((gemm_mma_kernel<1, 1>), cudaFuncAttributeMaxDynamicSharedMemorySize, GS1);
    cudaFuncSetAttribute((gemm_mma_kernel<0, 1>), cudaFuncAttributeMaxDynamicSharedMemorySize, GS1);

    // all conversions (5 weights + x) in one launch
    cvt_all_kernel<<<CVT_BLOCKS, 256>>>(
        w_attn, wqkv_hi, wqkv_lo,
        wa1, wa1_hi,
        wa2, wa2_hi,
        wf1, wf1_hi,
        wf2, wf2_hi,
        x, ahi);

    // 1) qkv = x @ w_attn + b_attn  (2-pass, hi+lo out)
    gemm_mma_kernel<2, 2><<<dim3(C3 / 128, MTOK / 128), 256, GS2>>>(
        ahi, wqkv_hi, wqkv_lo, b_attn, nullptr, qkvh, qkvl, C3, CC);
    // 2) attention -> hi-only att
    attn_mma_kernel<<<dim3(TT / 64, NHH, BB), 128, ASMEM>>>(qkvh, qkvl, ahi);
    // 3) h = gelu(att @ wa1 + ba1)  (1-pass)
    gemm_mma_kernel<1, 1><<<dim3(C4 / 128, MTOK / 128), 256, GS1>>>(
        ahi, wa1_hi, nullptr, ba1, nullptr, hhi, nullptr, C4, CC);
    // 4) y = h @ wa2 + ba2  (1-pass)
    gemm_mma_kernel<0, 1><<<dim3(CC / 128, MTOK / 128), 256, GS1>>>(
        hhi, wa2_hi, nullptr, ba2, y, nullptr, nullptr, CC, C4);
    // 5) x1 = x + ln(y); emit fp16 x1 hi
    ln_res_kernel<true><<<MTOK, 256>>>(x, y, g1, be1, x1, ahi);
    // 6) h = gelu(x1 @ wf1 + bf1)  (1-pass)
    gemm_mma_kernel<1, 1><<<dim3(C4 / 128, MTOK / 128), 256, GS1>>>(
        ahi, wf1_hi, nullptr, bf1, nullptr, hhi, nullptr, C4, CC);
    // 7) y = h @ wf2 + bf2  (1-pass)
    gemm_mma_kernel<0, 1><<<dim3(CC / 128, MTOK / 128), 256, GS1>>>(
        hhi, wf2_hi, nullptr, bf2, y, nullptr, nullptr, CC, C4);
    // 8) out = x1 + ln(y)
    ln_res_kernel<false><<<MTOK, 256>>>(x1, y, g2, be2, out, nullptr);
}

// round 13
// speedup vs baseline: 2.4039x; 1.0165x over previous
#include <cuda_runtime.h>
#include <cuda_fp16.h>
#include <math.h>
#include <stdint.h>

// Problem dims (fixed)
#define BB 2
#define TT 2048
#define CC 1024
#define NHH 16
#define HDD 64
#define MTOK 4096          // B*T
#define C3 3072
#define C4 4096

// ---------------- scratch (no allocation allowed) ----------------
__device__ float g_x1 [(size_t)MTOK * CC];
__device__ float g_y  [(size_t)MTOK * CC];

// fp16 weights, transposed to [N][K] (lo only for wqkv)
__device__ __half g_wqkv_hi[(size_t)C3 * CC], g_wqkv_lo[(size_t)C3 * CC];
__device__ __half g_wa1_hi [(size_t)C4 * CC];
__device__ __half g_wa2_hi [(size_t)CC * C4];
__device__ __half g_wf1_hi [(size_t)C4 * CC];
__device__ __half g_wf2_hi [(size_t)CC * C4];
// fp16 activations
__device__ __half g_ahi [(size_t)MTOK * CC];
__device__ __half g_hhi [(size_t)MTOK * C4];
__device__ __half g_qkvh[(size_t)MTOK * C3], g_qkvl[(size_t)MTOK * C3];

__device__ __forceinline__ float gelu_f(float v) {
    return 0.5f * v * (1.0f + erff(v * 0.7071067811865475f));
}

// ======================= PTX helpers =======================
__device__ __forceinline__ uint32_t smem_u32(const void* p) {
    uint32_t a;
    asm("{ .reg .u64 t; cvta.to.shared.u64 t, %1; cvt.u32.u64 %0, t; }" : "=r"(a) : "l"(p));
    return a;
}
__device__ __forceinline__ void ldsm4(uint32_t* r, uint32_t addr) {
    asm volatile("ldmatrix.sync.aligned.m8n8.x4.shared.b16 {%0,%1,%2,%3}, [%4];"
                 : "=r"(r[0]), "=r"(r[1]), "=r"(r[2]), "=r"(r[3]) : "r"(addr));
}
__device__ __forceinline__ void ldsm4t(uint32_t* r, uint32_t addr) {
    asm volatile("ldmatrix.sync.aligned.m8n8.x4.trans.shared.b16 {%0,%1,%2,%3}, [%4];"
                 : "=r"(r[0]), "=r"(r[1]), "=r"(r[2]), "=r"(r[3]) : "r"(addr));
}
__device__ __forceinline__ void mma_f16(float* d, const uint32_t* a, const uint32_t* b) {
    asm volatile(
        "mma.sync.aligned.m16n8k16.row.col.f32.f16.f16.f32 "
        "{%0,%1,%2,%3}, {%4,%5,%6,%7}, {%8,%9}, {%0,%1,%2,%3};"
        : "+f"(d[0]), "+f"(d[1]), "+f"(d[2]), "+f"(d[3])
        : "r"(a[0]), "r"(a[1]), "r"(a[2]), "r"(a[3]), "r"(b[0]), "r"(b[1]));
}
__device__ __forceinline__ void cp16(uint32_t dst, const void* src) {
    unsigned long long g = __cvta_generic_to_global(src);
    asm volatile("cp.async.ca.shared.global [%0], [%1], 16;" :: "r"(dst), "l"(g) : "memory");
}
__device__ __forceinline__ void cp_commit() {
    asm volatile("cp.async.commit_group;" ::: "memory");
}
template<int N>
__device__ __forceinline__ void cp_wait() {
    asm volatile("cp.async.wait_group %0;" :: "n"(N) : "memory");
}
__device__ __forceinline__ void split2(float a, float b, uint32_t& hi, uint32_t& lo) {
    __half ha = __float2half_rn(a), hb = __float2half_rn(b);
    __half2 H = __halves2half2(ha, hb);
    __half2 L = __halves2half2(__float2half_rn(a - __half2float(ha)),
                               __float2half_rn(b - __half2float(hb)));
    hi = *(uint32_t*)&H;
    lo = *(uint32_t*)&L;
}
__device__ __forceinline__ uint32_t pack2h(float a, float b) {
    __half2 H = __halves2half2(__float2half_rn(a), __float2half_rn(b));
    return *(uint32_t*)&H;
}

// ======================= fused conversion kernel =======================
#define CVT_BLOCKS (19456 + 4096)
__global__ void __launch_bounds__(256)
cvt_all_kernel(const float* __restrict__ W0, __half* __restrict__ h0, __half* __restrict__ l0,
               const float* __restrict__ W1, __half* __restrict__ h1,
               const float* __restrict__ W2, __half* __restrict__ h2,
               const float* __restrict__ W3, __half* __restrict__ h3,
               const float* __restrict__ W4, __half* __restrict__ h4,
               const float* __restrict__ x,  __half* __restrict__ xh)
{
    const int bid = blockIdx.x;
    if (bid >= 19456) {
        int i = ((bid - 19456) * 256 + threadIdx.x) * 4;
        float4 v = *(const float4*)(x + i);
        *(uint32_t*)(xh + i)     = pack2h(v.x, v.y);
        *(uint32_t*)(xh + i + 2) = pack2h(v.z, v.w);
        return;
    }
    __shared__ float tile[32][33];
    const float* W; __half* hi; __half* lo; int K, N, local;
    if      (bid < 3072)  { W = W0; hi = h0; lo = l0;      K = CC; N = C3; local = bid; }
    else if (bid < 7168)  { W = W1; hi = h1; lo = nullptr; K = CC; N = C4; local = bid - 3072; }
    else if (bid < 11264) { W = W2; hi = h2; lo = nullptr; K = C4; N = CC; local = bid - 7168; }
    else if (bid < 15360) { W = W3; hi = h3; lo = nullptr; K = CC; N = C4; local = bid - 11264; }
    else                  { W = W4; hi = h4; lo = nullptr; K = C4; N = CC; local = bid - 15360; }
    const int nb = N >> 5;
    const int n0 = (local % nb) * 32, k0 = (local / nb) * 32;
    const int tx = threadIdx.x & 31, ty = threadIdx.x >> 5;
#pragma unroll
    for (int r = 0; r < 4; ++r)
        tile[ty + r * 8][tx] = W[(size_t)(k0 + ty + r * 8) * N + n0 + tx];
    __syncthreads();
#pragma unroll
    for (int r = 0; r < 4; ++r) {
        int n = n0 + ty + r * 8;
        float v = tile[tx][ty + r * 8];
        __half h = __float2half_rn(v);
        hi[(size_t)n * K + k0 + tx] = h;
        if (lo) lo[(size_t)n * K + k0 + tx] = __float2half_rn(v - __half2float(h));
    }
}

// 128B-row swizzle (8 16B units per row, 8-way xor)
__device__ __forceinline__ uint32_t asw(int row, int u) {
    return (uint32_t)(row * 128 + ((u ^ (row & 7)) << 4));
}

// ======================= HMMA fp16 GEMM, CTA 128x128, BK=64 =======================
// 8 warps (2x4), warp tile 64x32, 2 CTAs/SM, ONE __syncthreads per K-chunk.
// PASSES=2: D = Ah*(Bh+Bl), 2-stage.  PASSES=1: D = Ah*Bh, 3-stage deep pipeline.
#define GS2 (2 * 49152)
#define GS1 (3 * 32768)
template<int MODE, int PASSES>
__global__ void __launch_bounds__(256, 2)
gemm_mma_kernel(const __half* __restrict__ Ahi,
                const __half* __restrict__ Bhi, const __half* __restrict__ Blo,
                const float* __restrict__ bias, float* __restrict__ Cf,
                __half* __restrict__ Chi, __half* __restrict__ Clo,
                int N, int K)
{
    constexpr uint32_t STAGE   = (PASSES == 2) ? 49152u : 32768u;
    constexpr uint32_t BHI_OFF = 16384u;
    constexpr uint32_t BLO_OFF = 32768u;
    constexpr int ITER = (PASSES == 2) ? 12 : 8;

    extern __shared__ char smem[];
    const uint32_t sb = smem_u32(smem);

    const int t = threadIdx.x;
    const int wid = t >> 5, lane = t & 31;
    const int bm = blockIdx.y * 128;
    const int bn = blockIdx.x * 128;
    const int wm = wid >> 2, wn = wid & 3;

    float acc[4][4][4];
#pragma unroll
    for (int i = 0; i < 4; ++i)
#pragma unroll
        for (int j = 0; j < 4; ++j)
#pragma unroll
            for (int k = 0; k < 4; ++k) acc[i][j][k] = 0.0f;

    const int nc = K >> 6;

    const int g  = lane >> 3, lr = lane & 7;
    const int a_rit = lr + (g & 1) * 8, a_kqo = g >> 1;
    const int b_rit = lr + (g >> 1) * 8, b_kqo = g & 1;

    uint32_t aA[4], aBh[2], aBl[2];
    int aRsw[4], bRsw[2];
#pragma unroll
    for (int mt = 0; mt < 4; ++mt) {
        int row = wm * 64 + mt * 16 + a_rit;
        aA[mt] = sb + row * 128;
        aRsw[mt] = row & 7;
    }
#pragma unroll
    for (int p = 0; p < 2; ++p) {
        int row = wn * 32 + p * 16 + b_rit;
        aBh[p] = sb + BHI_OFF + row * 128;
        aBl[p] = sb + BLO_OFF + row * 128;
        bRsw[p] = row & 7;
    }

    auto issue = [&](int c, int s) {
        const uint32_t st = sb + s * STAGE;
        const int kb = c * 64;
#pragma unroll
        for (int i = 0; i < ITER; ++i) {
            int u = t + i * 256;
            int arr = u >> 10, v = u & 1023, row = v >> 3, kq = v & 7;
            const __half* src;
            if      (arr == 0) src = Ahi + (size_t)(bm + row) * K + kb + kq * 8;
            else if (arr == 1) src = Bhi + (size_t)(bn + row) * K + kb + kq * 8;
            else               src = Blo + (size_t)(bn + row) * K + kb + kq * 8;
            cp16(st + arr * 16384u + asw(row, kq), src);
        }
        cp_commit();
    };

    issue(0, 0);
    if (PASSES == 1 && nc > 1) issue(1, 1);
    int s = 0;
    for (int c = 0; c < nc; ++c) {
        if (PASSES == 1) {
            if (c + 1 < nc) cp_wait<1>();
            else            cp_wait<0>();
        } else {
            cp_wait<0>();
        }
        __syncthreads();
        if (PASSES == 1) { if (c + 2 < nc) issue(c + 2, (c + 2) % 3); }
        else             { if (c + 1 < nc) issue(c + 1, s ^ 1); }

        const uint32_t stoff = (uint32_t)(s * STAGE);
#pragma unroll
        for (int kk = 0; kk < 4; ++kk) {
            uint32_t ah[4][4], bh[4][2], bl[4][2];
#pragma unroll
            for (int mt = 0; mt < 4; ++mt) {
                uint32_t o = (uint32_t)(((((kk << 1) | a_kqo) ^ aRsw[mt]) << 4));
                ldsm4(ah[mt], aA[mt] + stoff + o);
            }
#pragma unroll
            for (int p = 0; p < 2; ++p) {
                uint32_t r[4];
                uint32_t o = (uint32_t)(((((kk << 1) | b_kqo) ^ bRsw[p]) << 4));
                ldsm4(r, aBh[p] + stoff + o);
                bh[2 * p][0] = r[0]; bh[2 * p][1] = r[1];
                bh[2 * p + 1][0] = r[2]; bh[2 * p + 1][1] = r[3];
                if (PASSES == 2) {
                    ldsm4(r, aBl[p] + stoff + o);
                    bl[2 * p][0] = r[0]; bl[2 * p][1] = r[1];
                    bl[2 * p + 1][0] = r[2]; bl[2 * p + 1][1] = r[3];
                }
            }
#pragma unroll
            for (int mt = 0; mt < 4; ++mt)
#pragma unroll
                for (int nt = 0; nt < 4; ++nt) {
                    mma_f16(acc[mt][nt], ah[mt], bh[nt]);
                    if (PASSES == 2) mma_f16(acc[mt][nt], ah[mt], bl[nt]);
                }
        }
        s = (PASSES == 1) ? ((s + 1) % 3) : (s ^ 1);
    }

    const int mrow = bm + wm * 64;
    const int ncol = bn + wn * 32;
#pragma unroll
    for (int mt = 0; mt < 4; ++mt) {
#pragma unroll
        for (int nt = 0; nt < 4; ++nt) {
            float* d = acc[mt][nt];
            int r0 = mrow + mt * 16 + (lane >> 2);
            int cix = ncol + nt * 8 + (lane & 3) * 2;
            float b0 = bias[cix], b1 = bias[cix + 1];
            float v00 = d[0] + b0, v01 = d[1] + b1;
            float v10 = d[2] + b0, v11 = d[3] + b1;
            if (MODE == 0) {
                float2 p0{v00, v01}, p1{v10, v11};
                *(float2*)&Cf[(size_t)r0 * N + cix]       = p0;
                *(float2*)&Cf[(size_t)(r0 + 8) * N + cix] = p1;
            } else if (MODE == 1) {
                v00 = gelu_f(v00); v01 = gelu_f(v01);
                v10 = gelu_f(v10); v11 = gelu_f(v11);
                *(uint32_t*)&Chi[(size_t)r0 * N + cix]       = pack2h(v00, v01);
                *(uint32_t*)&Chi[(size_t)(r0 + 8) * N + cix] = pack2h(v10, v11);
            } else {
                uint32_t h0, l0, h1, l1;
                split2(v00, v01, h0, l0);
                split2(v10, v11, h1, l1);
                *(uint32_t*)&Chi[(size_t)r0 * N + cix]       = h0;
                *(uint32_t*)&Clo[(size_t)r0 * N + cix]       = l0;
                *(uint32_t*)&Chi[(size_t)(r0 + 8) * N + cix] = h1;
                *(uint32_t*)&Clo[(size_t)(r0 + 8) * N + cix] = l1;
            }
        }
    }
}

// ======================= HMMA causal attention =======================
// QK: 2-pass (Qh x (Kh + Kl)).  PV: 1-pass (P hi x Vh).
// smem: Qh 8K | Kh 8K | Kl 8K | Vh 8K = 32KB.
#define ASMEM 32768

__global__ void __launch_bounds__(128, 3)
attn_mma_kernel(const __half* __restrict__ qkvh, const __half* __restrict__ qkvl,
                __half* __restrict__ ohi)
{
    extern __shared__ char asmem[];
    const uint32_t sb = smem_u32(asmem);

    const int t = threadIdx.x, wid = t >> 5, lane = t & 31;
    const int qi = gridDim.x - 1 - blockIdx.x;
    const int qb = qi * 64;
    const int h  = blockIdx.y, b = blockIdx.z;

    const __half* Kh_g = qkvh + (size_t)b * TT * C3 + h * HDD;
    const __half* Kl_g = qkvl + (size_t)b * TT * C3 + h * HDD;
    const __half* Qh_g = Kh_g + CC;
    const __half* Vh_g = Kh_g + 2 * CC;

    // load Qh only: 512 16B units
#pragma unroll
    for (int i = 0; i < 4; ++i) {
        int uu = t + i * 128;
        int row = uu >> 3, u = uu & 7;
        cp16(sb + asw(row, u), Qh_g + (size_t)(qb + row) * C3 + u * 8);
    }
    cp_commit();

    const int g = lane >> 3, lr = lane & 7;
    const int r = lane >> 2, c = lane & 3;
    const int qrow = wid * 16 + lr + ((g & 1) << 3);
    const int a_u  = g >> 1;
    const int krit = lr + ((g >> 1) << 3);
    const int b_u  = g & 1;
    const int vrit = lr + ((g & 1) << 3);
    const int v_u  = g >> 1;

    float O[8][4];
#pragma unroll
    for (int i = 0; i < 8; ++i)
#pragma unroll
        for (int j = 0; j < 4; ++j) O[i][j] = 0.0f;
    float m0 = -1e30f, m1 = -1e30f, l0 = 0.0f, l1 = 0.0f;

    const int ntiles = qi + 1;
    for (int kt = 0; kt < ntiles; ++kt) {
        const int kb = kt * 64;
        __syncthreads();
        // Kh | Kl | Vh: 1536 units = 12 iters
#pragma unroll
        for (int i = 0; i < 12; ++i) {
            int uu = t + i * 128;
            int arr = uu >> 9, v = uu & 511, row = v >> 3, u = v & 7;
            const __half* src;
            if      (arr == 0) src = Kh_g + (size_t)(kb + row) * C3 + u * 8;
            else if (arr == 1) src = Kl_g + (size_t)(kb + row) * C3 + u * 8;
            else               src = Vh_g + (size_t)(kb + row) * C3 + u * 8;
            cp16(sb + 8192 + arr * 8192 + asw(row, u), src);
        }
        cp_commit();
        cp_wait<0>();
        __syncthreads();

        float S[8][4];
#pragma unroll
        for (int i = 0; i < 8; ++i)
#pragma unroll
            for (int j = 0; j < 4; ++j) S[i][j] = 0.0f;

#pragma unroll
        for (int kk = 0; kk < 4; ++kk) {
            uint32_t ah[4];
            uint32_t aoq = (uint32_t)(qrow * 128 + ((((kk << 1) | a_u) ^ (qrow & 7)) << 4));
            ldsm4(ah, sb + aoq);
#pragma unroll
            for (int p = 0; p < 4; ++p) {
                int krow = (p << 4) + krit;
                uint32_t ko = (uint32_t)(krow * 128 + ((((kk << 1) | b_u) ^ (krow & 7)) << 4));
                uint32_t bh[4], bl[4];
                ldsm4(bh, sb + 8192 + ko);
                ldsm4(bl, sb + 16384 + ko);
                mma_f16(S[2 * p],     ah, bh);
                mma_f16(S[2 * p],     ah, bl);
                mma_f16(S[2 * p + 1], ah, bh + 2);
                mma_f16(S[2 * p + 1], ah, bl + 2);
            }
        }

#pragma unroll
        for (int nt = 0; nt < 8; ++nt)
#pragma unroll
            for (int e = 0; e < 4; ++e) S[nt][e] *= 0.125f;
        if (kt == qi) {
            const int q0 = qb + wid * 16 + r, q1 = q0 + 8;
#pragma unroll
            for (int nt = 0; nt < 8; ++nt) {
                int k0 = kb + 8 * nt + 2 * c;
                if (k0     > q0) S[nt][0] = -1e30f;
                if (k0 + 1 > q0) S[nt][1] = -1e30f;
                if (k0     > q1) S[nt][2] = -1e30f;
                if (k0 + 1 > q1) S[nt][3] = -1e30f;
            }
        }

        float mx0 = -1e30f, mx1 = -1e30f;
#pragma unroll
        for (int nt = 0; nt < 8; ++nt) {
            mx0 = fmaxf(mx0, fmaxf(S[nt][0], S[nt][1]));
            mx1 = fmaxf(mx1, fmaxf(S[nt][2], S[nt][3]));
        }
        mx0 = fmaxf(mx0, __shfl_xor_sync(0xffffffffu, mx0, 1));
        mx0 = fmaxf(mx0, __shfl_xor_sync(0xffffffffu, mx0, 2));
        mx1 = fmaxf(mx1, __shfl_xor_sync(0xffffffffu, mx1, 1));
        mx1 = fmaxf(mx1, __shfl_xor_sync(0xffffffffu, mx1, 2));
        float mn0 = fmaxf(m0, mx0), mn1 = fmaxf(m1, mx1);
        float al0 = __expf(m0 - mn0), al1 = __expf(m1 - mn1);
        m0 = mn0; m1 = mn1;

        float s0 = 0.0f, s1 = 0.0f;
#pragma unroll
        for (int nt = 0; nt < 8; ++nt) {
            S[nt][0] = __expf(S[nt][0] - mn0);
            S[nt][1] = __expf(S[nt][1] - mn0);
            S[nt][2] = __expf(S[nt][2] - mn1);
            S[nt][3] = __expf(S[nt][3] - mn1);
            s0 += S[nt][0] + S[nt][1];
            s1 += S[nt][2] + S[nt][3];
        }
        l0 = l0 * al0 + s0;
        l1 = l1 * al1 + s1;
#pragma unroll
        for (int nt = 0; nt < 8; ++nt) {
            O[nt][0] *= al0; O[nt][1] *= al0;
            O[nt][2] *= al1; O[nt][3] *= al1;
        }

        // O += P * Vh, P in fp16 hi only
#pragma unroll
        for (int kk = 0; kk < 4; ++kk) {
            uint32_t ph[4];
            ph[0] = pack2h(S[2 * kk][0],     S[2 * kk][1]);
            ph[1] = pack2h(S[2 * kk][2],     S[2 * kk][3]);
            ph[2] = pack2h(S[2 * kk + 1][0], S[2 * kk + 1][1]);
            ph[3] = pack2h(S[2 * kk + 1][2], S[2 * kk + 1][3]);
            int vrow = (kk << 4) + vrit;
#pragma unroll
            for (int p = 0; p < 4; ++p) {
                uint32_t vo = (uint32_t)(vrow * 128 + ((((p << 1) | v_u) ^ (vrow & 7)) << 4));
                uint32_t vh[4];
                ldsm4t(vh, sb + 24576 + vo);
                mma_f16(O[2 * p],     ph, vh);
                mma_f16(O[2 * p + 1], ph, vh + 2);
            }
        }
    }

    l0 += __shfl_xor_sync(0xffffffffu, l0, 1);
    l0 += __shfl_xor_sync(0xffffffffu, l0, 2);
    l1 += __shfl_xor_sync(0xffffffffu, l1, 1);
    l1 += __shfl_xor_sync(0xffffffffu, l1, 2);
    const float i0 = 1.0f / l0, i1 = 1.0f / l1;
    const int row0 = qb + wid * 16 + r, row1 = row0 + 8;
#pragma unroll
    for (int nt = 0; nt < 8; ++nt) {
        int col = h * HDD + 8 * nt + 2 * c;
        size_t idx0 = ((size_t)b * TT + row0) * CC + col;
        size_t idx1 = ((size_t)b * TT + row1) * CC + col;
        *(uint32_t*)&ohi[idx0] = pack2h(O[nt][0] * i0, O[nt][1] * i0);
        *(uint32_t*)&ohi[idx1] = pack2h(O[nt][2] * i1, O[nt][3] * i1);
    }
}

// ---------------- LayerNorm + residual ----------------
__device__ __forceinline__ float block_sum(float v, float* red) {
    const int lane = threadIdx.x & 31, w = threadIdx.x >> 5;
#pragma unroll
    for (int o = 16; o; o >>= 1) v += __shfl_xor_sync(0xffffffffu, v, o);
    if (lane == 0) red[w] = v;
    __syncthreads();
    if (w == 0) {
        float s = (lane < 8) ? red[lane] : 0.0f;
#pragma unroll
        for (int o = 4; o; o >>= 1) s += __shfl_xor_sync(0xffffffffu, s, o);
        if (lane == 0) red[0] = s;
    }
    __syncthreads();
    float rr = red[0];
    __syncthreads();
    return rr;
}

template<bool SPLIT>
__global__ void __launch_bounds__(256)
ln_res_kernel(const float* __restrict__ res, const float* __restrict__ y,
              const float* __restrict__ g, const float* __restrict__ be,
              float* __restrict__ out, __half* __restrict__ ohi)
{
    __shared__ float red[8];
    const int row = blockIdx.x;
    const int t = threadIdx.x;
    const float* yr = y + (size_t)row * CC;

    float v[4];
    float s = 0.0f;
#pragma unroll
    for (int i = 0; i < 4; ++i) { v[i] = yr[t + i * 256]; s += v[i]; }
    const float mean = block_sum(s, red) * (1.0f / CC);

    float sq = 0.0f;
#pragma unroll
    for (int i = 0; i < 4; ++i) { float d = v[i] - mean; sq += d * d; }
    const float var = block_sum(sq, red) * (1.0f / CC);
    const float rstd = rsqrtf(var + 1e-5f);

    const float* rr = res + (size_t)row * CC;
    float* orow = out + (size_t)row * CC;
#pragma unroll
    for (int i = 0; i < 4; ++i) {
        int cix = t + i * 256;
        float o = rr[cix] + (v[i] - mean) * rstd * g[cix] + be[cix];
        orow[cix] = o;
        if (SPLIT) ohi[(size_t)row * CC + cix] = __float2half_rn(o);
    }
}

// ---------------- launch ----------------
extern "C" void kernel_launch(void* const* d_in, const int* in_sizes, int n_in,
                              void* d_out, int out_size)
{
    const float* x      = (const float*)d_in[0];
    const float* w_attn = (const float*)d_in[1];
    const float* b_attn = (const float*)d_in[2];
    const float* wa1    = (const float*)d_in[3];
    const float* ba1    = (const float*)d_in[4];
    const float* wa2    = (const float*)d_in[5];
    const float* ba2    = (const float*)d_in[6];
    const float* g1     = (const float*)d_in[7];
    const float* be1    = (const float*)d_in[8];
    const float* wf1    = (const float*)d_in[9];
    const float* bf1    = (const float*)d_in[10];
    const float* wf2    = (const float*)d_in[11];
    const float* bf2    = (const float*)d_in[12];
    const float* g2     = (const float*)d_in[13];
    const float* be2    = (const float*)d_in[14];
    float* out = (float*)d_out;

    float *x1, *y;
    cudaGetSymbolAddress((void**)&x1, g_x1);
    cudaGetSymbolAddress((void**)&y,  g_y);

    __half *wqkv_hi, *wqkv_lo, *wa1_hi, *wa2_hi, *wf1_hi, *wf2_hi,
           *ahi, *hhi, *qkvh, *qkvl;
    cudaGetSymbolAddress((void**)&wqkv_hi, g_wqkv_hi);
    cudaGetSymbolAddress((void**)&wqkv_lo, g_wqkv_lo);
    cudaGetSymbolAddress((void**)&wa1_hi,  g_wa1_hi);
    cudaGetSymbolAddress((void**)&wa2_hi,  g_wa2_hi);
    cudaGetSymbolAddress((void**)&wf1_hi,  g_wf1_hi);
    cudaGetSymbolAddress((void**)&wf2_hi,  g_wf2_hi);
    cudaGetSymbolAddress((void**)&ahi,     g_ahi);
    cudaGetSymbolAddress((void**)&hhi,     g_hhi);
    cudaGetSymbolAddress((void**)&qkvh,    g_qkvh);
    cudaGetSymbolAddress((void**)&qkvl,    g_qkvl);

    cudaFuncSetAttribute(attn_mma_kernel, cudaFuncAttributeMaxDynamicSharedMemorySize, ASMEM);
    cudaFuncSetAttribute((gemm_mma_kernel<2, 2>), cudaFuncAttributeMaxDynamicSharedMemorySize, GS2);
    cudaFuncSetAttribute((gemm_mma_kernel<1, 1>), cudaFuncAttributeMaxDynamicSharedMemorySize, GS1);
    cudaFuncSetAttribute((gemm_mma_kernel<0, 1>), cudaFuncAttributeMaxDynamicSharedMemorySize, GS1);

    // all conversions (5 weights + x) in one launch
    cvt_all_kernel<<<CVT_BLOCKS, 256>>>(
        w_attn, wqkv_hi, wqkv_lo,
        wa1, wa1_hi,
        wa2, wa2_hi,
        wf1, wf1_hi,
        wf2, wf2_hi,
        x, ahi);

    // 1) qkv = x @ w_attn + b_attn  (2-pass, hi+lo out)
    gemm_mma_kernel<2, 2><<<dim3(C3 / 128, MTOK / 128), 256, GS2>>>(
        ahi, wqkv_hi, wqkv_lo, b_attn, nullptr, qkvh, qkvl, C3, CC);
    // 2) attention (QK 2-pass, PV 1-pass) -> hi-only att
    attn_mma_kernel<<<dim3(TT / 64, NHH, BB), 128, ASMEM>>>(qkvh, qkvl, ahi);
    // 3) h = gelu(att @ wa1 + ba1)  (1-pass, 3-stage)
    gemm_mma_kernel<1, 1><<<dim3(C4 / 128, MTOK / 128), 256, GS1>>>(
        ahi, wa1_hi, nullptr, ba1, nullptr, hhi, nullptr, C4, CC);
    // 4) y = h @ wa2 + ba2  (1-pass, 3-stage)
    gemm_mma_kernel<0, 1><<<dim3(CC / 128, MTOK / 128), 256, GS1>>>(
        hhi, wa2_hi, nullptr, ba2, y, nullptr, nullptr, CC, C4);
    // 5) x1 = x + ln(y); emit fp16 x1 hi
    ln_res_kernel<true><<<MTOK, 256>>>(x, y, g1, be1, x1, ahi);
    // 6) h = gelu(x1 @ wf1 + bf1)  (1-pass, 3-stage)
    gemm_mma_kernel<1, 1><<<dim3(C4 / 128, MTOK / 128), 256, GS1>>>(
        ahi, wf1_hi, nullptr, bf1, nullptr, hhi, nullptr, C4, CC);
    // 7) y = h @ wf2 + bf2  (1-pass, 3-stage)
    gemm_mma_kernel<0, 1><<<dim3(CC / 128, MTOK / 128), 256, GS1>>>(
        hhi, wf2_hi, nullptr, bf2, y, nullptr, nullptr, CC, C4);
    // 8) out = x1 + ln(y)
    ln_res_kernel<false><<<MTOK, 256>>>(x1, y, g2, be2, out, nullptr);
}

// round 14
// speedup vs baseline: 2.8881x; 1.2014x over previous
#include <cuda_runtime.h>
#include <cuda_fp16.h>
#include <math.h>
#include <stdint.h>

// Problem dims (fixed)
#define BB 2
#define TT 2048
#define CC 1024
#define NHH 16
#define HDD 64
#define MTOK 4096          // B*T
#define C3 3072
#define C4 4096

// ---------------- scratch (no allocation allowed) ----------------
__device__ float g_x1 [(size_t)MTOK * CC];
__device__ float g_y  [(size_t)MTOK * CC];

// fp16 weights, transposed to [N][K]
__device__ __half g_wqkv_hi[(size_t)C3 * CC];
__device__ __half g_wa1_hi [(size_t)C4 * CC];
__device__ __half g_wa2_hi [(size_t)CC * C4];
__device__ __half g_wf1_hi [(size_t)C4 * CC];
__device__ __half g_wf2_hi [(size_t)CC * C4];
// fp16 activations
__device__ __half g_ahi [(size_t)MTOK * CC];
__device__ __half g_hhi [(size_t)MTOK * C4];
__device__ __half g_qkvh[(size_t)MTOK * C3];

__device__ __forceinline__ float gelu_f(float v) {
    return 0.5f * v * (1.0f + erff(v * 0.7071067811865475f));
}

// ======================= PTX helpers =======================
__device__ __forceinline__ uint32_t smem_u32(const void* p) {
    uint32_t a;
    asm("{ .reg .u64 t; cvta.to.shared.u64 t, %1; cvt.u32.u64 %0, t; }" : "=r"(a) : "l"(p));
    return a;
}
__device__ __forceinline__ void ldsm4(uint32_t* r, uint32_t addr) {
    asm volatile("ldmatrix.sync.aligned.m8n8.x4.shared.b16 {%0,%1,%2,%3}, [%4];"
                 : "=r"(r[0]), "=r"(r[1]), "=r"(r[2]), "=r"(r[3]) : "r"(addr));
}
__device__ __forceinline__ void ldsm4t(uint32_t* r, uint32_t addr) {
    asm volatile("ldmatrix.sync.aligned.m8n8.x4.trans.shared.b16 {%0,%1,%2,%3}, [%4];"
                 : "=r"(r[0]), "=r"(r[1]), "=r"(r[2]), "=r"(r[3]) : "r"(addr));
}
__device__ __forceinline__ void mma_f16(float* d, const uint32_t* a, const uint32_t* b) {
    asm volatile(
        "mma.sync.aligned.m16n8k16.row.col.f32.f16.f16.f32 "
        "{%0,%1,%2,%3}, {%4,%5,%6,%7}, {%8,%9}, {%0,%1,%2,%3};"
        : "+f"(d[0]), "+f"(d[1]), "+f"(d[2]), "+f"(d[3])
        : "r"(a[0]), "r"(a[1]), "r"(a[2]), "r"(a[3]), "r"(b[0]), "r"(b[1]));
}
__device__ __forceinline__ void cp16(uint32_t dst, const void* src) {
    unsigned long long g = __cvta_generic_to_global(src);
    asm volatile("cp.async.ca.shared.global [%0], [%1], 16;" :: "r"(dst), "l"(g) : "memory");
}
__device__ __forceinline__ void cp_commit() {
    asm volatile("cp.async.commit_group;" ::: "memory");
}
template<int N>
__device__ __forceinline__ void cp_wait() {
    asm volatile("cp.async.wait_group %0;" :: "n"(N) : "memory");
}
__device__ __forceinline__ uint32_t pack2h(float a, float b) {
    __half2 H = __halves2half2(__float2half_rn(a), __float2half_rn(b));
    return *(uint32_t*)&H;
}

// ======================= fused conversion kernel =======================
#define CVT_BLOCKS (19456 + 4096)
__global__ void __launch_bounds__(256)
cvt_all_kernel(const float* __restrict__ W0, __half* __restrict__ h0,
               const float* __restrict__ W1, __half* __restrict__ h1,
               const float* __restrict__ W2, __half* __restrict__ h2,
               const float* __restrict__ W3, __half* __restrict__ h3,
               const float* __restrict__ W4, __half* __restrict__ h4,
               const float* __restrict__ x,  __half* __restrict__ xh)
{
    const int bid = blockIdx.x;
    if (bid >= 19456) {
        int i = ((bid - 19456) * 256 + threadIdx.x) * 4;
        float4 v = *(const float4*)(x + i);
        *(uint32_t*)(xh + i)     = pack2h(v.x, v.y);
        *(uint32_t*)(xh + i + 2) = pack2h(v.z, v.w);
        return;
    }
    __shared__ float tile[32][33];
    const float* W; __half* hi; int K, N, local;
    if      (bid < 3072)  { W = W0; hi = h0; K = CC; N = C3; local = bid; }
    else if (bid < 7168)  { W = W1; hi = h1; K = CC; N = C4; local = bid - 3072; }
    else if (bid < 11264) { W = W2; hi = h2; K = C4; N = CC; local = bid - 7168; }
    else if (bid < 15360) { W = W3; hi = h3; K = CC; N = C4; local = bid - 11264; }
    else                  { W = W4; hi = h4; K = C4; N = CC; local = bid - 15360; }
    const int nb = N >> 5;
    const int n0 = (local % nb) * 32, k0 = (local / nb) * 32;
    const int tx = threadIdx.x & 31, ty = threadIdx.x >> 5;
#pragma unroll
    for (int r = 0; r < 4; ++r)
        tile[ty + r * 8][tx] = W[(size_t)(k0 + ty + r * 8) * N + n0 + tx];
    __syncthreads();
#pragma unroll
    for (int r = 0; r < 4; ++r) {
        int n = n0 + ty + r * 8;
        hi[(size_t)n * K + k0 + tx] = __float2half_rn(tile[tx][ty + r * 8]);
    }
}

// 128B-row swizzle (8 16B units per row, 8-way xor)
__device__ __forceinline__ uint32_t asw(int row, int u) {
    return (uint32_t)(row * 128 + ((u ^ (row & 7)) << 4));
}

// ======================= HMMA fp16 GEMM, CTA 128x128, BK=64, 1-pass ============
// 8 warps (2x4), warp tile 64x32, 2-stage double buffer, 2 CTAs/SM,
// ONE __syncthreads per 64-wide K-chunk.
// MODE 0: fp32 out.  MODE 1: exact-GELU + fp16 hi out.  MODE 2: fp16 hi out.
#define GS1 (2 * 32768)
template<int MODE>
__global__ void __launch_bounds__(256, 2)
gemm_mma_kernel(const __half* __restrict__ Ahi, const __half* __restrict__ Bhi,
                const float* __restrict__ bias, float* __restrict__ Cf,
                __half* __restrict__ Chi, int N, int K)
{
    constexpr uint32_t STAGE = 32768u;

    extern __shared__ char smem[];
    const uint32_t sb = smem_u32(smem);

    const int t = threadIdx.x;
    const int wid = t >> 5, lane = t & 31;
    const int bm = blockIdx.y * 128;
    const int bn = blockIdx.x * 128;
    const int wm = wid >> 2, wn = wid & 3;

    float acc[4][4][4];
#pragma unroll
    for (int i = 0; i < 4; ++i)
#pragma unroll
        for (int j = 0; j < 4; ++j)
#pragma unroll
            for (int k = 0; k < 4; ++k) acc[i][j][k] = 0.0f;

    const int nc = K >> 6;

    const int g  = lane >> 3, lr = lane & 7;
    const int a_rit = lr + (g & 1) * 8, a_kqo = g >> 1;
    const int b_rit = lr + (g >> 1) * 8, b_kqo = g & 1;

    uint32_t aA[4], aBh[2];
    int aRsw[4], bRsw[2];
#pragma unroll
    for (int mt = 0; mt < 4; ++mt) {
        int row = wm * 64 + mt * 16 + a_rit;
        aA[mt] = sb + row * 128;
        aRsw[mt] = row & 7;
    }
#pragma unroll
    for (int p = 0; p < 2; ++p) {
        int row = wn * 32 + p * 16 + b_rit;
        aBh[p] = sb + 16384u + row * 128;
        bRsw[p] = row & 7;
    }

    auto issue = [&](int c, int s) {
        const uint32_t st = sb + s * STAGE;
        const int kb = c * 64;
#pragma unroll
        for (int i = 0; i < 8; ++i) {
            int u = t + i * 256;
            int arr = u >> 10, v = u & 1023, row = v >> 3, kq = v & 7;
            const __half* src = (arr ? Bhi : Ahi) +
                (size_t)((arr ? bn : bm) + row) * K + kb + kq * 8;
            cp16(st + arr * 16384u + asw(row, kq), src);
        }
        cp_commit();
    };

    issue(0, 0);
    int s = 0;
    for (int c = 0; c < nc; ++c) {
        cp_wait<0>();
        __syncthreads();
        if (c + 1 < nc) issue(c + 1, s ^ 1);

        const uint32_t stoff = (uint32_t)(s * STAGE);
#pragma unroll
        for (int kk = 0; kk < 4; ++kk) {
            uint32_t ah[4][4], bh[4][2];
#pragma unroll
            for (int mt = 0; mt < 4; ++mt) {
                uint32_t o = (uint32_t)(((((kk << 1) | a_kqo) ^ aRsw[mt]) << 4));
                ldsm4(ah[mt], aA[mt] + stoff + o);
            }
#pragma unroll
            for (int p = 0; p < 2; ++p) {
                uint32_t r[4];
                uint32_t o = (uint32_t)(((((kk << 1) | b_kqo) ^ bRsw[p]) << 4));
                ldsm4(r, aBh[p] + stoff + o);
                bh[2 * p][0] = r[0]; bh[2 * p][1] = r[1];
                bh[2 * p + 1][0] = r[2]; bh[2 * p + 1][1] = r[3];
            }
#pragma unroll
            for (int mt = 0; mt < 4; ++mt)
#pragma unroll
                for (int nt = 0; nt < 4; ++nt)
                    mma_f16(acc[mt][nt], ah[mt], bh[nt]);
        }
        s ^= 1;
    }

    const int mrow = bm + wm * 64;
    const int ncol = bn + wn * 32;
#pragma unroll
    for (int mt = 0; mt < 4; ++mt) {
#pragma unroll
        for (int nt = 0; nt < 4; ++nt) {
            float* d = acc[mt][nt];
            int r0 = mrow + mt * 16 + (lane >> 2);
            int cix = ncol + nt * 8 + (lane & 3) * 2;
            float b0 = bias[cix], b1 = bias[cix + 1];
            float v00 = d[0] + b0, v01 = d[1] + b1;
            float v10 = d[2] + b0, v11 = d[3] + b1;
            if (MODE == 0) {
                float2 p0{v00, v01}, p1{v10, v11};
                *(float2*)&Cf[(size_t)r0 * N + cix]       = p0;
                *(float2*)&Cf[(size_t)(r0 + 8) * N + cix] = p1;
            } else {
                if (MODE == 1) {
                    v00 = gelu_f(v00); v01 = gelu_f(v01);
                    v10 = gelu_f(v10); v11 = gelu_f(v11);
                }
                *(uint32_t*)&Chi[(size_t)r0 * N + cix]       = pack2h(v00, v01);
                *(uint32_t*)&Chi[(size_t)(r0 + 8) * N + cix] = pack2h(v10, v11);
            }
        }
    }
}

// ======================= HMMA causal attention =======================
// QK: 1-pass (Qh x Kh).  PV: 1-pass (P hi x Vh).
// smem: Qh 8K | Kh 8K | Vh 8K = 24KB.
#define ASMEM 24576

__global__ void __launch_bounds__(128, 3)
attn_mma_kernel(const __half* __restrict__ qkvh, __half* __restrict__ ohi)
{
    extern __shared__ char asmem[];
    const uint32_t sb = smem_u32(asmem);

    const int t = threadIdx.x, wid = t >> 5, lane = t & 31;
    const int qi = gridDim.x - 1 - blockIdx.x;
    const int qb = qi * 64;
    const int h  = blockIdx.y, b = blockIdx.z;

    const __half* Kh_g = qkvh + (size_t)b * TT * C3 + h * HDD;
    const __half* Qh_g = Kh_g + CC;
    const __half* Vh_g = Kh_g + 2 * CC;

    // load Qh: 512 16B units
#pragma unroll
    for (int i = 0; i < 4; ++i) {
        int uu = t + i * 128;
        int row = uu >> 3, u = uu & 7;
        cp16(sb + asw(row, u), Qh_g + (size_t)(qb + row) * C3 + u * 8);
    }
    cp_commit();

    const int g = lane >> 3, lr = lane & 7;
    const int r = lane >> 2, c = lane & 3;
    const int qrow = wid * 16 + lr + ((g & 1) << 3);
    const int a_u  = g >> 1;
    const int krit = lr + ((g >> 1) << 3);
    const int b_u  = g & 1;
    const int vrit = lr + ((g & 1) << 3);
    const int v_u  = g >> 1;

    float O[8][4];
#pragma unroll
    for (int i = 0; i < 8; ++i)
#pragma unroll
        for (int j = 0; j < 4; ++j) O[i][j] = 0.0f;
    float m0 = -1e30f, m1 = -1e30f, l0 = 0.0f, l1 = 0.0f;

    const int ntiles = qi + 1;
    for (int kt = 0; kt < ntiles; ++kt) {
        const int kb = kt * 64;
        __syncthreads();
        // Kh | Vh: 1024 units = 8 iters
#pragma unroll
        for (int i = 0; i < 8; ++i) {
            int uu = t + i * 128;
            int arr = uu >> 9, v = uu & 511, row = v >> 3, u = v & 7;
            const __half* src = (arr ? Vh_g : Kh_g) + (size_t)(kb + row) * C3 + u * 8;
            cp16(sb + 8192 + arr * 8192 + asw(row, u), src);
        }
        cp_commit();
        cp_wait<0>();
        __syncthreads();

        float S[8][4];
#pragma unroll
        for (int i = 0; i < 8; ++i)
#pragma unroll
            for (int j = 0; j < 4; ++j) S[i][j] = 0.0f;

#pragma unroll
        for (int kk = 0; kk < 4; ++kk) {
            uint32_t ah[4];
            uint32_t aoq = (uint32_t)(qrow * 128 + ((((kk << 1) | a_u) ^ (qrow & 7)) << 4));
            ldsm4(ah, sb + aoq);
#pragma unroll
            for (int p = 0; p < 4; ++p) {
                int krow = (p << 4) + krit;
                uint32_t ko = (uint32_t)(krow * 128 + ((((kk << 1) | b_u) ^ (krow & 7)) << 4));
                uint32_t bh[4];
                ldsm4(bh, sb + 8192 + ko);
                mma_f16(S[2 * p],     ah, bh);
                mma_f16(S[2 * p + 1], ah, bh + 2);
            }
        }

#pragma unroll
        for (int nt = 0; nt < 8; ++nt)
#pragma unroll
            for (int e = 0; e < 4; ++e) S[nt][e] *= 0.125f;
        if (kt == qi) {
            const int q0 = qb + wid * 16 + r, q1 = q0 + 8;
#pragma unroll
            for (int nt = 0; nt < 8; ++nt) {
                int k0 = kb + 8 * nt + 2 * c;
                if (k0     > q0) S[nt][0] = -1e30f;
                if (k0 + 1 > q0) S[nt][1] = -1e30f;
                if (k0     > q1) S[nt][2] = -1e30f;
                if (k0 + 1 > q1) S[nt][3] = -1e30f;
            }
        }

        float mx0 = -1e30f, mx1 = -1e30f;
#pragma unroll
        for (int nt = 0; nt < 8; ++nt) {
            mx0 = fmaxf(mx0, fmaxf(S[nt][0], S[nt][1]));
            mx1 = fmaxf(mx1, fmaxf(S[nt][2], S[nt][3]));
        }
        mx0 = fmaxf(mx0, __shfl_xor_sync(0xffffffffu, mx0, 1));
        mx0 = fmaxf(mx0, __shfl_xor_sync(0xffffffffu, mx0, 2));
        mx1 = fmaxf(mx1, __shfl_xor_sync(0xffffffffu, mx1, 1));
        mx1 = fmaxf(mx1, __shfl_xor_sync(0xffffffffu, mx1, 2));
        float mn0 = fmaxf(m0, mx0), mn1 = fmaxf(m1, mx1);
        float al0 = __expf(m0 - mn0), al1 = __expf(m1 - mn1);
        m0 = mn0; m1 = mn1;

        float s0 = 0.0f, s1 = 0.0f;
#pragma unroll
        for (int nt = 0; nt < 8; ++nt) {
            S[nt][0] = __expf(S[nt][0] - mn0);
            S[nt][1] = __expf(S[nt][1] - mn0);
            S[nt][2] = __expf(S[nt][2] - mn1);
            S[nt][3] = __expf(S[nt][3] - mn1);
            s0 += S[nt][0] + S[nt][1];
            s1 += S[nt][2] + S[nt][3];
        }
        l0 = l0 * al0 + s0;
        l1 = l1 * al1 + s1;
#pragma unroll
        for (int nt = 0; nt < 8; ++nt) {
            O[nt][0] *= al0; O[nt][1] *= al0;
            O[nt][2] *= al1; O[nt][3] *= al1;
        }

        // O += P * Vh
#pragma unroll
        for (int kk = 0; kk < 4; ++kk) {
            uint32_t ph[4];
            ph[0] = pack2h(S[2 * kk][0],     S[2 * kk][1]);
            ph[1] = pack2h(S[2 * kk][2],     S[2 * kk][3]);
            ph[2] = pack2h(S[2 * kk + 1][0], S[2 * kk + 1][1]);
            ph[3] = pack2h(S[2 * kk + 1][2], S[2 * kk + 1][3]);
            int vrow = (kk << 4) + vrit;
#pragma unroll
            for (int p = 0; p < 4; ++p) {
                uint32_t vo = (uint32_t)(vrow * 128 + ((((p << 1) | v_u) ^ (vrow & 7)) << 4));
                uint32_t vh[4];
                ldsm4t(vh, sb + 16384 + vo);
                mma_f16(O[2 * p],     ph, vh);
                mma_f16(O[2 * p + 1], ph, vh + 2);
            }
        }
    }

    l0 += __shfl_xor_sync(0xffffffffu, l0, 1);
    l0 += __shfl_xor_sync(0xffffffffu, l0, 2);
    l1 += __shfl_xor_sync(0xffffffffu, l1, 1);
    l1 += __shfl_xor_sync(0xffffffffu, l1, 2);
    const float i0 = 1.0f / l0, i1 = 1.0f / l1;
    const int row0 = qb + wid * 16 + r, row1 = row0 + 8;
#pragma unroll
    for (int nt = 0; nt < 8; ++nt) {
        int col = h * HDD + 8 * nt + 2 * c;
        size_t idx0 = ((size_t)b * TT + row0) * CC + col;
        size_t idx1 = ((size_t)b * TT + row1) * CC + col;
        *(uint32_t*)&ohi[idx0] = pack2h(O[nt][0] * i0, O[nt][1] * i0);
        *(uint32_t*)&ohi[idx1] = pack2h(O[nt][2] * i1, O[nt][3] * i1);
    }
}

// ---------------- LayerNorm + residual ----------------
__device__ __forceinline__ float block_sum(float v, float* red) {
    const int lane = threadIdx.x & 31, w = threadIdx.x >> 5;
#pragma unroll
    for (int o = 16; o; o >>= 1) v += __shfl_xor_sync(0xffffffffu, v, o);
    if (lane == 0) red[w] = v;
    __syncthreads();
    if (w == 0) {
        float s = (lane < 8) ? red[lane] : 0.0f;
#pragma unroll
        for (int o = 4; o; o >>= 1) s += __shfl_xor_sync(0xffffffffu, s, o);
        if (lane == 0) red[0] = s;
    }
    __syncthreads();
    float rr = red[0];
    __syncthreads();
    return rr;
}

template<bool SPLIT>
__global__ void __launch_bounds__(256)
ln_res_kernel(const float* __restrict__ res, const float* __restrict__ y,
              const float* __restrict__ g, const float* __restrict__ be,
              float* __restrict__ out, __half* __restrict__ ohi)
{
    __shared__ float red[8];
    const int row = blockIdx.x;
    const int t = threadIdx.x;
    const float* yr = y + (size_t)row * CC;

    float v[4];
    float s = 0.0f;
#pragma unroll
    for (int i = 0; i < 4; ++i) { v[i] = yr[t + i * 256]; s += v[i]; }
    const float mean = block_sum(s, red) * (1.0f / CC);

    float sq = 0.0f;
#pragma unroll
    for (int i = 0; i < 4; ++i) { float d = v[i] - mean; sq += d * d; }
    const float var = block_sum(sq, red) * (1.0f / CC);
    const float rstd = rsqrtf(var + 1e-5f);

    const float* rr = res + (size_t)row * CC;
    float* orow = out + (size_t)row * CC;
#pragma unroll
    for (int i = 0; i < 4; ++i) {
        int cix = t + i * 256;
        float o = rr[cix] + (v[i] - mean) * rstd * g[cix] + be[cix];
        orow[cix] = o;
        if (SPLIT) ohi[(size_t)row * CC + cix] = __float2half_rn(o);
    }
}

// ---------------- launch ----------------
extern "C" void kernel_launch(void* const* d_in, const int* in_sizes, int n_in,
                              void* d_out, int out_size)
{
    const float* x      = (const float*)d_in[0];
    const float* w_attn = (const float*)d_in[1];
    const float* b_attn = (const float*)d_in[2];
    const float* wa1    = (const float*)d_in[3];
    const float* ba1    = (const float*)d_in[4];
    const float* wa2    = (const float*)d_in[5];
    const float* ba2    = (const float*)d_in[6];
    const float* g1     = (const float*)d_in[7];
    const float* be1    = (const float*)d_in[8];
    const float* wf1    = (const float*)d_in[9];
    const float* bf1    = (const float*)d_in[10];
    const float* wf2    = (const float*)d_in[11];
    const float* bf2    = (const float*)d_in[12];
    const float* g2     = (const float*)d_in[13];
    const float* be2    = (const float*)d_in[14];
    float* out = (float*)d_out;

    float *x1, *y;
    cudaGetSymbolAddress((void**)&x1, g_x1);
    cudaGetSymbolAddress((void**)&y,  g_y);

    __half *wqkv_hi, *wa1_hi, *wa2_hi, *wf1_hi, *wf2_hi, *ahi, *hhi, *qkvh;
    cudaGetSymbolAddress((void**)&wqkv_hi, g_wqkv_hi);
    cudaGetSymbolAddress((void**)&wa1_hi,  g_wa1_hi);
    cudaGetSymbolAddress((void**)&wa2_hi,  g_wa2_hi);
    cudaGetSymbolAddress((void**)&wf1_hi,  g_wf1_hi);
    cudaGetSymbolAddress((void**)&wf2_hi,  g_wf2_hi);
    cudaGetSymbolAddress((void**)&ahi,     g_ahi);
    cudaGetSymbolAddress((void**)&hhi,     g_hhi);
    cudaGetSymbolAddress((void**)&qkvh,    g_qkvh);

    cudaFuncSetAttribute(attn_mma_kernel, cudaFuncAttributeMaxDynamicSharedMemorySize, ASMEM);
    cudaFuncSetAttribute(gemm_mma_kernel<0>, cudaFuncAttributeMaxDynamicSharedMemorySize, GS1);
    cudaFuncSetAttribute(gemm_mma_kernel<1>, cudaFuncAttributeMaxDynamicSharedMemorySize, GS1);
    cudaFuncSetAttribute(gemm_mma_kernel<2>, cudaFuncAttributeMaxDynamicSharedMemorySize, GS1);

    // all conversions (5 weights + x) in one launch
    cvt_all_kernel<<<CVT_BLOCKS, 256>>>(
        w_attn, wqkv_hi,
        wa1, wa1_hi,
        wa2, wa2_hi,
        wf1, wf1_hi,
        wf2, wf2_hi,
        x, ahi);

    // 1) qkv = x @ w_attn + b_attn  (1-pass, hi out)
    gemm_mma_kernel<2><<<dim3(C3 / 128, MTOK / 128), 256, GS1>>>(
        ahi, wqkv_hi, b_attn, nullptr, qkvh, C3, CC);
    // 2) attention (QK 1-pass, PV 1-pass)
    attn_mma_kernel<<<dim3(TT / 64, NHH, BB), 128, ASMEM>>>(qkvh, ahi);
    // 3) h = gelu(att @ wa1 + ba1)
    gemm_mma_kernel<1><<<dim3(C4 / 128, MTOK / 128), 256, GS1>>>(
        ahi, wa1_hi, ba1, nullptr, hhi, C4, CC);
    // 4) y = h @ wa2 + ba2
    gemm_mma_kernel<0><<<dim3(CC / 128, MTOK / 128), 256, GS1>>>(
        hhi, wa2_hi, ba2, y, nullptr, CC, C4);
    // 5) x1 = x + ln(y); emit fp16 x1 hi
    ln_res_kernel<true><<<MTOK, 256>>>(x, y, g1, be1, x1, ahi);
    // 6) h = gelu(x1 @ wf1 + bf1)
    gemm_mma_kernel<1><<<dim3(C4 / 128, MTOK / 128), 256, GS1>>>(
        ahi, wf1_hi, bf1, nullptr, hhi, C4, CC);
    // 7) y = h @ wf2 + bf2
    gemm_mma_kernel<0><<<dim3(CC / 128, MTOK / 128), 256, GS1>>>(
        hhi, wf2_hi, bf2, y, nullptr, CC, C4);
    // 8) out = x1 + ln(y)
    ln_res_kernel<false><<<MTOK, 256>>>(x1, y, g2, be2, out, nullptr);
}